// round 7
// baseline (speedup 1.0000x reference)
#include <cuda_runtime.h>
#include <cuda_bf16.h>
#include <math.h>

// ---------------- problem dims ----------------
#define BATCH   1024
#define TLEN    16000
#define NFFT    400
#define HOP     200
#define NBINS   201
#define NMELS   128
#define NFRAMES 81
#define TSTEPS  79
#define HID     128
#define G4      512
#define R1      (BATCH*NFRAMES)   // 82944
#define R2      (BATCH*TSTEPS)    // 80896

#define KP_DFT  416
#define KP_MEL  224
#define KP_G    128
#define NP_DFT  448
#define KCONV   384

// GEMM pipeline smem (dynamic)
#define GEMM_STAGE_ROWS 384            // Ah 0-127, Al 128-255, Bh 256-319, Bl 320-383
#define GEMM_SMEM_BYTES (3*GEMM_STAGE_ROWS*40*2)   // 92160
#define CONV_STAGE_ROWS 192            // As 0-127, Bs 128-191
#define CONV_SMEM_BYTES (4*CONV_STAGE_ROWS*40*2)   // 61440

// LSTM smem (bf16 elements)
#define UH_STRIDE 136
#define ULW_STRIDE 24
#define H_STRIDE  264
#define SM_UH   (512*UH_STRIDE)
#define SM_ULW  (3*64*ULW_STRIDE)
#define SM_UL   (8*SM_ULW)
#define SM_H    (16*H_STRIDE)
#define LSTM_SMEM_BYTES ((SM_UH + SM_UL + SM_H)*2)  // 221440

// ---------------- scratch ----------------
__device__ float          d_hann[NFFT];
__device__ __nv_bfloat16  d_A2dft[(size_t)R1 * 2 * KP_DFT];
__device__ __nv_bfloat16  d_B2dft[(size_t)NP_DFT * 2 * KP_DFT];
__device__ __nv_bfloat16  d_A2mel[(size_t)R1 * 2 * KP_MEL];
__device__ __nv_bfloat16  d_B2mel[(size_t)128 * 2 * KP_MEL];
__device__ __nv_bfloat16  d_melsp[(size_t)R1 * 256];
__device__ __nv_bfloat16  d_B2conv[(size_t)128 * 2 * KCONV];
__device__ __nv_bfloat16  d_A2g[(size_t)R2 * 2 * KP_G];
__device__ __nv_bfloat16  d_B2W1p[(size_t)G4 * 2 * KP_G];
__device__ __nv_bfloat16  d_B2W2p[(size_t)G4 * 2 * KP_G];
__device__ __nv_bfloat16  d_U1p[(size_t)G4 * 2 * KP_G];
__device__ __nv_bfloat16  d_U2p[(size_t)G4 * 2 * KP_G];
__device__ float          d_b1p[G4];
__device__ float          d_b2p[G4];
__device__ float          d_g[(size_t)R2 * G4];
__device__ __nv_bfloat16  d_h1s[(size_t)R2 * 2 * KP_G];
__device__ float          d_hmean[BATCH * 128];
__device__ float          d_hfc[BATCH * 128];

// ---------------- helpers ----------------
__device__ __forceinline__ float sigf(float x) { return 1.0f / (1.0f + __expf(-x)); }
__device__ __forceinline__ float tanhf_acc(float x) {
    float t = __expf(-2.0f * fabsf(x));
    float r = (1.0f - t) / (1.0f + t);
    return copysignf(r, x);
}
__device__ __forceinline__ void splitw(__nv_bfloat16* P, size_t base, int KpOut, int k, float v) {
    __nv_bfloat16 h = __float2bfloat16(v);
    P[base + k] = h;
    P[base + KpOut + k] = __float2bfloat16(v - __bfloat162float(h));
}
__device__ __forceinline__ unsigned smaddr(const void* p) {
    return (unsigned)__cvta_generic_to_shared(p);
}
__device__ __forceinline__ void cpa16(unsigned dst, const void* src) {
    asm volatile("cp.async.cg.shared.global [%0], [%1], 16;" :: "r"(dst), "l"(src));
}
__device__ __forceinline__ void cpa_commit() { asm volatile("cp.async.commit_group;"); }
__device__ __forceinline__ void mma16816(float* c, const unsigned* a, unsigned b0, unsigned b1) {
    asm volatile(
        "mma.sync.aligned.m16n8k16.row.col.f32.bf16.bf16.f32 "
        "{%0,%1,%2,%3}, {%4,%5,%6,%7}, {%8,%9}, {%0,%1,%2,%3};"
        : "+f"(c[0]), "+f"(c[1]), "+f"(c[2]), "+f"(c[3])
        : "r"(a[0]), "r"(a[1]), "r"(a[2]), "r"(a[3]), "r"(b0), "r"(b1));
}
__device__ __forceinline__ void ldsm4(unsigned* r, unsigned addr) {
    asm volatile("ldmatrix.sync.aligned.m8n8.x4.shared.b16 {%0,%1,%2,%3}, [%4];"
        : "=r"(r[0]), "=r"(r[1]), "=r"(r[2]), "=r"(r[3]) : "r"(addr));
}
__device__ __forceinline__ int gperm(int n) {
    int w = n >> 6, s = n & 63, gate = s >> 4, u = s & 15;
    return gate * 128 + w * 16 + u;
}

// ---------------- precompute ----------------
__global__ void k_precompute(const float* __restrict__ conv_w,
                             const float* __restrict__ W1, const float* __restrict__ W2,
                             const float* __restrict__ U1, const float* __restrict__ U2,
                             const float* __restrict__ b1, const float* __restrict__ b2) {
    int tid = blockIdx.x * blockDim.x + threadIdx.x;
    int nth = gridDim.x * blockDim.x;

    for (int k = tid; k < NFFT; k += nth)
        d_hann[k] = (float)(0.5 - 0.5 * cospi((double)k / 200.0));

    for (int idx = tid; idx < NP_DFT * KP_DFT; idx += nth) {
        int n = idx / KP_DFT, k = idx % KP_DFT;
        float v = 0.f;
        if (n < 2 * NBINS && k < NFFT) {
            int m = n >> 1;
            int ph = (m * k) % 400;
            double s, c;
            sincospi((double)ph / 200.0, &s, &c);
            v = (float)((n & 1) ? s : c);
        }
        splitw(d_B2dft, (size_t)n * (2 * KP_DFT), KP_DFT, k, v);
    }

    const double mel_max = 2595.0 * log10(1.0 + 8000.0 / 700.0);
    for (int idx = tid; idx < 128 * KP_MEL; idx += nth) {
        int m = idx / KP_MEL, k = idx % KP_MEL;
        float v = 0.f;
        if (k < NBINS) {
            double freq = 40.0 * (double)k;
            double f0 = 700.0 * (pow(10.0, (mel_max * (double)(m    ) / 129.0) / 2595.0) - 1.0);
            double f1 = 700.0 * (pow(10.0, (mel_max * (double)(m + 1) / 129.0) / 2595.0) - 1.0);
            double f2 = 700.0 * (pow(10.0, (mel_max * (double)(m + 2) / 129.0) / 2595.0) - 1.0);
            double dn = (freq - f0) / (f1 - f0);
            double up = (f2 - freq) / (f2 - f1);
            double t = dn < up ? dn : up;
            if (t < 0.0) t = 0.0;
            v = (float)t;
        }
        splitw(d_B2mel, (size_t)m * (2 * KP_MEL), KP_MEL, k, v);
    }

    for (int idx = tid; idx < 128 * KCONV; idx += nth) {
        int o = idx / KCONV, q = idx % KCONV;
        int kk = q >> 7, i = q & 127;
        splitw(d_B2conv, (size_t)o * (2 * KCONV), KCONV, q, conv_w[o * 384 + i * 3 + kk]);
    }

    for (int idx = tid; idx < G4 * KP_G; idx += nth) {
        int n = idx / KP_G, k = idx % KP_G;
        int no = gperm(n);
        splitw(d_B2W1p, (size_t)n * (2 * KP_G), KP_G, k, W1[k * G4 + no]);
        splitw(d_B2W2p, (size_t)n * (2 * KP_G), KP_G, k, W2[k * G4 + no]);
        splitw(d_U1p,   (size_t)n * (2 * KP_G), KP_G, k, U1[k * G4 + no]);
        splitw(d_U2p,   (size_t)n * (2 * KP_G), KP_G, k, U2[k * G4 + no]);
    }
    for (int n = tid; n < G4; n += nth) {
        int no = gperm(n);
        d_b1p[n] = b1[no];
        d_b2p[n] = b2[no];
    }

    for (int idx = tid; idx < R1 * (KP_MEL - NBINS); idx += nth) {
        int r = idx / (KP_MEL - NBINS), k = NBINS + idx % (KP_MEL - NBINS);
        d_A2mel[(size_t)r * (2 * KP_MEL) + k] = __float2bfloat16(0.f);
        d_A2mel[(size_t)r * (2 * KP_MEL) + KP_MEL + k] = __float2bfloat16(0.f);
    }
}

// ---------------- window ----------------
__global__ void k_window(const float* __restrict__ x) {
    int f = blockIdx.x, b = blockIdx.y, tid = threadIdx.x;
    size_t row = (size_t)(b * NFRAMES + f) * (2 * KP_DFT);
    for (int k = tid; k < KP_DFT; k += blockDim.x) {
        float v = 0.f;
        if (k < NFFT) {
            int p = f * HOP + k - 200;
            int i = (p < 0) ? -p : ((p >= TLEN) ? (2 * TLEN - 2 - p) : p);
            v = x[(size_t)b * TLEN + i] * d_hann[k];
        }
        __nv_bfloat16 h = __float2bfloat16(v);
        d_A2dft[row + k] = h;
        d_A2dft[row + KP_DFT + k] = __float2bfloat16(v - __bfloat162float(h));
    }
}

// ---------------- 3-stage pipelined split-bf16 tensor GEMM (ldmatrix fragments) ----------------
// mode 0: fp32 out (+bias); mode 1: power -> split pack; mode 2: split pack (+bias)
__global__ void __launch_bounds__(256)
k_gemm(const __nv_bfloat16* __restrict__ A2, const __nv_bfloat16* __restrict__ B2,
       int Kp, const float* __restrict__ bias, int mode,
       float* __restrict__ outF, int ldc, int Nreal,
       __nv_bfloat16* __restrict__ outP, int KpOut) {
    extern __shared__ __nv_bfloat16 sm[];
    int tid = threadIdx.x, lane = tid & 31, w = tid >> 5;
    int wm = w >> 1, wn = w & 1;
    int m0 = blockIdx.y * 128, n0 = blockIdx.x * 64;
    int g = lane >> 2, t = lane & 3;
    int strideA = 2 * Kp;
    int la_row = tid >> 2, la_kc = (tid & 3) << 3;
    int nchunks = Kp >> 5;

    // ldmatrix lane offsets
    int aRowOff = lane & 15;              // row within 16-row tile pair
    int aKOff   = (lane >> 4) << 3;       // k-half select
    int bRowOff = ((lane >> 4) << 3) + (lane & 7);
    int bKOff   = ((lane >> 3) & 1) << 3;

    const __nv_bfloat16* Abase = A2 + (size_t)m0 * strideA;
    const __nv_bfloat16* Bbase = B2 + (size_t)n0 * strideA;

    float acc[2][4][4];
    #pragma unroll
    for (int i = 0; i < 2; i++)
        #pragma unroll
        for (int j = 0; j < 4; j++)
            #pragma unroll
            for (int q = 0; q < 4; q++) acc[i][j][q] = 0.f;

    auto load_chunk = [&](int s, int kk) {
        __nv_bfloat16* st = sm + (size_t)s * GEMM_STAGE_ROWS * 40;
        const __nv_bfloat16* Ah0 = Abase + (size_t)la_row * strideA + kk + la_kc;
        const __nv_bfloat16* Ah1 = Abase + (size_t)(la_row + 64) * strideA + kk + la_kc;
        const __nv_bfloat16* Bh0 = Bbase + (size_t)la_row * strideA + kk + la_kc;
        cpa16(smaddr(st + (la_row)       * 40 + la_kc), Ah0);
        cpa16(smaddr(st + (la_row + 64)  * 40 + la_kc), Ah1);
        cpa16(smaddr(st + (128 + la_row) * 40 + la_kc), Ah0 + Kp);
        cpa16(smaddr(st + (192 + la_row) * 40 + la_kc), Ah1 + Kp);
        cpa16(smaddr(st + (256 + la_row) * 40 + la_kc), Bh0);
        cpa16(smaddr(st + (320 + la_row) * 40 + la_kc), Bh0 + Kp);
        cpa_commit();
    };

    load_chunk(0, 0);
    load_chunk(1, 32);

    #pragma unroll 1
    for (int c = 0; c < nchunks; c++) {
        int s = c % 3;
        if (c + 1 < nchunks) asm volatile("cp.async.wait_group 1;");
        else                 asm volatile("cp.async.wait_group 0;");
        __syncthreads();
        if (c + 2 < nchunks) load_chunk((c + 2) % 3, (c + 2) * 32);

        const __nv_bfloat16* st = sm + (size_t)s * GEMM_STAGE_ROWS * 40;
        #pragma unroll
        for (int ko = 0; ko < 32; ko += 16) {
            unsigned ahf[2][4], alf[2][4];
            #pragma unroll
            for (int i = 0; i < 2; i++) {
                ldsm4(ahf[i], smaddr(st + (wm * 32 + i * 16 + aRowOff) * 40 + ko + aKOff));
                ldsm4(alf[i], smaddr(st + (128 + wm * 32 + i * 16 + aRowOff) * 40 + ko + aKOff));
            }
            #pragma unroll
            for (int p = 0; p < 2; p++) {
                unsigned bh[4], bl[4];
                ldsm4(bh, smaddr(st + (256 + wn * 32 + p * 16 + bRowOff) * 40 + ko + bKOff));
                ldsm4(bl, smaddr(st + (320 + wn * 32 + p * 16 + bRowOff) * 40 + ko + bKOff));
                #pragma unroll
                for (int i = 0; i < 2; i++) {
                    mma16816(acc[i][2 * p],     ahf[i], bh[0], bh[1]);
                    mma16816(acc[i][2 * p],     ahf[i], bl[0], bl[1]);
                    mma16816(acc[i][2 * p],     alf[i], bh[0], bh[1]);
                    mma16816(acc[i][2 * p + 1], ahf[i], bh[2], bh[3]);
                    mma16816(acc[i][2 * p + 1], ahf[i], bl[2], bl[3]);
                    mma16816(acc[i][2 * p + 1], alf[i], bh[2], bh[3]);
                }
            }
        }
    }

    #pragma unroll
    for (int i = 0; i < 2; i++) {
        int r = m0 + wm * 32 + i * 16 + g;
        #pragma unroll
        for (int j = 0; j < 4; j++) {
            int c = n0 + wn * 32 + j * 8 + 2 * t;
            float v00 = acc[i][j][0], v01 = acc[i][j][1];
            float v10 = acc[i][j][2], v11 = acc[i][j][3];
            if (mode == 0) {
                float b0 = bias ? bias[c] : 0.f, b1 = bias ? bias[c + 1] : 0.f;
                outF[(size_t)r * ldc + c]           = v00 + b0;
                outF[(size_t)r * ldc + c + 1]       = v01 + b1;
                outF[(size_t)(r + 8) * ldc + c]     = v10 + b0;
                outF[(size_t)(r + 8) * ldc + c + 1] = v11 + b1;
            } else if (mode == 1) {
                int k = c >> 1;
                if (k < Nreal) {
                    splitw(outP, (size_t)r * (2 * KpOut), KpOut, k, v00 * v00 + v01 * v01);
                    splitw(outP, (size_t)(r + 8) * (2 * KpOut), KpOut, k, v10 * v10 + v11 * v11);
                }
            } else {
                float b0 = bias ? bias[c] : 0.f, b1 = bias ? bias[c + 1] : 0.f;
                splitw(outP, (size_t)r * (2 * KpOut), KpOut, c, v00 + b0);
                splitw(outP, (size_t)r * (2 * KpOut), KpOut, c + 1, v01 + b1);
                splitw(outP, (size_t)(r + 8) * (2 * KpOut), KpOut, c, v10 + b0);
                splitw(outP, (size_t)(r + 8) * (2 * KpOut), KpOut, c + 1, v11 + b1);
            }
        }
    }
}

// ---------------- conv GEMM: 4-stage pipeline, 36 chunks, ldmatrix ----------------
__global__ void __launch_bounds__(256)
k_gemm_conv(const __nv_bfloat16* __restrict__ Msp, const __nv_bfloat16* __restrict__ B2,
            const float* __restrict__ bias, __nv_bfloat16* __restrict__ outP) {
    extern __shared__ __nv_bfloat16 sm[];
    int tid = threadIdx.x, lane = tid & 31, w = tid >> 5;
    int wm = w >> 1, wn = w & 1;
    int m0 = blockIdx.y * 128, n0 = blockIdx.x * 64;
    int g = lane >> 2, t = lane & 3;
    int la_row = tid >> 2, la_kc = (tid & 3) << 3;
    const int nchunks = 36;

    int aRowOff = lane & 15;
    int aKOff   = (lane >> 4) << 3;
    int bRowOff = ((lane >> 4) << 3) + (lane & 7);
    int bKOff   = ((lane >> 3) & 1) << 3;

    int gm0 = m0 + la_row, gm1 = m0 + la_row + 64;
    int sr0 = gm0 + 2 * (gm0 / TSTEPS);
    int sr1 = gm1 + 2 * (gm1 / TSTEPS);

    float acc[2][4][4];
    #pragma unroll
    for (int i = 0; i < 2; i++)
        #pragma unroll
        for (int j = 0; j < 4; j++)
            #pragma unroll
            for (int q = 0; q < 4; q++) acc[i][j][q] = 0.f;

    auto load_chunk = [&](int s, int q) {
        int seg = q >> 2, kk = (q & 3) << 5;
        int split = seg / 3, shift = seg % 3;
        int aoff = (split == 2) ? 128 : 0;
        int boff = ((split == 1) ? KCONV : 0) + shift * 128;
        __nv_bfloat16* st = sm + (size_t)s * CONV_STAGE_ROWS * 40;
        cpa16(smaddr(st + la_row * 40 + la_kc),
              Msp + (size_t)(sr0 + shift) * 256 + aoff + kk + la_kc);
        cpa16(smaddr(st + (la_row + 64) * 40 + la_kc),
              Msp + (size_t)(sr1 + shift) * 256 + aoff + kk + la_kc);
        cpa16(smaddr(st + (128 + la_row) * 40 + la_kc),
              B2 + (size_t)(n0 + la_row) * (2 * KCONV) + boff + kk + la_kc);
        cpa_commit();
    };

    load_chunk(0, 0);
    load_chunk(1, 1);
    load_chunk(2, 2);

    #pragma unroll 1
    for (int q = 0; q < nchunks; q++) {
        int s = q & 3;
        int ahead = nchunks - 1 - q;
        if (ahead >= 2)      asm volatile("cp.async.wait_group 2;");
        else if (ahead == 1) asm volatile("cp.async.wait_group 1;");
        else                 asm volatile("cp.async.wait_group 0;");
        __syncthreads();
        if (q + 3 < nchunks) load_chunk((q + 3) & 3, q + 3);

        const __nv_bfloat16* st = sm + (size_t)s * CONV_STAGE_ROWS * 40;
        #pragma unroll
        for (int ko = 0; ko < 32; ko += 16) {
            unsigned a[2][4];
            #pragma unroll
            for (int i = 0; i < 2; i++)
                ldsm4(a[i], smaddr(st + (wm * 32 + i * 16 + aRowOff) * 40 + ko + aKOff));
            #pragma unroll
            for (int p = 0; p < 2; p++) {
                unsigned bfr[4];
                ldsm4(bfr, smaddr(st + (128 + wn * 32 + p * 16 + bRowOff) * 40 + ko + bKOff));
                #pragma unroll
                for (int i = 0; i < 2; i++) {
                    mma16816(acc[i][2 * p],     a[i], bfr[0], bfr[1]);
                    mma16816(acc[i][2 * p + 1], a[i], bfr[2], bfr[3]);
                }
            }
        }
    }

    #pragma unroll
    for (int i = 0; i < 2; i++) {
        int r = m0 + wm * 32 + i * 16 + g;
        #pragma unroll
        for (int j = 0; j < 4; j++) {
            int c = n0 + wn * 32 + j * 8 + 2 * t;
            float b0 = bias[c], b1 = bias[c + 1];
            splitw(outP, (size_t)r * 256, 128, c,     acc[i][j][0] + b0);
            splitw(outP, (size_t)r * 256, 128, c + 1, acc[i][j][1] + b1);
            splitw(outP, (size_t)(r + 8) * 256, 128, c,     acc[i][j][2] + b0);
            splitw(outP, (size_t)(r + 8) * 256, 128, c + 1, acc[i][j][3] + b1);
        }
    }
}

// ---------------- tensor-core LSTM v4: ldmatrix fragments ----------------
__global__ void __launch_bounds__(256)
k_lstm_mma(const float* __restrict__ gx, const __nv_bfloat16* __restrict__ Up,
           __nv_bfloat16* __restrict__ hsplit, float* __restrict__ hmean) {
    extern __shared__ __nv_bfloat16 sm[];
    __nv_bfloat16* Uh  = sm;
    __nv_bfloat16* Ulw = sm + SM_UH;
    __nv_bfloat16* Hsp = sm + SM_UH + SM_UL;

    int tid = threadIdx.x, lane = tid & 31, w = tid >> 5;
    int g = lane >> 2, tq = lane & 3;
    int b0 = blockIdx.x * 16;
    int wbase = w * 64;
    __nv_bfloat16* myUl = Ulw + w * SM_ULW;

    int aRowOff = lane & 15;
    int aKOff   = (lane >> 4) << 3;
    int bRowOff = ((lane >> 4) << 3) + (lane & 7);
    int bKOff   = ((lane >> 3) & 1) << 3;

    for (int idx = tid; idx < 512 * 16; idx += 256) {
        int n = idx >> 4, j = idx & 15;
        *(uint4*)(Uh + n * UH_STRIDE + j * 8) = *(const uint4*)(Up + (size_t)n * 256 + j * 8);
    }
    for (int idx = tid; idx < SM_H; idx += 256) Hsp[idx] = __float2bfloat16(0.f);

    float cst[8], hsum[8];
    #pragma unroll
    for (int i = 0; i < 8; i++) { cst[i] = 0.f; hsum[i] = 0.f; }

    for (int t = 0; t < TSTEPS; t++) {
        float acc[8][4];
        {
            size_t rlo = ((size_t)(b0 + g) * TSTEPS + t) * G4 + wbase + 2 * tq;
            size_t rhi = ((size_t)(b0 + g + 8) * TSTEPS + t) * G4 + wbase + 2 * tq;
            #pragma unroll
            for (int a = 0; a < 8; a++) {
                float2 v0 = *(const float2*)&gx[rlo + a * 8];
                float2 v1 = *(const float2*)&gx[rhi + a * 8];
                acc[a][0] = v0.x; acc[a][1] = v0.y;
                acc[a][2] = v1.x; acc[a][3] = v1.y;
            }
        }
        __syncthreads();

        #pragma unroll
        for (int c0 = 0; c0 < 2; c0++) {
            __nv_bfloat16* buf = myUl + (c0 % 3) * 64 * ULW_STRIDE;
            #pragma unroll
            for (int i = 0; i < 4; i++) {
                int u = lane + 32 * i, n1 = u >> 1, hf = u & 1;
                cpa16(smaddr(buf + n1 * ULW_STRIDE + hf * 8),
                      Up + (size_t)(wbase + n1) * 256 + 128 + c0 * 16 + hf * 8);
            }
            cpa_commit();
        }

        #pragma unroll 1
        for (int c = 0; c < 8; c++) {
            if (c < 7) asm volatile("cp.async.wait_group 1;");
            else       asm volatile("cp.async.wait_group 0;");
            __syncwarp();
            if (c + 2 < 8) {
                __nv_bfloat16* nbuf = myUl + ((c + 2) % 3) * 64 * ULW_STRIDE;
                #pragma unroll
                for (int i = 0; i < 4; i++) {
                    int u = lane + 32 * i, n1 = u >> 1, hf = u & 1;
                    cpa16(smaddr(nbuf + n1 * ULW_STRIDE + hf * 8),
                          Up + (size_t)(wbase + n1) * 256 + 128 + (c + 2) * 16 + hf * 8);
                }
                cpa_commit();
            }
            int ko = c * 16;
            unsigned ah[4], al[4];
            ldsm4(ah, smaddr(Hsp + aRowOff * H_STRIDE + ko + aKOff));
            ldsm4(al, smaddr(Hsp + aRowOff * H_STRIDE + 128 + ko + aKOff));
            const __nv_bfloat16* ulB = myUl + (c % 3) * 64 * ULW_STRIDE;
            #pragma unroll
            for (int p = 0; p < 4; p++) {
                unsigned ub[4], lb[4];
                ldsm4(ub, smaddr(Uh + (wbase + p * 16 + bRowOff) * UH_STRIDE + ko + bKOff));
                ldsm4(lb, smaddr(ulB + (p * 16 + bRowOff) * ULW_STRIDE + bKOff));
                mma16816(acc[2 * p],     ah, ub[0], ub[1]);
                mma16816(acc[2 * p],     al, ub[0], ub[1]);
                mma16816(acc[2 * p],     ah, lb[0], lb[1]);
                mma16816(acc[2 * p + 1], ah, ub[2], ub[3]);
                mma16816(acc[2 * p + 1], al, ub[2], ub[3]);
                mma16816(acc[2 * p + 1], ah, lb[2], lb[3]);
            }
        }
        __syncthreads();

        #pragma unroll
        for (int uh = 0; uh < 2; uh++)
            #pragma unroll
            for (int par = 0; par < 2; par++)
                #pragma unroll
                for (int q2 = 0; q2 < 2; q2++) {
                    int u = uh * 8 + 2 * tq + par;
                    int r = g + 8 * q2;
                    int qq = q2 * 2 + par;
                    int ci = uh * 4 + par * 2 + q2;
                    float gi = acc[0 + uh][qq];
                    float gf = acc[2 + uh][qq];
                    float gg = acc[4 + uh][qq];
                    float go = acc[6 + uh][qq];
                    float c = sigf(gf) * cst[ci] + sigf(gi) * tanhf_acc(gg);
                    float h = sigf(go) * tanhf_acc(c);
                    cst[ci] = c;
                    int ug = w * 16 + u;
                    __nv_bfloat16 hh = __float2bfloat16(h);
                    __nv_bfloat16 hl = __float2bfloat16(h - __bfloat162float(hh));
                    Hsp[r * H_STRIDE + ug] = hh;
                    Hsp[r * H_STRIDE + 128 + ug] = hl;
                    if (hsplit) {
                        size_t row2 = ((size_t)(b0 + r) * TSTEPS + t) * 256;
                        hsplit[row2 + ug] = hh;
                        hsplit[row2 + 128 + ug] = hl;
                    }
                    hsum[ci] += h;
                }
    }

    if (hmean) {
        #pragma unroll
        for (int uh = 0; uh < 2; uh++)
            #pragma unroll
            for (int par = 0; par < 2; par++)
                #pragma unroll
                for (int q2 = 0; q2 < 2; q2++) {
                    int u = uh * 8 + 2 * tq + par;
                    int r = g + 8 * q2;
                    int ci = uh * 4 + par * 2 + q2;
                    hmean[(size_t)(b0 + r) * 128 + w * 16 + u] = hsum[ci] * (1.0f / (float)TSTEPS);
                }
    }
}

// ---------------- small fp32 SGEMM for fc/proj ----------------
__global__ void k_sgemm(const float* __restrict__ A, const float* __restrict__ Bm,
                        float* __restrict__ C, const float* __restrict__ bias,
                        int M, int N, int K) {
    __shared__ float As[8][68];
    __shared__ float Bs[8][64];
    int tid = threadIdx.x;
    int m0 = blockIdx.y * 64, n0 = blockIdx.x * 64;
    int tm = tid & 15, tn = tid >> 4;
    float acc[4][8];
    #pragma unroll
    for (int i = 0; i < 4; i++)
        #pragma unroll
        for (int j = 0; j < 8; j++) acc[i][j] = 0.f;
    for (int kk = 0; kk < K; kk += 8) {
        #pragma unroll
        for (int i = 0; i < 4; i++) {
            int l = tid + i * 128, m = l >> 3, k = l & 7;
            int gm = m0 + m, gk = kk + k;
            As[k][m] = (gm < M && gk < K) ? A[(size_t)gm * K + gk] : 0.f;
        }
        #pragma unroll
        for (int i = 0; i < 4; i++) {
            int l = tid + i * 128, k = l >> 6, n = l & 63;
            int gk = kk + k, gn = n0 + n;
            Bs[k][n] = (gk < K && gn < N) ? Bm[(size_t)gk * N + gn] : 0.f;
        }
        __syncthreads();
        #pragma unroll
        for (int k = 0; k < 8; k++) {
            float a[4], bv[8];
            #pragma unroll
            for (int i = 0; i < 4; i++) a[i] = As[k][tm * 4 + i];
            #pragma unroll
            for (int j = 0; j < 8; j++) bv[j] = Bs[k][tn * 8 + j];
            #pragma unroll
            for (int i = 0; i < 4; i++)
                #pragma unroll
                for (int j = 0; j < 8; j++) acc[i][j] += a[i] * bv[j];
        }
        __syncthreads();
    }
    #pragma unroll
    for (int i = 0; i < 4; i++) {
        int gm = m0 + tm * 4 + i;
        if (gm >= M) continue;
        #pragma unroll
        for (int j = 0; j < 8; j++) {
            int gn = n0 + tn * 8 + j;
            if (gn < N) C[(size_t)gm * N + gn] = acc[i][j] + (bias ? bias[gn] : 0.f);
        }
    }
}

// ---------------- launch ----------------
extern "C" void kernel_launch(void* const* d_in, const int* in_sizes, int n_in,
                              void* d_out, int out_size) {
    const float* x      = (const float*)d_in[0];
    const float* conv_w = (const float*)d_in[1];
    const float* conv_b = (const float*)d_in[2];
    const float* W1     = (const float*)d_in[3];
    const float* U1     = (const float*)d_in[4];
    const float* b1     = (const float*)d_in[5];
    const float* W2     = (const float*)d_in[6];
    const float* U2     = (const float*)d_in[7];
    const float* b2     = (const float*)d_in[8];
    const float* fc1_w  = (const float*)d_in[9];
    const float* fc1_b  = (const float*)d_in[10];
    const float* proj_w = (const float*)d_in[11];
    const float* proj_b = (const float*)d_in[12];
    float* out = (float*)d_out;

    __nv_bfloat16 *pA2dft, *pB2dft, *pA2mel, *pB2mel, *pMelsp, *pB2conv, *pA2g;
    __nv_bfloat16 *pB2W1p, *pB2W2p, *pU1p, *pU2p, *pH1s;
    float *pG, *pHmean, *pHfc, *pB1p, *pB2p;
    cudaGetSymbolAddress((void**)&pA2dft,  d_A2dft);
    cudaGetSymbolAddress((void**)&pB2dft,  d_B2dft);
    cudaGetSymbolAddress((void**)&pA2mel,  d_A2mel);
    cudaGetSymbolAddress((void**)&pB2mel,  d_B2mel);
    cudaGetSymbolAddress((void**)&pMelsp,  d_melsp);
    cudaGetSymbolAddress((void**)&pB2conv, d_B2conv);
    cudaGetSymbolAddress((void**)&pA2g,    d_A2g);
    cudaGetSymbolAddress((void**)&pB2W1p,  d_B2W1p);
    cudaGetSymbolAddress((void**)&pB2W2p,  d_B2W2p);
    cudaGetSymbolAddress((void**)&pU1p,    d_U1p);
    cudaGetSymbolAddress((void**)&pU2p,    d_U2p);
    cudaGetSymbolAddress((void**)&pH1s,    d_h1s);
    cudaGetSymbolAddress((void**)&pG,      d_g);
    cudaGetSymbolAddress((void**)&pHmean,  d_hmean);
    cudaGetSymbolAddress((void**)&pHfc,    d_hfc);
    cudaGetSymbolAddress((void**)&pB1p,    d_b1p);
    cudaGetSymbolAddress((void**)&pB2p,    d_b2p);

    cudaFuncSetAttribute(k_lstm_mma,  cudaFuncAttributeMaxDynamicSharedMemorySize, LSTM_SMEM_BYTES);
    cudaFuncSetAttribute(k_gemm,      cudaFuncAttributeMaxDynamicSharedMemorySize, GEMM_SMEM_BYTES);
    cudaFuncSetAttribute(k_gemm_conv, cudaFuncAttributeMaxDynamicSharedMemorySize, CONV_SMEM_BYTES);

    k_precompute<<<128, 256>>>(conv_w, W1, W2, U1, U2, b1, b2);
    k_window<<<dim3(NFRAMES, BATCH), 256>>>(x);

    // DFT -> power split-pack into A2mel
    k_gemm<<<dim3(NP_DFT / 64, R1 / 128), 256, GEMM_SMEM_BYTES>>>(
        pA2dft, pB2dft, KP_DFT, nullptr, 1, nullptr, 0, NBINS, pA2mel, KP_MEL);
    // mel -> split pack
    k_gemm<<<dim3(2, R1 / 128), 256, GEMM_SMEM_BYTES>>>(
        pA2mel, pB2mel, KP_MEL, nullptr, 2, nullptr, 0, NMELS, pMelsp, 128);
    // conv (shifted-row) -> split pack into A2g
    k_gemm_conv<<<dim3(2, R2 / 128), 256, CONV_SMEM_BYTES>>>(pMelsp, pB2conv, conv_b, pA2g);
    // g1 (permuted gates)
    k_gemm<<<dim3(8, R2 / 128), 256, GEMM_SMEM_BYTES>>>(
        pA2g, pB2W1p, KP_G, pB1p, 0, pG, G4, G4, nullptr, 0);
    k_lstm_mma<<<BATCH / 16, 256, LSTM_SMEM_BYTES>>>(pG, pU1p, pH1s, nullptr);
    // g2 (permuted gates)
    k_gemm<<<dim3(8, R2 / 128), 256, GEMM_SMEM_BYTES>>>(
        pH1s, pB2W2p, KP_G, pB2p, 0, pG, G4, G4, nullptr, 0);
    k_lstm_mma<<<BATCH / 16, 256, LSTM_SMEM_BYTES>>>(pG, pU2p, nullptr, pHmean);

    k_sgemm<<<dim3(2, BATCH / 64), 128>>>(pHmean, fc1_w, pHfc, fc1_b, BATCH, 128, 128);
    k_sgemm<<<dim3(1, BATCH / 64), 128>>>(pHfc, proj_w, out, proj_b, BATCH, 35, 128);
}

// round 8
// speedup vs baseline: 1.3749x; 1.3749x over previous
#include <cuda_runtime.h>
#include <cuda_bf16.h>
#include <math.h>

// ---------------- problem dims ----------------
#define BATCH   1024
#define TLEN    16000
#define NFFT    400
#define HOP     200
#define NBINS   201
#define NMELS   128
#define NFRAMES 81
#define TSTEPS  79
#define HID     128
#define G4      512
#define R1      (BATCH*NFRAMES)   // 82944
#define R2      (BATCH*TSTEPS)    // 80896

#define KP_DFT  416
#define KP_MEL  224
#define KP_G    128
#define NP_DFT  448
#define KCONV   384

// ---- DFT A-resident kernel smem (bf16 elements) ----
#define AH_STRIDE 424
#define DFT_SM_A   (2*64*AH_STRIDE)        // Ah + Al = 54272
#define DFT_BSTAGE (128*40)                // Bh rows 0-63, Bl rows 64-127 = 5120
#define DFT_SMEM_ELEMS (DFT_SM_A + 3*DFT_BSTAGE)   // 69632
#define DFT_SMEM_BYTES (DFT_SMEM_ELEMS*2)          // 139264

// LSTM smem (bf16 elements)
#define UH_STRIDE 136
#define ULW_STRIDE 24
#define H_STRIDE  264
#define SM_UH   (512*UH_STRIDE)
#define SM_ULW  (3*64*ULW_STRIDE)
#define SM_UL   (8*SM_ULW)
#define SM_H    (16*H_STRIDE)
#define LSTM_SMEM_BYTES ((SM_UH + SM_UL + SM_H)*2)  // 221440

// ---------------- scratch ----------------
__device__ float          d_hann[NFFT];
__device__ __nv_bfloat16  d_A2dft[(size_t)R1 * 2 * KP_DFT];
__device__ __nv_bfloat16  d_B2dft[(size_t)NP_DFT * 2 * KP_DFT];
__device__ __nv_bfloat16  d_A2mel[(size_t)R1 * 2 * KP_MEL];
__device__ __nv_bfloat16  d_B2mel[(size_t)128 * 2 * KP_MEL];
__device__ __nv_bfloat16  d_melsp[(size_t)R1 * 256];
__device__ __nv_bfloat16  d_B2conv[(size_t)128 * 2 * KCONV];
__device__ __nv_bfloat16  d_A2g[(size_t)R2 * 2 * KP_G];
__device__ __nv_bfloat16  d_B2W1p[(size_t)G4 * 2 * KP_G];
__device__ __nv_bfloat16  d_B2W2p[(size_t)G4 * 2 * KP_G];
__device__ __nv_bfloat16  d_U1p[(size_t)G4 * 2 * KP_G];
__device__ __nv_bfloat16  d_U2p[(size_t)G4 * 2 * KP_G];
__device__ float          d_b1p[G4];
__device__ float          d_b2p[G4];
__device__ float          d_g[(size_t)R2 * G4];
__device__ __nv_bfloat16  d_h1s[(size_t)R2 * 2 * KP_G];
__device__ float          d_hmean[BATCH * 128];
__device__ float          d_hfc[BATCH * 128];

// ---------------- helpers ----------------
__device__ __forceinline__ float sigf(float x) { return 1.0f / (1.0f + __expf(-x)); }
__device__ __forceinline__ float tanhf_acc(float x) {
    float t = __expf(-2.0f * fabsf(x));
    float r = (1.0f - t) / (1.0f + t);
    return copysignf(r, x);
}
__device__ __forceinline__ void splitw(__nv_bfloat16* P, size_t base, int KpOut, int k, float v) {
    __nv_bfloat16 h = __float2bfloat16(v);
    P[base + k] = h;
    P[base + KpOut + k] = __float2bfloat16(v - __bfloat162float(h));
}
__device__ __forceinline__ unsigned smaddr(const void* p) {
    return (unsigned)__cvta_generic_to_shared(p);
}
__device__ __forceinline__ void cpa16(unsigned dst, const void* src) {
    asm volatile("cp.async.cg.shared.global [%0], [%1], 16;" :: "r"(dst), "l"(src));
}
__device__ __forceinline__ void cpa_commit() { asm volatile("cp.async.commit_group;"); }
__device__ __forceinline__ void mma16816(float* c, const unsigned* a, unsigned b0, unsigned b1) {
    asm volatile(
        "mma.sync.aligned.m16n8k16.row.col.f32.bf16.bf16.f32 "
        "{%0,%1,%2,%3}, {%4,%5,%6,%7}, {%8,%9}, {%0,%1,%2,%3};"
        : "+f"(c[0]), "+f"(c[1]), "+f"(c[2]), "+f"(c[3])
        : "r"(a[0]), "r"(a[1]), "r"(a[2]), "r"(a[3]), "r"(b0), "r"(b1));
}
__device__ __forceinline__ int gperm(int n) {
    int w = n >> 6, s = n & 63, gate = s >> 4, u = s & 15;
    return gate * 128 + w * 16 + u;
}

// ---------------- precompute ----------------
__global__ void k_precompute(const float* __restrict__ conv_w,
                             const float* __restrict__ W1, const float* __restrict__ W2,
                             const float* __restrict__ U1, const float* __restrict__ U2,
                             const float* __restrict__ b1, const float* __restrict__ b2) {
    int tid = blockIdx.x * blockDim.x + threadIdx.x;
    int nth = gridDim.x * blockDim.x;

    for (int k = tid; k < NFFT; k += nth)
        d_hann[k] = (float)(0.5 - 0.5 * cospi((double)k / 200.0));

    for (int idx = tid; idx < NP_DFT * KP_DFT; idx += nth) {
        int n = idx / KP_DFT, k = idx % KP_DFT;
        float v = 0.f;
        if (n < 2 * NBINS && k < NFFT) {
            int m = n >> 1;
            int ph = (m * k) % 400;
            double s, c;
            sincospi((double)ph / 200.0, &s, &c);
            v = (float)((n & 1) ? s : c);
        }
        splitw(d_B2dft, (size_t)n * (2 * KP_DFT), KP_DFT, k, v);
    }

    const double mel_max = 2595.0 * log10(1.0 + 8000.0 / 700.0);
    for (int idx = tid; idx < 128 * KP_MEL; idx += nth) {
        int m = idx / KP_MEL, k = idx % KP_MEL;
        float v = 0.f;
        if (k < NBINS) {
            double freq = 40.0 * (double)k;
            double f0 = 700.0 * (pow(10.0, (mel_max * (double)(m    ) / 129.0) / 2595.0) - 1.0);
            double f1 = 700.0 * (pow(10.0, (mel_max * (double)(m + 1) / 129.0) / 2595.0) - 1.0);
            double f2 = 700.0 * (pow(10.0, (mel_max * (double)(m + 2) / 129.0) / 2595.0) - 1.0);
            double dn = (freq - f0) / (f1 - f0);
            double up = (f2 - freq) / (f2 - f1);
            double t = dn < up ? dn : up;
            if (t < 0.0) t = 0.0;
            v = (float)t;
        }
        splitw(d_B2mel, (size_t)m * (2 * KP_MEL), KP_MEL, k, v);
    }

    for (int idx = tid; idx < 128 * KCONV; idx += nth) {
        int o = idx / KCONV, q = idx % KCONV;
        int kk = q >> 7, i = q & 127;
        splitw(d_B2conv, (size_t)o * (2 * KCONV), KCONV, q, conv_w[o * 384 + i * 3 + kk]);
    }

    for (int idx = tid; idx < G4 * KP_G; idx += nth) {
        int n = idx / KP_G, k = idx % KP_G;
        int no = gperm(n);
        splitw(d_B2W1p, (size_t)n * (2 * KP_G), KP_G, k, W1[k * G4 + no]);
        splitw(d_B2W2p, (size_t)n * (2 * KP_G), KP_G, k, W2[k * G4 + no]);
        splitw(d_U1p,   (size_t)n * (2 * KP_G), KP_G, k, U1[k * G4 + no]);
        splitw(d_U2p,   (size_t)n * (2 * KP_G), KP_G, k, U2[k * G4 + no]);
    }
    for (int n = tid; n < G4; n += nth) {
        int no = gperm(n);
        d_b1p[n] = b1[no];
        d_b2p[n] = b2[no];
    }

    for (int idx = tid; idx < R1 * (KP_MEL - NBINS); idx += nth) {
        int r = idx / (KP_MEL - NBINS), k = NBINS + idx % (KP_MEL - NBINS);
        d_A2mel[(size_t)r * (2 * KP_MEL) + k] = __float2bfloat16(0.f);
        d_A2mel[(size_t)r * (2 * KP_MEL) + KP_MEL + k] = __float2bfloat16(0.f);
    }
}

// ---------------- window ----------------
__global__ void k_window(const float* __restrict__ x) {
    int f = blockIdx.x, b = blockIdx.y, tid = threadIdx.x;
    size_t row = (size_t)(b * NFRAMES + f) * (2 * KP_DFT);
    for (int k = tid; k < KP_DFT; k += blockDim.x) {
        float v = 0.f;
        if (k < NFFT) {
            int p = f * HOP + k - 200;
            int i = (p < 0) ? -p : ((p >= TLEN) ? (2 * TLEN - 2 - p) : p);
            v = x[(size_t)b * TLEN + i] * d_hann[k];
        }
        __nv_bfloat16 h = __float2bfloat16(v);
        d_A2dft[row + k] = h;
        d_A2dft[row + KP_DFT + k] = __float2bfloat16(v - __bfloat162float(h));
    }
}

// ---------------- DFT GEMM: A-resident (M=64/block), B streamed 3-stage ----------------
// A read from DRAM exactly once. Epilogue: power split-pack into A2mel.
__global__ void __launch_bounds__(256)
k_gemm_dft(const __nv_bfloat16* __restrict__ A2, const __nv_bfloat16* __restrict__ B2,
           __nv_bfloat16* __restrict__ outP) {
    extern __shared__ __nv_bfloat16 sm[];
    __nv_bfloat16* Ah = sm;                        // [64][424]
    __nv_bfloat16* Al = sm + 64 * AH_STRIDE;       // [64][424]
    __nv_bfloat16* Bst = sm + DFT_SM_A;            // 3 stages x [128][40] (Bh 0-63, Bl 64-127)

    int tid = threadIdx.x, lane = tid & 31, w = tid >> 5;
    int wm = w >> 2, wn = w & 3;                   // 2 m-halves x 4 n-quarters
    int m0 = blockIdx.x * 64;
    int g = lane >> 2, t = lane & 3;
    int lb_row = tid >> 2, lb_kc = (tid & 3) << 3;

    const __nv_bfloat16* Abase = A2 + (size_t)m0 * (2 * KP_DFT);

    // ---- load A slice (hi+lo) into smem once ----
    for (int i = tid; i < 64 * 52 * 2; i += 256) {
        int row = i / 104, rem = i % 104;
        int half = rem / 52, off = (rem % 52) * 8;
        __nv_bfloat16* dst = (half ? Al : Ah) + row * AH_STRIDE + off;
        cpa16(smaddr(dst), Abase + (size_t)row * (2 * KP_DFT) + half * KP_DFT + off);
    }
    cpa_commit();

    auto loadB = [&](int s, int q) {
        int n0 = q / 13, kc = q % 13;
        __nv_bfloat16* st = Bst + s * DFT_BSTAGE;
        const __nv_bfloat16* src = B2 + (size_t)(n0 * 64 + lb_row) * (2 * KP_DFT) + kc * 32 + lb_kc;
        cpa16(smaddr(st + lb_row * 40 + lb_kc), src);
        cpa16(smaddr(st + (64 + lb_row) * 40 + lb_kc), src + KP_DFT);
        cpa_commit();
    };

    loadB(0, 0);
    loadB(1, 1);

    float acc[2][2][4];
    #pragma unroll
    for (int i = 0; i < 2; i++)
        #pragma unroll
        for (int j = 0; j < 2; j++)
            #pragma unroll
            for (int q = 0; q < 4; q++) acc[i][j][q] = 0.f;

    #pragma unroll 1
    for (int q = 0; q < 91; q++) {       // 7 n-tiles x 13 k-chunks
        int s = q % 3, n0 = q / 13, kc = q % 13;
        if (q + 1 < 91) asm volatile("cp.async.wait_group 1;");
        else            asm volatile("cp.async.wait_group 0;");
        __syncthreads();
        if (q + 2 < 91) loadB((q + 2) % 3, q + 2);

        const __nv_bfloat16* st = Bst + s * DFT_BSTAGE;
        #pragma unroll
        for (int ko = 0; ko < 32; ko += 16) {
            int kg = kc * 32 + ko + 2 * t;
            unsigned ahf[2][4], alf[2][4], bhf[2][2], blf[2][2];
            #pragma unroll
            for (int i = 0; i < 2; i++) {
                int r = wm * 32 + i * 16;
                ahf[i][0] = *(const unsigned*)&Ah[(r + g) * AH_STRIDE + kg];
                ahf[i][1] = *(const unsigned*)&Ah[(r + g + 8) * AH_STRIDE + kg];
                ahf[i][2] = *(const unsigned*)&Ah[(r + g) * AH_STRIDE + kg + 8];
                ahf[i][3] = *(const unsigned*)&Ah[(r + g + 8) * AH_STRIDE + kg + 8];
                alf[i][0] = *(const unsigned*)&Al[(r + g) * AH_STRIDE + kg];
                alf[i][1] = *(const unsigned*)&Al[(r + g + 8) * AH_STRIDE + kg];
                alf[i][2] = *(const unsigned*)&Al[(r + g) * AH_STRIDE + kg + 8];
                alf[i][3] = *(const unsigned*)&Al[(r + g + 8) * AH_STRIDE + kg + 8];
            }
            #pragma unroll
            for (int j = 0; j < 2; j++) {
                int bn = wn * 16 + j * 8 + g;
                bhf[j][0] = *(const unsigned*)&st[bn * 40 + ko + 2 * t];
                bhf[j][1] = *(const unsigned*)&st[bn * 40 + ko + 2 * t + 8];
                blf[j][0] = *(const unsigned*)&st[(64 + bn) * 40 + ko + 2 * t];
                blf[j][1] = *(const unsigned*)&st[(64 + bn) * 40 + ko + 2 * t + 8];
            }
            #pragma unroll
            for (int i = 0; i < 2; i++)
                #pragma unroll
                for (int j = 0; j < 2; j++) {
                    mma16816(acc[i][j], ahf[i], bhf[j][0], bhf[j][1]);
                    mma16816(acc[i][j], ahf[i], blf[j][0], blf[j][1]);
                    mma16816(acc[i][j], alf[i], bhf[j][0], bhf[j][1]);
                }
        }

        if (kc == 12) {   // end of this n-tile: power epilogue, reset acc
            #pragma unroll
            for (int i = 0; i < 2; i++) {
                int r = m0 + wm * 32 + i * 16 + g;
                #pragma unroll
                for (int j = 0; j < 2; j++) {
                    int c = n0 * 64 + wn * 16 + j * 8 + 2 * t;
                    int k = c >> 1;
                    if (k < NBINS) {
                        float p0 = acc[i][j][0] * acc[i][j][0] + acc[i][j][1] * acc[i][j][1];
                        float p1 = acc[i][j][2] * acc[i][j][2] + acc[i][j][3] * acc[i][j][3];
                        splitw(outP, (size_t)r * (2 * KP_MEL), KP_MEL, k, p0);
                        splitw(outP, (size_t)(r + 8) * (2 * KP_MEL), KP_MEL, k, p1);
                    }
                    #pragma unroll
                    for (int qq = 0; qq < 4; qq++) acc[i][j][qq] = 0.f;
                }
            }
        }
    }
}

// ---------------- single-pass split-bf16 tensor GEMM (R5 proven version) ----------------
// mode 0: fp32 out (+bias); mode 2: split pack (+bias)
__global__ void __launch_bounds__(256)
k_gemm(const __nv_bfloat16* __restrict__ A2, const __nv_bfloat16* __restrict__ B2,
       int Kp, const float* __restrict__ bias, int mode,
       float* __restrict__ outF, int ldc, int Nreal,
       __nv_bfloat16* __restrict__ outP, int KpOut) {
    __shared__ __nv_bfloat16 Ah[2][128][40];
    __shared__ __nv_bfloat16 Al[2][128][40];
    __shared__ __nv_bfloat16 Bh[2][64][40];
    __shared__ __nv_bfloat16 Bl[2][64][40];
    int tid = threadIdx.x, lane = tid & 31, w = tid >> 5;
    int wm = w >> 1, wn = w & 1;
    int m0 = blockIdx.y * 128, n0 = blockIdx.x * 64;
    int g = lane >> 2, t = lane & 3;
    int strideA = 2 * Kp;
    int la_row = tid >> 2, la_kc = (tid & 3) << 3;

    const __nv_bfloat16* Abase = A2 + (size_t)m0 * strideA;
    const __nv_bfloat16* Bbase = B2 + (size_t)n0 * strideA;

    float acc[2][4][4];
    #pragma unroll
    for (int i = 0; i < 2; i++)
        #pragma unroll
        for (int j = 0; j < 4; j++)
            #pragma unroll
            for (int q = 0; q < 4; q++) acc[i][j][q] = 0.f;

    {
        cpa16(smaddr(&Ah[0][la_row][la_kc]),      Abase + (size_t)la_row * strideA + la_kc);
        cpa16(smaddr(&Ah[0][la_row + 64][la_kc]), Abase + (size_t)(la_row + 64) * strideA + la_kc);
        cpa16(smaddr(&Al[0][la_row][la_kc]),      Abase + (size_t)la_row * strideA + Kp + la_kc);
        cpa16(smaddr(&Al[0][la_row + 64][la_kc]), Abase + (size_t)(la_row + 64) * strideA + Kp + la_kc);
        cpa16(smaddr(&Bh[0][la_row][la_kc]),      Bbase + (size_t)la_row * strideA + la_kc);
        cpa16(smaddr(&Bl[0][la_row][la_kc]),      Bbase + (size_t)la_row * strideA + Kp + la_kc);
        cpa_commit();
    }
    #pragma unroll 1
    for (int kk = 0; kk < Kp; kk += 32) {
        int buf = (kk >> 5) & 1;
        asm volatile("cp.async.wait_group 0;");
        __syncthreads();
        if (kk + 32 < Kp) {
            int nb = buf ^ 1, kn = kk + 32;
            cpa16(smaddr(&Ah[nb][la_row][la_kc]),      Abase + (size_t)la_row * strideA + kn + la_kc);
            cpa16(smaddr(&Ah[nb][la_row + 64][la_kc]), Abase + (size_t)(la_row + 64) * strideA + kn + la_kc);
            cpa16(smaddr(&Al[nb][la_row][la_kc]),      Abase + (size_t)la_row * strideA + Kp + kn + la_kc);
            cpa16(smaddr(&Al[nb][la_row + 64][la_kc]), Abase + (size_t)(la_row + 64) * strideA + Kp + kn + la_kc);
            cpa16(smaddr(&Bh[nb][la_row][la_kc]),      Bbase + (size_t)la_row * strideA + kn + la_kc);
            cpa16(smaddr(&Bl[nb][la_row][la_kc]),      Bbase + (size_t)la_row * strideA + Kp + kn + la_kc);
            cpa_commit();
        }
        #pragma unroll
        for (int ko = 0; ko < 32; ko += 16) {
            unsigned ahf[2][4], alf[2][4], bhf[4][2], blf[4][2];
            #pragma unroll
            for (int i = 0; i < 2; i++) {
                int r = wm * 32 + i * 16;
                ahf[i][0] = *(const unsigned*)&Ah[buf][r + g][ko + 2 * t];
                ahf[i][1] = *(const unsigned*)&Ah[buf][r + g + 8][ko + 2 * t];
                ahf[i][2] = *(const unsigned*)&Ah[buf][r + g][ko + 2 * t + 8];
                ahf[i][3] = *(const unsigned*)&Ah[buf][r + g + 8][ko + 2 * t + 8];
                alf[i][0] = *(const unsigned*)&Al[buf][r + g][ko + 2 * t];
                alf[i][1] = *(const unsigned*)&Al[buf][r + g + 8][ko + 2 * t];
                alf[i][2] = *(const unsigned*)&Al[buf][r + g][ko + 2 * t + 8];
                alf[i][3] = *(const unsigned*)&Al[buf][r + g + 8][ko + 2 * t + 8];
            }
            #pragma unroll
            for (int j = 0; j < 4; j++) {
                int bn = wn * 32 + j * 8 + g;
                bhf[j][0] = *(const unsigned*)&Bh[buf][bn][ko + 2 * t];
                bhf[j][1] = *(const unsigned*)&Bh[buf][bn][ko + 2 * t + 8];
                blf[j][0] = *(const unsigned*)&Bl[buf][bn][ko + 2 * t];
                blf[j][1] = *(const unsigned*)&Bl[buf][bn][ko + 2 * t + 8];
            }
            #pragma unroll
            for (int i = 0; i < 2; i++)
                #pragma unroll
                for (int j = 0; j < 4; j++) {
                    mma16816(acc[i][j], ahf[i], bhf[j][0], bhf[j][1]);
                    mma16816(acc[i][j], ahf[i], blf[j][0], blf[j][1]);
                    mma16816(acc[i][j], alf[i], bhf[j][0], bhf[j][1]);
                }
        }
        __syncthreads();
    }

    #pragma unroll
    for (int i = 0; i < 2; i++) {
        int r = m0 + wm * 32 + i * 16 + g;
        #pragma unroll
        for (int j = 0; j < 4; j++) {
            int c = n0 + wn * 32 + j * 8 + 2 * t;
            float v00 = acc[i][j][0], v01 = acc[i][j][1];
            float v10 = acc[i][j][2], v11 = acc[i][j][3];
            if (mode == 0) {
                float b0 = bias ? bias[c] : 0.f, b1 = bias ? bias[c + 1] : 0.f;
                outF[(size_t)r * ldc + c]           = v00 + b0;
                outF[(size_t)r * ldc + c + 1]       = v01 + b1;
                outF[(size_t)(r + 8) * ldc + c]     = v10 + b0;
                outF[(size_t)(r + 8) * ldc + c + 1] = v11 + b1;
            } else {
                float b0 = bias ? bias[c] : 0.f, b1 = bias ? bias[c + 1] : 0.f;
                splitw(outP, (size_t)r * (2 * KpOut), KpOut, c, v00 + b0);
                splitw(outP, (size_t)r * (2 * KpOut), KpOut, c + 1, v01 + b1);
                splitw(outP, (size_t)(r + 8) * (2 * KpOut), KpOut, c, v10 + b0);
                splitw(outP, (size_t)(r + 8) * (2 * KpOut), KpOut, c + 1, v11 + b1);
            }
        }
    }
}

// ---------------- conv GEMM (R5 proven version): shifted rows, 9 segments ----------------
__global__ void __launch_bounds__(256)
k_gemm_conv(const __nv_bfloat16* __restrict__ Msp, const __nv_bfloat16* __restrict__ B2,
            const float* __restrict__ bias, __nv_bfloat16* __restrict__ outP) {
    __shared__ __nv_bfloat16 As[2][128][40];
    __shared__ __nv_bfloat16 Bs[2][64][40];
    int tid = threadIdx.x, lane = tid & 31, w = tid >> 5;
    int wm = w >> 1, wn = w & 1;
    int m0 = blockIdx.y * 128, n0 = blockIdx.x * 64;
    int g = lane >> 2, t = lane & 3;
    int la_row = tid >> 2, la_kc = (tid & 3) << 3;

    int gm0 = m0 + la_row, gm1 = m0 + la_row + 64;
    int sr0 = gm0 + 2 * (gm0 / TSTEPS);
    int sr1 = gm1 + 2 * (gm1 / TSTEPS);

    float acc[2][4][4];
    #pragma unroll
    for (int i = 0; i < 2; i++)
        #pragma unroll
        for (int j = 0; j < 4; j++)
            #pragma unroll
            for (int q = 0; q < 4; q++) acc[i][j][q] = 0.f;

    #pragma unroll 1
    for (int s = 0; s < 9; s++) {
        int split = s / 3, shift = s % 3;
        int aoff = (split == 2) ? 128 : 0;
        int boff = ((split == 1) ? KCONV : 0) + shift * 128;
        const __nv_bfloat16* A0 = Msp + (size_t)(sr0 + shift) * 256 + aoff;
        const __nv_bfloat16* A1 = Msp + (size_t)(sr1 + shift) * 256 + aoff;
        const __nv_bfloat16* Bb = B2 + (size_t)n0 * (2 * KCONV) + boff;

        cpa16(smaddr(&As[0][la_row][la_kc]),      A0 + la_kc);
        cpa16(smaddr(&As[0][la_row + 64][la_kc]), A1 + la_kc);
        cpa16(smaddr(&Bs[0][la_row][la_kc]),      Bb + (size_t)la_row * (2 * KCONV) + la_kc);
        cpa_commit();
        #pragma unroll 1
        for (int kk = 0; kk < 128; kk += 32) {
            int buf = (kk >> 5) & 1;
            asm volatile("cp.async.wait_group 0;");
            __syncthreads();
            if (kk + 32 < 128) {
                int nb = buf ^ 1, kn = kk + 32;
                cpa16(smaddr(&As[nb][la_row][la_kc]),      A0 + kn + la_kc);
                cpa16(smaddr(&As[nb][la_row + 64][la_kc]), A1 + kn + la_kc);
                cpa16(smaddr(&Bs[nb][la_row][la_kc]),      Bb + (size_t)la_row * (2 * KCONV) + kn + la_kc);
                cpa_commit();
            }
            #pragma unroll
            for (int ko = 0; ko < 32; ko += 16) {
                unsigned a[2][4], bfr[4][2];
                #pragma unroll
                for (int i = 0; i < 2; i++) {
                    int r = wm * 32 + i * 16;
                    a[i][0] = *(const unsigned*)&As[buf][r + g][ko + 2 * t];
                    a[i][1] = *(const unsigned*)&As[buf][r + g + 8][ko + 2 * t];
                    a[i][2] = *(const unsigned*)&As[buf][r + g][ko + 2 * t + 8];
                    a[i][3] = *(const unsigned*)&As[buf][r + g + 8][ko + 2 * t + 8];
                }
                #pragma unroll
                for (int j = 0; j < 4; j++) {
                    int bn = wn * 32 + j * 8 + g;
                    bfr[j][0] = *(const unsigned*)&Bs[buf][bn][ko + 2 * t];
                    bfr[j][1] = *(const unsigned*)&Bs[buf][bn][ko + 2 * t + 8];
                }
                #pragma unroll
                for (int i = 0; i < 2; i++)
                    #pragma unroll
                    for (int j = 0; j < 4; j++)
                        mma16816(acc[i][j], a[i], bfr[j][0], bfr[j][1]);
            }
            __syncthreads();
        }
    }

    #pragma unroll
    for (int i = 0; i < 2; i++) {
        int r = m0 + wm * 32 + i * 16 + g;
        #pragma unroll
        for (int j = 0; j < 4; j++) {
            int c = n0 + wn * 32 + j * 8 + 2 * t;
            float b0 = bias[c], b1 = bias[c + 1];
            splitw(outP, (size_t)r * 256, 128, c,     acc[i][j][0] + b0);
            splitw(outP, (size_t)r * 256, 128, c + 1, acc[i][j][1] + b1);
            splitw(outP, (size_t)(r + 8) * 256, 128, c,     acc[i][j][2] + b0);
            splitw(outP, (size_t)(r + 8) * 256, 128, c + 1, acc[i][j][3] + b1);
        }
    }
}

// ---------------- tensor-core LSTM v3 (R5 proven version) ----------------
__global__ void __launch_bounds__(256)
k_lstm_mma(const float* __restrict__ gx, const __nv_bfloat16* __restrict__ Up,
           __nv_bfloat16* __restrict__ hsplit, float* __restrict__ hmean) {
    extern __shared__ __nv_bfloat16 sm[];
    __nv_bfloat16* Uh  = sm;
    __nv_bfloat16* Ulw = sm + SM_UH;
    __nv_bfloat16* Hsp = sm + SM_UH + SM_UL;

    int tid = threadIdx.x, lane = tid & 31, w = tid >> 5;
    int g = lane >> 2, tq = lane & 3;
    int b0 = blockIdx.x * 16;
    int wbase = w * 64;
    __nv_bfloat16* myUl = Ulw + w * SM_ULW;

    for (int idx = tid; idx < 512 * 16; idx += 256) {
        int n = idx >> 4, j = idx & 15;
        *(uint4*)(Uh + n * UH_STRIDE + j * 8) = *(const uint4*)(Up + (size_t)n * 256 + j * 8);
    }
    for (int idx = tid; idx < SM_H; idx += 256) Hsp[idx] = __float2bfloat16(0.f);

    float cst[8], hsum[8];
    #pragma unroll
    for (int i = 0; i < 8; i++) { cst[i] = 0.f; hsum[i] = 0.f; }

    for (int t = 0; t < TSTEPS; t++) {
        float acc[8][4];
        {
            size_t rlo = ((size_t)(b0 + g) * TSTEPS + t) * G4 + wbase + 2 * tq;
            size_t rhi = ((size_t)(b0 + g + 8) * TSTEPS + t) * G4 + wbase + 2 * tq;
            #pragma unroll
            for (int a = 0; a < 8; a++) {
                float2 v0 = *(const float2*)&gx[rlo + a * 8];
                float2 v1 = *(const float2*)&gx[rhi + a * 8];
                acc[a][0] = v0.x; acc[a][1] = v0.y;
                acc[a][2] = v1.x; acc[a][3] = v1.y;
            }
        }
        __syncthreads();

        #pragma unroll
        for (int c0 = 0; c0 < 2; c0++) {
            __nv_bfloat16* buf = myUl + (c0 % 3) * 64 * ULW_STRIDE;
            #pragma unroll
            for (int i = 0; i < 4; i++) {
                int u = lane + 32 * i, n1 = u >> 1, hf = u & 1;
                cpa16(smaddr(buf + n1 * ULW_STRIDE + hf * 8),
                      Up + (size_t)(wbase + n1) * 256 + 128 + c0 * 16 + hf * 8);
            }
            cpa_commit();
        }

        #pragma unroll 1
        for (int c = 0; c < 8; c++) {
            if (c < 7) asm volatile("cp.async.wait_group 1;");
            else       asm volatile("cp.async.wait_group 0;");
            __syncwarp();
            if (c + 2 < 8) {
                __nv_bfloat16* nbuf = myUl + ((c + 2) % 3) * 64 * ULW_STRIDE;
                #pragma unroll
                for (int i = 0; i < 4; i++) {
                    int u = lane + 32 * i, n1 = u >> 1, hf = u & 1;
                    cpa16(smaddr(nbuf + n1 * ULW_STRIDE + hf * 8),
                          Up + (size_t)(wbase + n1) * 256 + 128 + (c + 2) * 16 + hf * 8);
                }
                cpa_commit();
            }
            int ko = c * 16 + 2 * tq;
            unsigned ah[4], al[4];
            ah[0] = *(const unsigned*)&Hsp[g * H_STRIDE + ko];
            ah[1] = *(const unsigned*)&Hsp[(g + 8) * H_STRIDE + ko];
            ah[2] = *(const unsigned*)&Hsp[g * H_STRIDE + ko + 8];
            ah[3] = *(const unsigned*)&Hsp[(g + 8) * H_STRIDE + ko + 8];
            al[0] = *(const unsigned*)&Hsp[g * H_STRIDE + 128 + ko];
            al[1] = *(const unsigned*)&Hsp[(g + 8) * H_STRIDE + 128 + ko];
            al[2] = *(const unsigned*)&Hsp[g * H_STRIDE + 128 + ko + 8];
            al[3] = *(const unsigned*)&Hsp[(g + 8) * H_STRIDE + 128 + ko + 8];
            const __nv_bfloat16* ulB = myUl + (c % 3) * 64 * ULW_STRIDE;
            #pragma unroll
            for (int bn = 0; bn < 8; bn++) {
                int n = wbase + bn * 8 + g;
                const __nv_bfloat16* bph = Uh + n * UH_STRIDE + ko;
                unsigned h0 = *(const unsigned*)bph;
                unsigned h1 = *(const unsigned*)(bph + 8);
                mma16816(acc[bn], ah, h0, h1);
                mma16816(acc[bn], al, h0, h1);
                const __nv_bfloat16* bpl = ulB + (bn * 8 + g) * ULW_STRIDE + 2 * tq;
                unsigned l0 = *(const unsigned*)bpl;
                unsigned l1 = *(const unsigned*)(bpl + 8);
                mma16816(acc[bn], ah, l0, l1);
            }
        }
        __syncthreads();

        #pragma unroll
        for (int uh = 0; uh < 2; uh++)
            #pragma unroll
            for (int par = 0; par < 2; par++)
                #pragma unroll
                for (int q2 = 0; q2 < 2; q2++) {
                    int u = uh * 8 + 2 * tq + par;
                    int r = g + 8 * q2;
                    int qq = q2 * 2 + par;
                    int ci = uh * 4 + par * 2 + q2;
                    float gi = acc[0 + uh][qq];
                    float gf = acc[2 + uh][qq];
                    float gg = acc[4 + uh][qq];
                    float go = acc[6 + uh][qq];
                    float c = sigf(gf) * cst[ci] + sigf(gi) * tanhf_acc(gg);
                    float h = sigf(go) * tanhf_acc(c);
                    cst[ci] = c;
                    int ug = w * 16 + u;
                    __nv_bfloat16 hh = __float2bfloat16(h);
                    __nv_bfloat16 hl = __float2bfloat16(h - __bfloat162float(hh));
                    Hsp[r * H_STRIDE + ug] = hh;
                    Hsp[r * H_STRIDE + 128 + ug] = hl;
                    if (hsplit) {
                        size_t row2 = ((size_t)(b0 + r) * TSTEPS + t) * 256;
                        hsplit[row2 + ug] = hh;
                        hsplit[row2 + 128 + ug] = hl;
                    }
                    hsum[ci] += h;
                }
    }

    if (hmean) {
        #pragma unroll
        for (int uh = 0; uh < 2; uh++)
            #pragma unroll
            for (int par = 0; par < 2; par++)
                #pragma unroll
                for (int q2 = 0; q2 < 2; q2++) {
                    int u = uh * 8 + 2 * tq + par;
                    int r = g + 8 * q2;
                    int ci = uh * 4 + par * 2 + q2;
                    hmean[(size_t)(b0 + r) * 128 + w * 16 + u] = hsum[ci] * (1.0f / (float)TSTEPS);
                }
    }
}

// ---------------- small fp32 SGEMM for fc/proj ----------------
__global__ void k_sgemm(const float* __restrict__ A, const float* __restrict__ Bm,
                        float* __restrict__ C, const float* __restrict__ bias,
                        int M, int N, int K) {
    __shared__ float As[8][68];
    __shared__ float Bs[8][64];
    int tid = threadIdx.x;
    int m0 = blockIdx.y * 64, n0 = blockIdx.x * 64;
    int tm = tid & 15, tn = tid >> 4;
    float acc[4][8];
    #pragma unroll
    for (int i = 0; i < 4; i++)
        #pragma unroll
        for (int j = 0; j < 8; j++) acc[i][j] = 0.f;
    for (int kk = 0; kk < K; kk += 8) {
        #pragma unroll
        for (int i = 0; i < 4; i++) {
            int l = tid + i * 128, m = l >> 3, k = l & 7;
            int gm = m0 + m, gk = kk + k;
            As[k][m] = (gm < M && gk < K) ? A[(size_t)gm * K + gk] : 0.f;
        }
        #pragma unroll
        for (int i = 0; i < 4; i++) {
            int l = tid + i * 128, k = l >> 6, n = l & 63;
            int gk = kk + k, gn = n0 + n;
            Bs[k][n] = (gk < K && gn < N) ? Bm[(size_t)gk * N + gn] : 0.f;
        }
        __syncthreads();
        #pragma unroll
        for (int k = 0; k < 8; k++) {
            float a[4], bv[8];
            #pragma unroll
            for (int i = 0; i < 4; i++) a[i] = As[k][tm * 4 + i];
            #pragma unroll
            for (int j = 0; j < 8; j++) bv[j] = Bs[k][tn * 8 + j];
            #pragma unroll
            for (int i = 0; i < 4; i++)
                #pragma unroll
                for (int j = 0; j < 8; j++) acc[i][j] += a[i] * bv[j];
        }
        __syncthreads();
    }
    #pragma unroll
    for (int i = 0; i < 4; i++) {
        int gm = m0 + tm * 4 + i;
        if (gm >= M) continue;
        #pragma unroll
        for (int j = 0; j < 8; j++) {
            int gn = n0 + tn * 8 + j;
            if (gn < N) C[(size_t)gm * N + gn] = acc[i][j] + (bias ? bias[gn] : 0.f);
        }
    }
}

// ---------------- launch ----------------
extern "C" void kernel_launch(void* const* d_in, const int* in_sizes, int n_in,
                              void* d_out, int out_size) {
    const float* x      = (const float*)d_in[0];
    const float* conv_w = (const float*)d_in[1];
    const float* conv_b = (const float*)d_in[2];
    const float* W1     = (const float*)d_in[3];
    const float* U1     = (const float*)d_in[4];
    const float* b1     = (const float*)d_in[5];
    const float* W2     = (const float*)d_in[6];
    const float* U2     = (const float*)d_in[7];
    const float* b2     = (const float*)d_in[8];
    const float* fc1_w  = (const float*)d_in[9];
    const float* fc1_b  = (const float*)d_in[10];
    const float* proj_w = (const float*)d_in[11];
    const float* proj_b = (const float*)d_in[12];
    float* out = (float*)d_out;

    __nv_bfloat16 *pA2dft, *pB2dft, *pA2mel, *pB2mel, *pMelsp, *pB2conv, *pA2g;
    __nv_bfloat16 *pB2W1p, *pB2W2p, *pU1p, *pU2p, *pH1s;
    float *pG, *pHmean, *pHfc, *pB1p, *pB2p;
    cudaGetSymbolAddress((void**)&pA2dft,  d_A2dft);
    cudaGetSymbolAddress((void**)&pB2dft,  d_B2dft);
    cudaGetSymbolAddress((void**)&pA2mel,  d_A2mel);
    cudaGetSymbolAddress((void**)&pB2mel,  d_B2mel);
    cudaGetSymbolAddress((void**)&pMelsp,  d_melsp);
    cudaGetSymbolAddress((void**)&pB2conv, d_B2conv);
    cudaGetSymbolAddress((void**)&pA2g,    d_A2g);
    cudaGetSymbolAddress((void**)&pB2W1p,  d_B2W1p);
    cudaGetSymbolAddress((void**)&pB2W2p,  d_B2W2p);
    cudaGetSymbolAddress((void**)&pU1p,    d_U1p);
    cudaGetSymbolAddress((void**)&pU2p,    d_U2p);
    cudaGetSymbolAddress((void**)&pH1s,    d_h1s);
    cudaGetSymbolAddress((void**)&pG,      d_g);
    cudaGetSymbolAddress((void**)&pHmean,  d_hmean);
    cudaGetSymbolAddress((void**)&pHfc,    d_hfc);
    cudaGetSymbolAddress((void**)&pB1p,    d_b1p);
    cudaGetSymbolAddress((void**)&pB2p,    d_b2p);

    cudaFuncSetAttribute(k_lstm_mma,  cudaFuncAttributeMaxDynamicSharedMemorySize, LSTM_SMEM_BYTES);
    cudaFuncSetAttribute(k_gemm_dft,  cudaFuncAttributeMaxDynamicSharedMemorySize, DFT_SMEM_BYTES);

    k_precompute<<<128, 256>>>(conv_w, W1, W2, U1, U2, b1, b2);
    k_window<<<dim3(NFRAMES, BATCH), 256>>>(x);

    // DFT -> power split-pack into A2mel (A-resident: A streamed from DRAM once)
    k_gemm_dft<<<R1 / 64, 256, DFT_SMEM_BYTES>>>(pA2dft, pB2dft, pA2mel);
    // mel -> split pack
    k_gemm<<<dim3(2, R1 / 128), 256>>>(pA2mel, pB2mel, KP_MEL, nullptr, 2,
                                       nullptr, 0, NMELS, pMelsp, 128);
    // conv (shifted-row) -> split pack into A2g
    k_gemm_conv<<<dim3(2, R2 / 128), 256>>>(pMelsp, pB2conv, conv_b, pA2g);
    // g1 (permuted gates)
    k_gemm<<<dim3(8, R2 / 128), 256>>>(pA2g, pB2W1p, KP_G, pB1p, 0,
                                       pG, G4, G4, nullptr, 0);
    k_lstm_mma<<<BATCH / 16, 256, LSTM_SMEM_BYTES>>>(pG, pU1p, pH1s, nullptr);
    // g2 (permuted gates)
    k_gemm<<<dim3(8, R2 / 128), 256>>>(pH1s, pB2W2p, KP_G, pB2p, 0,
                                       pG, G4, G4, nullptr, 0);
    k_lstm_mma<<<BATCH / 16, 256, LSTM_SMEM_BYTES>>>(pG, pU2p, nullptr, pHmean);

    k_sgemm<<<dim3(2, BATCH / 64), 128>>>(pHmean, fc1_w, pHfc, fc1_b, BATCH, 128, 128);
    k_sgemm<<<dim3(1, BATCH / 64), 128>>>(pHfc, proj_w, out, proj_b, BATCH, 35, 128);
}

// round 9
// speedup vs baseline: 1.4815x; 1.0776x over previous
#include <cuda_runtime.h>
#include <cuda_bf16.h>
#include <math.h>

// ---------------- problem dims ----------------
#define BATCH   1024
#define TLEN    16000
#define NFFT    400
#define HOP     200
#define NBINS   201
#define NMELS   128
#define NFRAMES 81
#define TSTEPS  79
#define HID     128
#define G4      512
#define R1      (BATCH*NFRAMES)   // 82944
#define R2      (BATCH*TSTEPS)    // 80896

#define KP_DFT  416
#define KP_MEL  224
#define KP_G    128
#define NP_DFT  448
#define KCONV   384

// k_gemm dynamic smem layout (bf16 elems): Ah[2][128][40] Al[2][128][40] Bh[2][64][40] Bl[2][64][40]
#define GEMM_SMEM_ELEMS (2*128*40*2 + 2*64*40*2)   // 30720
#define GEMM_SMEM_BYTES (GEMM_SMEM_ELEMS*2)        // 61440
#define OFF_AL  10240
#define OFF_BH  20480
#define OFF_BL  25600

// LSTM smem (bf16 elements)
#define UH_STRIDE 136
#define ULW_STRIDE 24
#define H_STRIDE  264
#define SM_UH   (512*UH_STRIDE)
#define SM_ULW  (3*64*ULW_STRIDE)
#define SM_UL   (8*SM_ULW)
#define SM_H    (16*H_STRIDE)
#define LSTM_SMEM_BYTES ((SM_UH + SM_UL + SM_H)*2)  // 221440

// ---------------- scratch ----------------
__device__ float          d_hann[NFFT];
__device__ __nv_bfloat16  d_A2dft[(size_t)R1 * 2 * KP_DFT];
__device__ __nv_bfloat16  d_B2dft[(size_t)NP_DFT * 2 * KP_DFT];
__device__ __nv_bfloat16  d_A2mel[(size_t)R1 * 2 * KP_MEL];
__device__ __nv_bfloat16  d_B2mel[(size_t)128 * 2 * KP_MEL];
__device__ __nv_bfloat16  d_melsp[(size_t)R1 * 256];
__device__ __nv_bfloat16  d_B2conv[(size_t)128 * 2 * KCONV];
__device__ __nv_bfloat16  d_A2g[(size_t)R2 * 2 * KP_G];
__device__ __nv_bfloat16  d_B2W1p[(size_t)G4 * 2 * KP_G];
__device__ __nv_bfloat16  d_B2W2p[(size_t)G4 * 2 * KP_G];
__device__ __nv_bfloat16  d_U1p[(size_t)G4 * 2 * KP_G];
__device__ __nv_bfloat16  d_U2p[(size_t)G4 * 2 * KP_G];
__device__ float          d_b1p[G4];
__device__ float          d_b2p[G4];
__device__ float          d_g[(size_t)R2 * G4];
__device__ __nv_bfloat16  d_h1s[(size_t)R2 * 2 * KP_G];
__device__ float          d_hmean[BATCH * 128];
__device__ float          d_hfc[BATCH * 128];

// ---------------- helpers ----------------
__device__ __forceinline__ float sigf(float x) { return 1.0f / (1.0f + __expf(-x)); }
__device__ __forceinline__ float tanhf_acc(float x) {
    float t = __expf(-2.0f * fabsf(x));
    float r = (1.0f - t) / (1.0f + t);
    return copysignf(r, x);
}
__device__ __forceinline__ void splitw(__nv_bfloat16* P, size_t base, int KpOut, int k, float v) {
    __nv_bfloat16 h = __float2bfloat16(v);
    P[base + k] = h;
    P[base + KpOut + k] = __float2bfloat16(v - __bfloat162float(h));
}
__device__ __forceinline__ unsigned smaddr(const void* p) {
    return (unsigned)__cvta_generic_to_shared(p);
}
__device__ __forceinline__ void cpa16(unsigned dst, const void* src) {
    asm volatile("cp.async.cg.shared.global [%0], [%1], 16;" :: "r"(dst), "l"(src));
}
__device__ __forceinline__ void cpa_commit() { asm volatile("cp.async.commit_group;"); }
__device__ __forceinline__ void mma16816(float* c, const unsigned* a, unsigned b0, unsigned b1) {
    asm volatile(
        "mma.sync.aligned.m16n8k16.row.col.f32.bf16.bf16.f32 "
        "{%0,%1,%2,%3}, {%4,%5,%6,%7}, {%8,%9}, {%0,%1,%2,%3};"
        : "+f"(c[0]), "+f"(c[1]), "+f"(c[2]), "+f"(c[3])
        : "r"(a[0]), "r"(a[1]), "r"(a[2]), "r"(a[3]), "r"(b0), "r"(b1));
}
__device__ __forceinline__ int gperm(int n) {
    int w = n >> 6, s = n & 63, gate = s >> 4, u = s & 15;
    return gate * 128 + w * 16 + u;
}

// ---------------- precompute ----------------
__global__ void k_precompute(const float* __restrict__ conv_w,
                             const float* __restrict__ W1, const float* __restrict__ W2,
                             const float* __restrict__ U1, const float* __restrict__ U2,
                             const float* __restrict__ b1, const float* __restrict__ b2) {
    int tid = blockIdx.x * blockDim.x + threadIdx.x;
    int nth = gridDim.x * blockDim.x;

    for (int k = tid; k < NFFT; k += nth)
        d_hann[k] = (float)(0.5 - 0.5 * cospi((double)k / 200.0));

    for (int idx = tid; idx < NP_DFT * KP_DFT; idx += nth) {
        int n = idx / KP_DFT, k = idx % KP_DFT;
        float v = 0.f;
        if (n < 2 * NBINS && k < NFFT) {
            int m = n >> 1;
            int ph = (m * k) % 400;
            double s, c;
            sincospi((double)ph / 200.0, &s, &c);
            v = (float)((n & 1) ? s : c);
        }
        splitw(d_B2dft, (size_t)n * (2 * KP_DFT), KP_DFT, k, v);
    }

    const double mel_max = 2595.0 * log10(1.0 + 8000.0 / 700.0);
    for (int idx = tid; idx < 128 * KP_MEL; idx += nth) {
        int m = idx / KP_MEL, k = idx % KP_MEL;
        float v = 0.f;
        if (k < NBINS) {
            double freq = 40.0 * (double)k;
            double f0 = 700.0 * (pow(10.0, (mel_max * (double)(m    ) / 129.0) / 2595.0) - 1.0);
            double f1 = 700.0 * (pow(10.0, (mel_max * (double)(m + 1) / 129.0) / 2595.0) - 1.0);
            double f2 = 700.0 * (pow(10.0, (mel_max * (double)(m + 2) / 129.0) / 2595.0) - 1.0);
            double dn = (freq - f0) / (f1 - f0);
            double up = (f2 - freq) / (f2 - f1);
            double t = dn < up ? dn : up;
            if (t < 0.0) t = 0.0;
            v = (float)t;
        }
        splitw(d_B2mel, (size_t)m * (2 * KP_MEL), KP_MEL, k, v);
    }

    for (int idx = tid; idx < 128 * KCONV; idx += nth) {
        int o = idx / KCONV, q = idx % KCONV;
        int kk = q >> 7, i = q & 127;
        splitw(d_B2conv, (size_t)o * (2 * KCONV), KCONV, q, conv_w[o * 384 + i * 3 + kk]);
    }

    for (int idx = tid; idx < G4 * KP_G; idx += nth) {
        int n = idx / KP_G, k = idx % KP_G;
        int no = gperm(n);
        splitw(d_B2W1p, (size_t)n * (2 * KP_G), KP_G, k, W1[k * G4 + no]);
        splitw(d_B2W2p, (size_t)n * (2 * KP_G), KP_G, k, W2[k * G4 + no]);
        splitw(d_U1p,   (size_t)n * (2 * KP_G), KP_G, k, U1[k * G4 + no]);
        splitw(d_U2p,   (size_t)n * (2 * KP_G), KP_G, k, U2[k * G4 + no]);
    }
    for (int n = tid; n < G4; n += nth) {
        int no = gperm(n);
        d_b1p[n] = b1[no];
        d_b2p[n] = b2[no];
    }

    for (int idx = tid; idx < R1 * (KP_MEL - NBINS); idx += nth) {
        int r = idx / (KP_MEL - NBINS), k = NBINS + idx % (KP_MEL - NBINS);
        d_A2mel[(size_t)r * (2 * KP_MEL) + k] = __float2bfloat16(0.f);
        d_A2mel[(size_t)r * (2 * KP_MEL) + KP_MEL + k] = __float2bfloat16(0.f);
    }
}

// ---------------- window ----------------
__global__ void k_window(const float* __restrict__ x) {
    int f = blockIdx.x, b = blockIdx.y, tid = threadIdx.x;
    size_t row = (size_t)(b * NFRAMES + f) * (2 * KP_DFT);
    for (int k = tid; k < KP_DFT; k += blockDim.x) {
        float v = 0.f;
        if (k < NFFT) {
            int p = f * HOP + k - 200;
            int i = (p < 0) ? -p : ((p >= TLEN) ? (2 * TLEN - 2 - p) : p);
            v = x[(size_t)b * TLEN + i] * d_hann[k];
        }
        __nv_bfloat16 h = __float2bfloat16(v);
        d_A2dft[row + k] = h;
        d_A2dft[row + KP_DFT + k] = __float2bfloat16(v - __bfloat162float(h));
    }
}

// ---------------- single-pass split-bf16 tensor GEMM (R5 inner loop, dynamic smem, 3 blocks/SM) ----------------
// mode 0: fp32 out (+bias); mode 1: power -> split pack; mode 2: split pack (+bias)
__global__ void __launch_bounds__(256, 3)
k_gemm(const __nv_bfloat16* __restrict__ A2, const __nv_bfloat16* __restrict__ B2,
       int Kp, const float* __restrict__ bias, int mode,
       float* __restrict__ outF, int ldc, int Nreal,
       __nv_bfloat16* __restrict__ outP, int KpOut) {
    extern __shared__ __nv_bfloat16 smd[];
    __nv_bfloat16* AHs = smd;              // [2][128][40]
    __nv_bfloat16* ALs = smd + OFF_AL;     // [2][128][40]
    __nv_bfloat16* BHs = smd + OFF_BH;     // [2][64][40]
    __nv_bfloat16* BLs = smd + OFF_BL;     // [2][64][40]

    int tid = threadIdx.x, lane = tid & 31, w = tid >> 5;
    int wm = w >> 1, wn = w & 1;
    int m0 = blockIdx.y * 128, n0 = blockIdx.x * 64;
    int g = lane >> 2, t = lane & 3;
    int strideA = 2 * Kp;
    int la_row = tid >> 2, la_kc = (tid & 3) << 3;

    const __nv_bfloat16* Abase = A2 + (size_t)m0 * strideA;
    const __nv_bfloat16* Bbase = B2 + (size_t)n0 * strideA;

    float acc[2][4][4];
    #pragma unroll
    for (int i = 0; i < 2; i++)
        #pragma unroll
        for (int j = 0; j < 4; j++)
            #pragma unroll
            for (int q = 0; q < 4; q++) acc[i][j][q] = 0.f;

    auto load_chunk = [&](int buf, int kk) {
        int bo = buf * 5120, bo2 = buf * 2560;
        cpa16(smaddr(AHs + bo + la_row * 40 + la_kc),        Abase + (size_t)la_row * strideA + kk + la_kc);
        cpa16(smaddr(AHs + bo + (la_row + 64) * 40 + la_kc), Abase + (size_t)(la_row + 64) * strideA + kk + la_kc);
        cpa16(smaddr(ALs + bo + la_row * 40 + la_kc),        Abase + (size_t)la_row * strideA + Kp + kk + la_kc);
        cpa16(smaddr(ALs + bo + (la_row + 64) * 40 + la_kc), Abase + (size_t)(la_row + 64) * strideA + Kp + kk + la_kc);
        cpa16(smaddr(BHs + bo2 + la_row * 40 + la_kc),       Bbase + (size_t)la_row * strideA + kk + la_kc);
        cpa16(smaddr(BLs + bo2 + la_row * 40 + la_kc),       Bbase + (size_t)la_row * strideA + Kp + kk + la_kc);
        cpa_commit();
    };

    load_chunk(0, 0);

    #pragma unroll 1
    for (int kk = 0; kk < Kp; kk += 32) {
        int buf = (kk >> 5) & 1;
        asm volatile("cp.async.wait_group 0;");
        __syncthreads();
        if (kk + 32 < Kp) load_chunk(buf ^ 1, kk + 32);

        int bo = buf * 5120, bo2 = buf * 2560;
        #pragma unroll
        for (int ko = 0; ko < 32; ko += 16) {
            unsigned ahf[2][4], alf[2][4], bhf[4][2], blf[4][2];
            #pragma unroll
            for (int i = 0; i < 2; i++) {
                int r = wm * 32 + i * 16;
                ahf[i][0] = *(const unsigned*)&AHs[bo + (r + g) * 40 + ko + 2 * t];
                ahf[i][1] = *(const unsigned*)&AHs[bo + (r + g + 8) * 40 + ko + 2 * t];
                ahf[i][2] = *(const unsigned*)&AHs[bo + (r + g) * 40 + ko + 2 * t + 8];
                ahf[i][3] = *(const unsigned*)&AHs[bo + (r + g + 8) * 40 + ko + 2 * t + 8];
                alf[i][0] = *(const unsigned*)&ALs[bo + (r + g) * 40 + ko + 2 * t];
                alf[i][1] = *(const unsigned*)&ALs[bo + (r + g + 8) * 40 + ko + 2 * t];
                alf[i][2] = *(const unsigned*)&ALs[bo + (r + g) * 40 + ko + 2 * t + 8];
                alf[i][3] = *(const unsigned*)&ALs[bo + (r + g + 8) * 40 + ko + 2 * t + 8];
            }
            #pragma unroll
            for (int j = 0; j < 4; j++) {
                int bn = wn * 32 + j * 8 + g;
                bhf[j][0] = *(const unsigned*)&BHs[bo2 + bn * 40 + ko + 2 * t];
                bhf[j][1] = *(const unsigned*)&BHs[bo2 + bn * 40 + ko + 2 * t + 8];
                blf[j][0] = *(const unsigned*)&BLs[bo2 + bn * 40 + ko + 2 * t];
                blf[j][1] = *(const unsigned*)&BLs[bo2 + bn * 40 + ko + 2 * t + 8];
            }
            #pragma unroll
            for (int i = 0; i < 2; i++)
                #pragma unroll
                for (int j = 0; j < 4; j++) {
                    mma16816(acc[i][j], ahf[i], bhf[j][0], bhf[j][1]);
                    mma16816(acc[i][j], ahf[i], blf[j][0], blf[j][1]);
                    mma16816(acc[i][j], alf[i], bhf[j][0], bhf[j][1]);
                }
        }
        __syncthreads();
    }

    #pragma unroll
    for (int i = 0; i < 2; i++) {
        int r = m0 + wm * 32 + i * 16 + g;
        #pragma unroll
        for (int j = 0; j < 4; j++) {
            int c = n0 + wn * 32 + j * 8 + 2 * t;
            float v00 = acc[i][j][0], v01 = acc[i][j][1];
            float v10 = acc[i][j][2], v11 = acc[i][j][3];
            if (mode == 0) {
                float b0 = bias ? bias[c] : 0.f, b1 = bias ? bias[c + 1] : 0.f;
                outF[(size_t)r * ldc + c]           = v00 + b0;
                outF[(size_t)r * ldc + c + 1]       = v01 + b1;
                outF[(size_t)(r + 8) * ldc + c]     = v10 + b0;
                outF[(size_t)(r + 8) * ldc + c + 1] = v11 + b1;
            } else if (mode == 1) {
                int k = c >> 1;
                if (k < Nreal) {
                    splitw(outP, (size_t)r * (2 * KpOut), KpOut, k, v00 * v00 + v01 * v01);
                    splitw(outP, (size_t)(r + 8) * (2 * KpOut), KpOut, k, v10 * v10 + v11 * v11);
                }
            } else {
                float b0 = bias ? bias[c] : 0.f, b1 = bias ? bias[c + 1] : 0.f;
                splitw(outP, (size_t)r * (2 * KpOut), KpOut, c, v00 + b0);
                splitw(outP, (size_t)r * (2 * KpOut), KpOut, c + 1, v01 + b1);
                splitw(outP, (size_t)(r + 8) * (2 * KpOut), KpOut, c, v10 + b0);
                splitw(outP, (size_t)(r + 8) * (2 * KpOut), KpOut, c + 1, v11 + b1);
            }
        }
    }
}

// ---------------- conv GEMM (R5 proven): shifted rows, 9 segments ----------------
__global__ void __launch_bounds__(256, 3)
k_gemm_conv(const __nv_bfloat16* __restrict__ Msp, const __nv_bfloat16* __restrict__ B2,
            const float* __restrict__ bias, __nv_bfloat16* __restrict__ outP) {
    __shared__ __nv_bfloat16 As[2][128][40];
    __shared__ __nv_bfloat16 Bs[2][64][40];
    int tid = threadIdx.x, lane = tid & 31, w = tid >> 5;
    int wm = w >> 1, wn = w & 1;
    int m0 = blockIdx.y * 128, n0 = blockIdx.x * 64;
    int g = lane >> 2, t = lane & 3;
    int la_row = tid >> 2, la_kc = (tid & 3) << 3;

    int gm0 = m0 + la_row, gm1 = m0 + la_row + 64;
    int sr0 = gm0 + 2 * (gm0 / TSTEPS);
    int sr1 = gm1 + 2 * (gm1 / TSTEPS);

    float acc[2][4][4];
    #pragma unroll
    for (int i = 0; i < 2; i++)
        #pragma unroll
        for (int j = 0; j < 4; j++)
            #pragma unroll
            for (int q = 0; q < 4; q++) acc[i][j][q] = 0.f;

    #pragma unroll 1
    for (int s = 0; s < 9; s++) {
        int split = s / 3, shift = s % 3;
        int aoff = (split == 2) ? 128 : 0;
        int boff = ((split == 1) ? KCONV : 0) + shift * 128;
        const __nv_bfloat16* A0 = Msp + (size_t)(sr0 + shift) * 256 + aoff;
        const __nv_bfloat16* A1 = Msp + (size_t)(sr1 + shift) * 256 + aoff;
        const __nv_bfloat16* Bb = B2 + (size_t)n0 * (2 * KCONV) + boff;

        cpa16(smaddr(&As[0][la_row][la_kc]),      A0 + la_kc);
        cpa16(smaddr(&As[0][la_row + 64][la_kc]), A1 + la_kc);
        cpa16(smaddr(&Bs[0][la_row][la_kc]),      Bb + (size_t)la_row * (2 * KCONV) + la_kc);
        cpa_commit();
        #pragma unroll 1
        for (int kk = 0; kk < 128; kk += 32) {
            int buf = (kk >> 5) & 1;
            asm volatile("cp.async.wait_group 0;");
            __syncthreads();
            if (kk + 32 < 128) {
                int nb = buf ^ 1, kn = kk + 32;
                cpa16(smaddr(&As[nb][la_row][la_kc]),      A0 + kn + la_kc);
                cpa16(smaddr(&As[nb][la_row + 64][la_kc]), A1 + kn + la_kc);
                cpa16(smaddr(&Bs[nb][la_row][la_kc]),      Bb + (size_t)la_row * (2 * KCONV) + kn + la_kc);
                cpa_commit();
            }
            #pragma unroll
            for (int ko = 0; ko < 32; ko += 16) {
                unsigned a[2][4], bfr[4][2];
                #pragma unroll
                for (int i = 0; i < 2; i++) {
                    int r = wm * 32 + i * 16;
                    a[i][0] = *(const unsigned*)&As[buf][r + g][ko + 2 * t];
                    a[i][1] = *(const unsigned*)&As[buf][r + g + 8][ko + 2 * t];
                    a[i][2] = *(const unsigned*)&As[buf][r + g][ko + 2 * t + 8];
                    a[i][3] = *(const unsigned*)&As[buf][r + g + 8][ko + 2 * t + 8];
                }
                #pragma unroll
                for (int j = 0; j < 4; j++) {
                    int bn = wn * 32 + j * 8 + g;
                    bfr[j][0] = *(const unsigned*)&Bs[buf][bn][ko + 2 * t];
                    bfr[j][1] = *(const unsigned*)&Bs[buf][bn][ko + 2 * t + 8];
                }
                #pragma unroll
                for (int i = 0; i < 2; i++)
                    #pragma unroll
                    for (int j = 0; j < 4; j++)
                        mma16816(acc[i][j], a[i], bfr[j][0], bfr[j][1]);
            }
            __syncthreads();
        }
    }

    #pragma unroll
    for (int i = 0; i < 2; i++) {
        int r = m0 + wm * 32 + i * 16 + g;
        #pragma unroll
        for (int j = 0; j < 4; j++) {
            int c = n0 + wn * 32 + j * 8 + 2 * t;
            float b0 = bias[c], b1 = bias[c + 1];
            splitw(outP, (size_t)r * 256, 128, c,     acc[i][j][0] + b0);
            splitw(outP, (size_t)r * 256, 128, c + 1, acc[i][j][1] + b1);
            splitw(outP, (size_t)(r + 8) * 256, 128, c,     acc[i][j][2] + b0);
            splitw(outP, (size_t)(r + 8) * 256, 128, c + 1, acc[i][j][3] + b1);
        }
    }
}

// ---------------- tensor-core LSTM v3 (R5 proven version) ----------------
__global__ void __launch_bounds__(256)
k_lstm_mma(const float* __restrict__ gx, const __nv_bfloat16* __restrict__ Up,
           __nv_bfloat16* __restrict__ hsplit, float* __restrict__ hmean) {
    extern __shared__ __nv_bfloat16 sm[];
    __nv_bfloat16* Uh  = sm;
    __nv_bfloat16* Ulw = sm + SM_UH;
    __nv_bfloat16* Hsp = sm + SM_UH + SM_UL;

    int tid = threadIdx.x, lane = tid & 31, w = tid >> 5;
    int g = lane >> 2, tq = lane & 3;
    int b0 = blockIdx.x * 16;
    int wbase = w * 64;
    __nv_bfloat16* myUl = Ulw + w * SM_ULW;

    for (int idx = tid; idx < 512 * 16; idx += 256) {
        int n = idx >> 4, j = idx & 15;
        *(uint4*)(Uh + n * UH_STRIDE + j * 8) = *(const uint4*)(Up + (size_t)n * 256 + j * 8);
    }
    for (int idx = tid; idx < SM_H; idx += 256) Hsp[idx] = __float2bfloat16(0.f);

    float cst[8], hsum[8];
    #pragma unroll
    for (int i = 0; i < 8; i++) { cst[i] = 0.f; hsum[i] = 0.f; }

    for (int t = 0; t < TSTEPS; t++) {
        float acc[8][4];
        {
            size_t rlo = ((size_t)(b0 + g) * TSTEPS + t) * G4 + wbase + 2 * tq;
            size_t rhi = ((size_t)(b0 + g + 8) * TSTEPS + t) * G4 + wbase + 2 * tq;
            #pragma unroll
            for (int a = 0; a < 8; a++) {
                float2 v0 = *(const float2*)&gx[rlo + a * 8];
                float2 v1 = *(const float2*)&gx[rhi + a * 8];
                acc[a][0] = v0.x; acc[a][1] = v0.y;
                acc[a][2] = v1.x; acc[a][3] = v1.y;
            }
        }
        __syncthreads();

        #pragma unroll
        for (int c0 = 0; c0 < 2; c0++) {
            __nv_bfloat16* buf = myUl + (c0 % 3) * 64 * ULW_STRIDE;
            #pragma unroll
            for (int i = 0; i < 4; i++) {
                int u = lane + 32 * i, n1 = u >> 1, hf = u & 1;
                cpa16(smaddr(buf + n1 * ULW_STRIDE + hf * 8),
                      Up + (size_t)(wbase + n1) * 256 + 128 + c0 * 16 + hf * 8);
            }
            cpa_commit();
        }

        #pragma unroll 1
        for (int c = 0; c < 8; c++) {
            if (c < 7) asm volatile("cp.async.wait_group 1;");
            else       asm volatile("cp.async.wait_group 0;");
            __syncwarp();
            if (c + 2 < 8) {
                __nv_bfloat16* nbuf = myUl + ((c + 2) % 3) * 64 * ULW_STRIDE;
                #pragma unroll
                for (int i = 0; i < 4; i++) {
                    int u = lane + 32 * i, n1 = u >> 1, hf = u & 1;
                    cpa16(smaddr(nbuf + n1 * ULW_STRIDE + hf * 8),
                          Up + (size_t)(wbase + n1) * 256 + 128 + (c + 2) * 16 + hf * 8);
                }
                cpa_commit();
            }
            int ko = c * 16 + 2 * tq;
            unsigned ah[4], al[4];
            ah[0] = *(const unsigned*)&Hsp[g * H_STRIDE + ko];
            ah[1] = *(const unsigned*)&Hsp[(g + 8) * H_STRIDE + ko];
            ah[2] = *(const unsigned*)&Hsp[g * H_STRIDE + ko + 8];
            ah[3] = *(const unsigned*)&Hsp[(g + 8) * H_STRIDE + ko + 8];
            al[0] = *(const unsigned*)&Hsp[g * H_STRIDE + 128 + ko];
            al[1] = *(const unsigned*)&Hsp[(g + 8) * H_STRIDE + 128 + ko];
            al[2] = *(const unsigned*)&Hsp[g * H_STRIDE + 128 + ko + 8];
            al[3] = *(const unsigned*)&Hsp[(g + 8) * H_STRIDE + 128 + ko + 8];
            const __nv_bfloat16* ulB = myUl + (c % 3) * 64 * ULW_STRIDE;
            #pragma unroll
            for (int bn = 0; bn < 8; bn++) {
                int n = wbase + bn * 8 + g;
                const __nv_bfloat16* bph = Uh + n * UH_STRIDE + ko;
                unsigned h0 = *(const unsigned*)bph;
                unsigned h1 = *(const unsigned*)(bph + 8);
                mma16816(acc[bn], ah, h0, h1);
                mma16816(acc[bn], al, h0, h1);
                const __nv_bfloat16* bpl = ulB + (bn * 8 + g) * ULW_STRIDE + 2 * tq;
                unsigned l0 = *(const unsigned*)bpl;
                unsigned l1 = *(const unsigned*)(bpl + 8);
                mma16816(acc[bn], ah, l0, l1);
            }
        }
        __syncthreads();

        #pragma unroll
        for (int uh = 0; uh < 2; uh++)
            #pragma unroll
            for (int par = 0; par < 2; par++)
                #pragma unroll
                for (int q2 = 0; q2 < 2; q2++) {
                    int u = uh * 8 + 2 * tq + par;
                    int r = g + 8 * q2;
                    int qq = q2 * 2 + par;
                    int ci = uh * 4 + par * 2 + q2;
                    float gi = acc[0 + uh][qq];
                    float gf = acc[2 + uh][qq];
                    float gg = acc[4 + uh][qq];
                    float go = acc[6 + uh][qq];
                    float c = sigf(gf) * cst[ci] + sigf(gi) * tanhf_acc(gg);
                    float h = sigf(go) * tanhf_acc(c);
                    cst[ci] = c;
                    int ug = w * 16 + u;
                    __nv_bfloat16 hh = __float2bfloat16(h);
                    __nv_bfloat16 hl = __float2bfloat16(h - __bfloat162float(hh));
                    Hsp[r * H_STRIDE + ug] = hh;
                    Hsp[r * H_STRIDE + 128 + ug] = hl;
                    if (hsplit) {
                        size_t row2 = ((size_t)(b0 + r) * TSTEPS + t) * 256;
                        hsplit[row2 + ug] = hh;
                        hsplit[row2 + 128 + ug] = hl;
                    }
                    hsum[ci] += h;
                }
    }

    if (hmean) {
        #pragma unroll
        for (int uh = 0; uh < 2; uh++)
            #pragma unroll
            for (int par = 0; par < 2; par++)
                #pragma unroll
                for (int q2 = 0; q2 < 2; q2++) {
                    int u = uh * 8 + 2 * tq + par;
                    int r = g + 8 * q2;
                    int ci = uh * 4 + par * 2 + q2;
                    hmean[(size_t)(b0 + r) * 128 + w * 16 + u] = hsum[ci] * (1.0f / (float)TSTEPS);
                }
    }
}

// ---------------- small fp32 SGEMM for fc/proj ----------------
__global__ void k_sgemm(const float* __restrict__ A, const float* __restrict__ Bm,
                        float* __restrict__ C, const float* __restrict__ bias,
                        int M, int N, int K) {
    __shared__ float As[8][68];
    __shared__ float Bs[8][64];
    int tid = threadIdx.x;
    int m0 = blockIdx.y * 64, n0 = blockIdx.x * 64;
    int tm = tid & 15, tn = tid >> 4;
    float acc[4][8];
    #pragma unroll
    for (int i = 0; i < 4; i++)
        #pragma unroll
        for (int j = 0; j < 8; j++) acc[i][j] = 0.f;
    for (int kk = 0; kk < K; kk += 8) {
        #pragma unroll
        for (int i = 0; i < 4; i++) {
            int l = tid + i * 128, m = l >> 3, k = l & 7;
            int gm = m0 + m, gk = kk + k;
            As[k][m] = (gm < M && gk < K) ? A[(size_t)gm * K + gk] : 0.f;
        }
        #pragma unroll
        for (int i = 0; i < 4; i++) {
            int l = tid + i * 128, k = l >> 6, n = l & 63;
            int gk = kk + k, gn = n0 + n;
            Bs[k][n] = (gk < K && gn < N) ? Bm[(size_t)gk * N + gn] : 0.f;
        }
        __syncthreads();
        #pragma unroll
        for (int k = 0; k < 8; k++) {
            float a[4], bv[8];
            #pragma unroll
            for (int i = 0; i < 4; i++) a[i] = As[k][tm * 4 + i];
            #pragma unroll
            for (int j = 0; j < 8; j++) bv[j] = Bs[k][tn * 8 + j];
            #pragma unroll
            for (int i = 0; i < 4; i++)
                #pragma unroll
                for (int j = 0; j < 8; j++) acc[i][j] += a[i] * bv[j];
        }
        __syncthreads();
    }
    #pragma unroll
    for (int i = 0; i < 4; i++) {
        int gm = m0 + tm * 4 + i;
        if (gm >= M) continue;
        #pragma unroll
        for (int j = 0; j < 8; j++) {
            int gn = n0 + tn * 8 + j;
            if (gn < N) C[(size_t)gm * N + gn] = acc[i][j] + (bias ? bias[gn] : 0.f);
        }
    }
}

// ---------------- launch ----------------
extern "C" void kernel_launch(void* const* d_in, const int* in_sizes, int n_in,
                              void* d_out, int out_size) {
    const float* x      = (const float*)d_in[0];
    const float* conv_w = (const float*)d_in[1];
    const float* conv_b = (const float*)d_in[2];
    const float* W1     = (const float*)d_in[3];
    const float* U1     = (const float*)d_in[4];
    const float* b1     = (const float*)d_in[5];
    const float* W2     = (const float*)d_in[6];
    const float* U2     = (const float*)d_in[7];
    const float* b2     = (const float*)d_in[8];
    const float* fc1_w  = (const float*)d_in[9];
    const float* fc1_b  = (const float*)d_in[10];
    const float* proj_w = (const float*)d_in[11];
    const float* proj_b = (const float*)d_in[12];
    float* out = (float*)d_out;

    __nv_bfloat16 *pA2dft, *pB2dft, *pA2mel, *pB2mel, *pMelsp, *pB2conv, *pA2g;
    __nv_bfloat16 *pB2W1p, *pB2W2p, *pU1p, *pU2p, *pH1s;
    float *pG, *pHmean, *pHfc, *pB1p, *pB2p;
    cudaGetSymbolAddress((void**)&pA2dft,  d_A2dft);
    cudaGetSymbolAddress((void**)&pB2dft,  d_B2dft);
    cudaGetSymbolAddress((void**)&pA2mel,  d_A2mel);
    cudaGetSymbolAddress((void**)&pB2mel,  d_B2mel);
    cudaGetSymbolAddress((void**)&pMelsp,  d_melsp);
    cudaGetSymbolAddress((void**)&pB2conv, d_B2conv);
    cudaGetSymbolAddress((void**)&pA2g,    d_A2g);
    cudaGetSymbolAddress((void**)&pB2W1p,  d_B2W1p);
    cudaGetSymbolAddress((void**)&pB2W2p,  d_B2W2p);
    cudaGetSymbolAddress((void**)&pU1p,    d_U1p);
    cudaGetSymbolAddress((void**)&pU2p,    d_U2p);
    cudaGetSymbolAddress((void**)&pH1s,    d_h1s);
    cudaGetSymbolAddress((void**)&pG,      d_g);
    cudaGetSymbolAddress((void**)&pHmean,  d_hmean);
    cudaGetSymbolAddress((void**)&pHfc,    d_hfc);
    cudaGetSymbolAddress((void**)&pB1p,    d_b1p);
    cudaGetSymbolAddress((void**)&pB2p,    d_b2p);

    cudaFuncSetAttribute(k_lstm_mma, cudaFuncAttributeMaxDynamicSharedMemorySize, LSTM_SMEM_BYTES);
    cudaFuncSetAttribute(k_gemm,     cudaFuncAttributeMaxDynamicSharedMemorySize, GEMM_SMEM_BYTES);

    k_precompute<<<128, 256>>>(conv_w, W1, W2, U1, U2, b1, b2);
    k_window<<<dim3(NFRAMES, BATCH), 256>>>(x);

    // DFT -> power split-pack into A2mel
    k_gemm<<<dim3(NP_DFT / 64, R1 / 128), 256, GEMM_SMEM_BYTES>>>(
        pA2dft, pB2dft, KP_DFT, nullptr, 1, nullptr, 0, NBINS, pA2mel, KP_MEL);
    // mel -> split pack
    k_gemm<<<dim3(2, R1 / 128), 256, GEMM_SMEM_BYTES>>>(
        pA2mel, pB2mel, KP_MEL, nullptr, 2, nullptr, 0, NMELS, pMelsp, 128);
    // conv (shifted-row) -> split pack into A2g
    k_gemm_conv<<<dim3(2, R2 / 128), 256>>>(pMelsp, pB2conv, conv_b, pA2g);
    // g1 (permuted gates)
    k_gemm<<<dim3(8, R2 / 128), 256, GEMM_SMEM_BYTES>>>(
        pA2g, pB2W1p, KP_G, pB1p, 0, pG, G4, G4, nullptr, 0);
    k_lstm_mma<<<BATCH / 16, 256, LSTM_SMEM_BYTES>>>(pG, pU1p, pH1s, nullptr);
    // g2 (permuted gates)
    k_gemm<<<dim3(8, R2 / 128), 256, GEMM_SMEM_BYTES>>>(
        pH1s, pB2W2p, KP_G, pB2p, 0, pG, G4, G4, nullptr, 0);
    k_lstm_mma<<<BATCH / 16, 256, LSTM_SMEM_BYTES>>>(pG, pU2p, nullptr, pHmean);

    k_sgemm<<<dim3(2, BATCH / 64), 128>>>(pHmean, fc1_w, pHfc, fc1_b, BATCH, 128, 128);
    k_sgemm<<<dim3(1, BATCH / 64), 128>>>(pHfc, proj_w, out, proj_b, BATCH, 35, 128);
}

// round 10
// speedup vs baseline: 1.4910x; 1.0064x over previous
#include <cuda_runtime.h>
#include <cuda_bf16.h>
#include <math.h>

// ---------------- problem dims ----------------
#define BATCH   1024
#define TLEN    16000
#define NFFT    400
#define HOP     200
#define NBINS   201
#define NMELS   128
#define NFRAMES 81
#define TSTEPS  79
#define HID     128
#define G4      512
#define R1      (BATCH*NFRAMES)   // 82944
#define R2      (BATCH*TSTEPS)    // 80896

#define KP_DFT  416
#define KP_MEL  224
#define KP_G    128
#define NP_DFT  448
#define KCONV   384

// k_gemm dynamic smem layout (bf16 elems)
#define GEMM_SMEM_ELEMS (2*128*40*2 + 2*64*40*2)   // 30720
#define GEMM_SMEM_BYTES (GEMM_SMEM_ELEMS*2)        // 61440
#define OFF_AL  10240
#define OFF_BH  20480
#define OFF_BL  25600

// LSTM smem (bf16 elements)
#define UH_STRIDE 136
#define ULW_STRIDE 24
#define H_STRIDE  264
#define SM_UH   (512*UH_STRIDE)
#define SM_ULW  (3*64*ULW_STRIDE)
#define SM_UL   (8*SM_ULW)
#define SM_H    (16*H_STRIDE)
#define LSTM_SMEM_BYTES ((SM_UH + SM_UL + SM_H)*2)  // 221440

// ---------------- scratch ----------------
__device__ float          d_hann[NFFT];
__device__ __nv_bfloat16  d_A2dft[(size_t)R1 * 2 * KP_DFT];
__device__ __nv_bfloat16  d_B2dft[(size_t)NP_DFT * 2 * KP_DFT];
__device__ __nv_bfloat16  d_A2mel[(size_t)R1 * 2 * KP_MEL];
__device__ __nv_bfloat16  d_B2mel[(size_t)128 * 2 * KP_MEL];
__device__ __nv_bfloat16  d_melsp[(size_t)R1 * 256];
__device__ __nv_bfloat16  d_B2conv[(size_t)128 * 2 * KCONV];
__device__ __nv_bfloat16  d_A2g[(size_t)R2 * 2 * KP_G];
__device__ __nv_bfloat16  d_B2W1p[(size_t)G4 * 2 * KP_G];
__device__ __nv_bfloat16  d_B2W2p[(size_t)G4 * 2 * KP_G];
__device__ __nv_bfloat16  d_U1p[(size_t)G4 * 2 * KP_G];
__device__ __nv_bfloat16  d_U2p[(size_t)G4 * 2 * KP_G];
__device__ float          d_b1p[G4];
__device__ float          d_b2p[G4];
__device__ float          d_g[(size_t)R2 * G4];
__device__ __nv_bfloat16  d_h1s[(size_t)R2 * 2 * KP_G];
__device__ float          d_hmean[BATCH * 128];
__device__ float          d_hfc[BATCH * 128];

// ---------------- helpers ----------------
__device__ __forceinline__ float sigf(float x) { return 1.0f / (1.0f + __expf(-x)); }
__device__ __forceinline__ float tanhf_acc(float x) {
    float t = __expf(-2.0f * fabsf(x));
    float r = (1.0f - t) / (1.0f + t);
    return copysignf(r, x);
}
__device__ __forceinline__ void splitw(__nv_bfloat16* P, size_t base, int KpOut, int k, float v) {
    __nv_bfloat16 h = __float2bfloat16(v);
    P[base + k] = h;
    P[base + KpOut + k] = __float2bfloat16(v - __bfloat162float(h));
}
__device__ __forceinline__ unsigned smaddr(const void* p) {
    return (unsigned)__cvta_generic_to_shared(p);
}
__device__ __forceinline__ void cpa16(unsigned dst, const void* src) {
    asm volatile("cp.async.cg.shared.global [%0], [%1], 16;" :: "r"(dst), "l"(src));
}
__device__ __forceinline__ void cpa_commit() { asm volatile("cp.async.commit_group;"); }
__device__ __forceinline__ void mma16816(float* c, const unsigned* a, unsigned b0, unsigned b1) {
    asm volatile(
        "mma.sync.aligned.m16n8k16.row.col.f32.bf16.bf16.f32 "
        "{%0,%1,%2,%3}, {%4,%5,%6,%7}, {%8,%9}, {%0,%1,%2,%3};"
        : "+f"(c[0]), "+f"(c[1]), "+f"(c[2]), "+f"(c[3])
        : "r"(a[0]), "r"(a[1]), "r"(a[2]), "r"(a[3]), "r"(b0), "r"(b1));
}
__device__ __forceinline__ int gperm(int n) {
    int w = n >> 6, s = n & 63, gate = s >> 4, u = s & 15;
    return gate * 128 + w * 16 + u;
}

// ---------------- precompute (fp32 fast math) ----------------
__global__ void k_precompute(const float* __restrict__ conv_w,
                             const float* __restrict__ W1, const float* __restrict__ W2,
                             const float* __restrict__ U1, const float* __restrict__ U2,
                             const float* __restrict__ b1, const float* __restrict__ b2) {
    int tid = blockIdx.x * blockDim.x + threadIdx.x;
    int nth = gridDim.x * blockDim.x;

    for (int k = tid; k < NFFT; k += nth)
        d_hann[k] = 0.5f - 0.5f * cospif((float)k / 200.0f);

    for (int idx = tid; idx < NP_DFT * KP_DFT; idx += nth) {
        int n = idx / KP_DFT, k = idx % KP_DFT;
        float v = 0.f;
        if (n < 2 * NBINS && k < NFFT) {
            int m = n >> 1;
            int ph = (m * k) % 400;
            float s, c;
            sincospif((float)ph / 200.0f, &s, &c);
            v = (n & 1) ? s : c;
        }
        splitw(d_B2dft, (size_t)n * (2 * KP_DFT), KP_DFT, k, v);
    }

    const float mel_max = 2595.0f * log10f(1.0f + 8000.0f / 700.0f);
    for (int idx = tid; idx < 128 * KP_MEL; idx += nth) {
        int m = idx / KP_MEL, k = idx % KP_MEL;
        float v = 0.f;
        if (k < NBINS) {
            float freq = 40.0f * (float)k;
            float f0 = 700.0f * (exp10f((mel_max * (float)(m    ) / 129.0f) / 2595.0f) - 1.0f);
            float f1 = 700.0f * (exp10f((mel_max * (float)(m + 1) / 129.0f) / 2595.0f) - 1.0f);
            float f2 = 700.0f * (exp10f((mel_max * (float)(m + 2) / 129.0f) / 2595.0f) - 1.0f);
            float dn = (freq - f0) / (f1 - f0);
            float up = (f2 - freq) / (f2 - f1);
            float t = fminf(dn, up);
            v = fmaxf(t, 0.0f);
        }
        splitw(d_B2mel, (size_t)m * (2 * KP_MEL), KP_MEL, k, v);
    }

    for (int idx = tid; idx < 128 * KCONV; idx += nth) {
        int o = idx / KCONV, q = idx % KCONV;
        int kk = q >> 7, i = q & 127;
        splitw(d_B2conv, (size_t)o * (2 * KCONV), KCONV, q, conv_w[o * 384 + i * 3 + kk]);
    }

    for (int idx = tid; idx < G4 * KP_G; idx += nth) {
        int n = idx / KP_G, k = idx % KP_G;
        int no = gperm(n);
        splitw(d_B2W1p, (size_t)n * (2 * KP_G), KP_G, k, W1[k * G4 + no]);
        splitw(d_B2W2p, (size_t)n * (2 * KP_G), KP_G, k, W2[k * G4 + no]);
        splitw(d_U1p,   (size_t)n * (2 * KP_G), KP_G, k, U1[k * G4 + no]);
        splitw(d_U2p,   (size_t)n * (2 * KP_G), KP_G, k, U2[k * G4 + no]);
    }
    for (int n = tid; n < G4; n += nth) {
        int no = gperm(n);
        d_b1p[n] = b1[no];
        d_b2p[n] = b2[no];
    }

    for (int idx = tid; idx < R1 * (KP_MEL - NBINS); idx += nth) {
        int r = idx / (KP_MEL - NBINS), k = NBINS + idx % (KP_MEL - NBINS);
        d_A2mel[(size_t)r * (2 * KP_MEL) + k] = __float2bfloat16(0.f);
        d_A2mel[(size_t)r * (2 * KP_MEL) + KP_MEL + k] = __float2bfloat16(0.f);
    }
}

// ---------------- window ----------------
__global__ void k_window(const float* __restrict__ x) {
    int f = blockIdx.x, b = blockIdx.y, tid = threadIdx.x;
    size_t row = (size_t)(b * NFRAMES + f) * (2 * KP_DFT);
    for (int k = tid; k < KP_DFT; k += blockDim.x) {
        float v = 0.f;
        if (k < NFFT) {
            int p = f * HOP + k - 200;
            int i = (p < 0) ? -p : ((p >= TLEN) ? (2 * TLEN - 2 - p) : p);
            v = x[(size_t)b * TLEN + i] * d_hann[k];
        }
        __nv_bfloat16 h = __float2bfloat16(v);
        d_A2dft[row + k] = h;
        d_A2dft[row + KP_DFT + k] = __float2bfloat16(v - __bfloat162float(h));
    }
}

// ---------------- single-pass split-bf16 tensor GEMM (R9 proven) ----------------
__global__ void __launch_bounds__(256, 3)
k_gemm(const __nv_bfloat16* __restrict__ A2, const __nv_bfloat16* __restrict__ B2,
       int Kp, const float* __restrict__ bias, int mode,
       float* __restrict__ outF, int ldc, int Nreal,
       __nv_bfloat16* __restrict__ outP, int KpOut) {
    extern __shared__ __nv_bfloat16 smd[];
    __nv_bfloat16* AHs = smd;
    __nv_bfloat16* ALs = smd + OFF_AL;
    __nv_bfloat16* BHs = smd + OFF_BH;
    __nv_bfloat16* BLs = smd + OFF_BL;

    int tid = threadIdx.x, lane = tid & 31, w = tid >> 5;
    int wm = w >> 1, wn = w & 1;
    int m0 = blockIdx.y * 128, n0 = blockIdx.x * 64;
    int g = lane >> 2, t = lane & 3;
    int strideA = 2 * Kp;
    int la_row = tid >> 2, la_kc = (tid & 3) << 3;

    const __nv_bfloat16* Abase = A2 + (size_t)m0 * strideA;
    const __nv_bfloat16* Bbase = B2 + (size_t)n0 * strideA;

    float acc[2][4][4];
    #pragma unroll
    for (int i = 0; i < 2; i++)
        #pragma unroll
        for (int j = 0; j < 4; j++)
            #pragma unroll
            for (int q = 0; q < 4; q++) acc[i][j][q] = 0.f;

    auto load_chunk = [&](int buf, int kk) {
        int bo = buf * 5120, bo2 = buf * 2560;
        cpa16(smaddr(AHs + bo + la_row * 40 + la_kc),        Abase + (size_t)la_row * strideA + kk + la_kc);
        cpa16(smaddr(AHs + bo + (la_row + 64) * 40 + la_kc), Abase + (size_t)(la_row + 64) * strideA + kk + la_kc);
        cpa16(smaddr(ALs + bo + la_row * 40 + la_kc),        Abase + (size_t)la_row * strideA + Kp + kk + la_kc);
        cpa16(smaddr(ALs + bo + (la_row + 64) * 40 + la_kc), Abase + (size_t)(la_row + 64) * strideA + Kp + kk + la_kc);
        cpa16(smaddr(BHs + bo2 + la_row * 40 + la_kc),       Bbase + (size_t)la_row * strideA + kk + la_kc);
        cpa16(smaddr(BLs + bo2 + la_row * 40 + la_kc),       Bbase + (size_t)la_row * strideA + Kp + kk + la_kc);
        cpa_commit();
    };

    load_chunk(0, 0);

    #pragma unroll 1
    for (int kk = 0; kk < Kp; kk += 32) {
        int buf = (kk >> 5) & 1;
        asm volatile("cp.async.wait_group 0;");
        __syncthreads();
        if (kk + 32 < Kp) load_chunk(buf ^ 1, kk + 32);

        int bo = buf * 5120, bo2 = buf * 2560;
        #pragma unroll
        for (int ko = 0; ko < 32; ko += 16) {
            unsigned ahf[2][4], alf[2][4], bhf[4][2], blf[4][2];
            #pragma unroll
            for (int i = 0; i < 2; i++) {
                int r = wm * 32 + i * 16;
                ahf[i][0] = *(const unsigned*)&AHs[bo + (r + g) * 40 + ko + 2 * t];
                ahf[i][1] = *(const unsigned*)&AHs[bo + (r + g + 8) * 40 + ko + 2 * t];
                ahf[i][2] = *(const unsigned*)&AHs[bo + (r + g) * 40 + ko + 2 * t + 8];
                ahf[i][3] = *(const unsigned*)&AHs[bo + (r + g + 8) * 40 + ko + 2 * t + 8];
                alf[i][0] = *(const unsigned*)&ALs[bo + (r + g) * 40 + ko + 2 * t];
                alf[i][1] = *(const unsigned*)&ALs[bo + (r + g + 8) * 40 + ko + 2 * t];
                alf[i][2] = *(const unsigned*)&ALs[bo + (r + g) * 40 + ko + 2 * t + 8];
                alf[i][3] = *(const unsigned*)&ALs[bo + (r + g + 8) * 40 + ko + 2 * t + 8];
            }
            #pragma unroll
            for (int j = 0; j < 4; j++) {
                int bn = wn * 32 + j * 8 + g;
                bhf[j][0] = *(const unsigned*)&BHs[bo2 + bn * 40 + ko + 2 * t];
                bhf[j][1] = *(const unsigned*)&BHs[bo2 + bn * 40 + ko + 2 * t + 8];
                blf[j][0] = *(const unsigned*)&BLs[bo2 + bn * 40 + ko + 2 * t];
                blf[j][1] = *(const unsigned*)&BLs[bo2 + bn * 40 + ko + 2 * t + 8];
            }
            #pragma unroll
            for (int i = 0; i < 2; i++)
                #pragma unroll
                for (int j = 0; j < 4; j++) {
                    mma16816(acc[i][j], ahf[i], bhf[j][0], bhf[j][1]);
                    mma16816(acc[i][j], ahf[i], blf[j][0], blf[j][1]);
                    mma16816(acc[i][j], alf[i], bhf[j][0], bhf[j][1]);
                }
        }
        __syncthreads();
    }

    #pragma unroll
    for (int i = 0; i < 2; i++) {
        int r = m0 + wm * 32 + i * 16 + g;
        #pragma unroll
        for (int j = 0; j < 4; j++) {
            int c = n0 + wn * 32 + j * 8 + 2 * t;
            float v00 = acc[i][j][0], v01 = acc[i][j][1];
            float v10 = acc[i][j][2], v11 = acc[i][j][3];
            if (mode == 0) {
                float b0 = bias ? bias[c] : 0.f, b1 = bias ? bias[c + 1] : 0.f;
                outF[(size_t)r * ldc + c]           = v00 + b0;
                outF[(size_t)r * ldc + c + 1]       = v01 + b1;
                outF[(size_t)(r + 8) * ldc + c]     = v10 + b0;
                outF[(size_t)(r + 8) * ldc + c + 1] = v11 + b1;
            } else if (mode == 1) {
                int k = c >> 1;
                if (k < Nreal) {
                    splitw(outP, (size_t)r * (2 * KpOut), KpOut, k, v00 * v00 + v01 * v01);
                    splitw(outP, (size_t)(r + 8) * (2 * KpOut), KpOut, k, v10 * v10 + v11 * v11);
                }
            } else {
                float b0 = bias ? bias[c] : 0.f, b1 = bias ? bias[c + 1] : 0.f;
                splitw(outP, (size_t)r * (2 * KpOut), KpOut, c, v00 + b0);
                splitw(outP, (size_t)r * (2 * KpOut), KpOut, c + 1, v01 + b1);
                splitw(outP, (size_t)(r + 8) * (2 * KpOut), KpOut, c, v10 + b0);
                splitw(outP, (size_t)(r + 8) * (2 * KpOut), KpOut, c + 1, v11 + b1);
            }
        }
    }
}

// ---------------- conv GEMM (R5 proven): shifted rows, 9 segments ----------------
__global__ void __launch_bounds__(256, 3)
k_gemm_conv(const __nv_bfloat16* __restrict__ Msp, const __nv_bfloat16* __restrict__ B2,
            const float* __restrict__ bias, __nv_bfloat16* __restrict__ outP) {
    __shared__ __nv_bfloat16 As[2][128][40];
    __shared__ __nv_bfloat16 Bs[2][64][40];
    int tid = threadIdx.x, lane = tid & 31, w = tid >> 5;
    int wm = w >> 1, wn = w & 1;
    int m0 = blockIdx.y * 128, n0 = blockIdx.x * 64;
    int g = lane >> 2, t = lane & 3;
    int la_row = tid >> 2, la_kc = (tid & 3) << 3;

    int gm0 = m0 + la_row, gm1 = m0 + la_row + 64;
    int sr0 = gm0 + 2 * (gm0 / TSTEPS);
    int sr1 = gm1 + 2 * (gm1 / TSTEPS);

    float acc[2][4][4];
    #pragma unroll
    for (int i = 0; i < 2; i++)
        #pragma unroll
        for (int j = 0; j < 4; j++)
            #pragma unroll
            for (int q = 0; q < 4; q++) acc[i][j][q] = 0.f;

    #pragma unroll 1
    for (int s = 0; s < 9; s++) {
        int split = s / 3, shift = s % 3;
        int aoff = (split == 2) ? 128 : 0;
        int boff = ((split == 1) ? KCONV : 0) + shift * 128;
        const __nv_bfloat16* A0 = Msp + (size_t)(sr0 + shift) * 256 + aoff;
        const __nv_bfloat16* A1 = Msp + (size_t)(sr1 + shift) * 256 + aoff;
        const __nv_bfloat16* Bb = B2 + (size_t)n0 * (2 * KCONV) + boff;

        cpa16(smaddr(&As[0][la_row][la_kc]),      A0 + la_kc);
        cpa16(smaddr(&As[0][la_row + 64][la_kc]), A1 + la_kc);
        cpa16(smaddr(&Bs[0][la_row][la_kc]),      Bb + (size_t)la_row * (2 * KCONV) + la_kc);
        cpa_commit();
        #pragma unroll 1
        for (int kk = 0; kk < 128; kk += 32) {
            int buf = (kk >> 5) & 1;
            asm volatile("cp.async.wait_group 0;");
            __syncthreads();
            if (kk + 32 < 128) {
                int nb = buf ^ 1, kn = kk + 32;
                cpa16(smaddr(&As[nb][la_row][la_kc]),      A0 + kn + la_kc);
                cpa16(smaddr(&As[nb][la_row + 64][la_kc]), A1 + kn + la_kc);
                cpa16(smaddr(&Bs[nb][la_row][la_kc]),      Bb + (size_t)la_row * (2 * KCONV) + kn + la_kc);
                cpa_commit();
            }
            #pragma unroll
            for (int ko = 0; ko < 32; ko += 16) {
                unsigned a[2][4], bfr[4][2];
                #pragma unroll
                for (int i = 0; i < 2; i++) {
                    int r = wm * 32 + i * 16;
                    a[i][0] = *(const unsigned*)&As[buf][r + g][ko + 2 * t];
                    a[i][1] = *(const unsigned*)&As[buf][r + g + 8][ko + 2 * t];
                    a[i][2] = *(const unsigned*)&As[buf][r + g][ko + 2 * t + 8];
                    a[i][3] = *(const unsigned*)&As[buf][r + g + 8][ko + 2 * t + 8];
                }
                #pragma unroll
                for (int j = 0; j < 4; j++) {
                    int bn = wn * 32 + j * 8 + g;
                    bfr[j][0] = *(const unsigned*)&Bs[buf][bn][ko + 2 * t];
                    bfr[j][1] = *(const unsigned*)&Bs[buf][bn][ko + 2 * t + 8];
                }
                #pragma unroll
                for (int i = 0; i < 2; i++)
                    #pragma unroll
                    for (int j = 0; j < 4; j++)
                        mma16816(acc[i][j], a[i], bfr[j][0], bfr[j][1]);
            }
            __syncthreads();
        }
    }

    #pragma unroll
    for (int i = 0; i < 2; i++) {
        int r = m0 + wm * 32 + i * 16 + g;
        #pragma unroll
        for (int j = 0; j < 4; j++) {
            int c = n0 + wn * 32 + j * 8 + 2 * t;
            float b0 = bias[c], b1 = bias[c + 1];
            splitw(outP, (size_t)r * 256, 128, c,     acc[i][j][0] + b0);
            splitw(outP, (size_t)r * 256, 128, c + 1, acc[i][j][1] + b1);
            splitw(outP, (size_t)(r + 8) * 256, 128, c,     acc[i][j][2] + b0);
            splitw(outP, (size_t)(r + 8) * 256, 128, c + 1, acc[i][j][3] + b1);
        }
    }
}

// ---------------- tensor-core LSTM v3 + coalesced h-split store ----------------
__global__ void __launch_bounds__(256)
k_lstm_mma(const float* __restrict__ gx, const __nv_bfloat16* __restrict__ Up,
           __nv_bfloat16* __restrict__ hsplit, float* __restrict__ hmean) {
    extern __shared__ __nv_bfloat16 sm[];
    __nv_bfloat16* Uh  = sm;
    __nv_bfloat16* Ulw = sm + SM_UH;
    __nv_bfloat16* Hsp = sm + SM_UH + SM_UL;

    int tid = threadIdx.x, lane = tid & 31, w = tid >> 5;
    int g = lane >> 2, tq = lane & 3;
    int b0 = blockIdx.x * 16;
    int wbase = w * 64;
    __nv_bfloat16* myUl = Ulw + w * SM_ULW;

    for (int idx = tid; idx < 512 * 16; idx += 256) {
        int n = idx >> 4, j = idx & 15;
        *(uint4*)(Uh + n * UH_STRIDE + j * 8) = *(const uint4*)(Up + (size_t)n * 256 + j * 8);
    }
    for (int idx = tid; idx < SM_H; idx += 256) Hsp[idx] = __float2bfloat16(0.f);

    float cst[8], hsum[8];
    #pragma unroll
    for (int i = 0; i < 8; i++) { cst[i] = 0.f; hsum[i] = 0.f; }

    for (int t = 0; t < TSTEPS; t++) {
        float acc[8][4];
        {
            size_t rlo = ((size_t)(b0 + g) * TSTEPS + t) * G4 + wbase + 2 * tq;
            size_t rhi = ((size_t)(b0 + g + 8) * TSTEPS + t) * G4 + wbase + 2 * tq;
            #pragma unroll
            for (int a = 0; a < 8; a++) {
                float2 v0 = *(const float2*)&gx[rlo + a * 8];
                float2 v1 = *(const float2*)&gx[rhi + a * 8];
                acc[a][0] = v0.x; acc[a][1] = v0.y;
                acc[a][2] = v1.x; acc[a][3] = v1.y;
            }
        }
        __syncthreads();

        #pragma unroll
        for (int c0 = 0; c0 < 2; c0++) {
            __nv_bfloat16* buf = myUl + (c0 % 3) * 64 * ULW_STRIDE;
            #pragma unroll
            for (int i = 0; i < 4; i++) {
                int u = lane + 32 * i, n1 = u >> 1, hf = u & 1;
                cpa16(smaddr(buf + n1 * ULW_STRIDE + hf * 8),
                      Up + (size_t)(wbase + n1) * 256 + 128 + c0 * 16 + hf * 8);
            }
            cpa_commit();
        }

        #pragma unroll 1
        for (int c = 0; c < 8; c++) {
            if (c < 7) asm volatile("cp.async.wait_group 1;");
            else       asm volatile("cp.async.wait_group 0;");
            __syncwarp();
            if (c + 2 < 8) {
                __nv_bfloat16* nbuf = myUl + ((c + 2) % 3) * 64 * ULW_STRIDE;
                #pragma unroll
                for (int i = 0; i < 4; i++) {
                    int u = lane + 32 * i, n1 = u >> 1, hf = u & 1;
                    cpa16(smaddr(nbuf + n1 * ULW_STRIDE + hf * 8),
                          Up + (size_t)(wbase + n1) * 256 + 128 + (c + 2) * 16 + hf * 8);
                }
                cpa_commit();
            }
            int ko = c * 16 + 2 * tq;
            unsigned ah[4], al[4];
            ah[0] = *(const unsigned*)&Hsp[g * H_STRIDE + ko];
            ah[1] = *(const unsigned*)&Hsp[(g + 8) * H_STRIDE + ko];
            ah[2] = *(const unsigned*)&Hsp[g * H_STRIDE + ko + 8];
            ah[3] = *(const unsigned*)&Hsp[(g + 8) * H_STRIDE + ko + 8];
            al[0] = *(const unsigned*)&Hsp[g * H_STRIDE + 128 + ko];
            al[1] = *(const unsigned*)&Hsp[(g + 8) * H_STRIDE + 128 + ko];
            al[2] = *(const unsigned*)&Hsp[g * H_STRIDE + 128 + ko + 8];
            al[3] = *(const unsigned*)&Hsp[(g + 8) * H_STRIDE + 128 + ko + 8];
            const __nv_bfloat16* ulB = myUl + (c % 3) * 64 * ULW_STRIDE;
            #pragma unroll
            for (int bn = 0; bn < 8; bn++) {
                int n = wbase + bn * 8 + g;
                const __nv_bfloat16* bph = Uh + n * UH_STRIDE + ko;
                unsigned h0 = *(const unsigned*)bph;
                unsigned h1 = *(const unsigned*)(bph + 8);
                mma16816(acc[bn], ah, h0, h1);
                mma16816(acc[bn], al, h0, h1);
                const __nv_bfloat16* bpl = ulB + (bn * 8 + g) * ULW_STRIDE + 2 * tq;
                unsigned l0 = *(const unsigned*)bpl;
                unsigned l1 = *(const unsigned*)(bpl + 8);
                mma16816(acc[bn], ah, l0, l1);
            }
        }
        __syncthreads();

        #pragma unroll
        for (int uh = 0; uh < 2; uh++)
            #pragma unroll
            for (int par = 0; par < 2; par++)
                #pragma unroll
                for (int q2 = 0; q2 < 2; q2++) {
                    int u = uh * 8 + 2 * tq + par;
                    int r = g + 8 * q2;
                    int qq = q2 * 2 + par;
                    int ci = uh * 4 + par * 2 + q2;
                    float gi = acc[0 + uh][qq];
                    float gf = acc[2 + uh][qq];
                    float gg = acc[4 + uh][qq];
                    float go = acc[6 + uh][qq];
                    float c = sigf(gf) * cst[ci] + sigf(gi) * tanhf_acc(gg);
                    float h = sigf(go) * tanhf_acc(c);
                    cst[ci] = c;
                    int ug = w * 16 + u;
                    __nv_bfloat16 hh = __float2bfloat16(h);
                    __nv_bfloat16 hl = __float2bfloat16(h - __bfloat162float(hh));
                    Hsp[r * H_STRIDE + ug] = hh;
                    Hsp[r * H_STRIDE + 128 + ug] = hl;
                    hsum[ci] += h;
                }

        // coalesced h-split store from smem (layer 1 only)
        if (hsplit) {
            __syncthreads();
            #pragma unroll
            for (int i = tid; i < 512; i += 256) {
                int r = i >> 5, c16 = i & 31;
                size_t row2 = ((size_t)(b0 + r) * TSTEPS + t) * 256;
                *(uint4*)(hsplit + row2 + c16 * 8) =
                    *(const uint4*)(Hsp + r * H_STRIDE + c16 * 8);
            }
        }
    }

    if (hmean) {
        #pragma unroll
        for (int uh = 0; uh < 2; uh++)
            #pragma unroll
            for (int par = 0; par < 2; par++)
                #pragma unroll
                for (int q2 = 0; q2 < 2; q2++) {
                    int u = uh * 8 + 2 * tq + par;
                    int r = g + 8 * q2;
                    int ci = uh * 4 + par * 2 + q2;
                    hmean[(size_t)(b0 + r) * 128 + w * 16 + u] = hsum[ci] * (1.0f / (float)TSTEPS);
                }
    }
}

// ---------------- small fp32 SGEMM for fc/proj ----------------
__global__ void k_sgemm(const float* __restrict__ A, const float* __restrict__ Bm,
                        float* __restrict__ C, const float* __restrict__ bias,
                        int M, int N, int K) {
    __shared__ float As[8][68];
    __shared__ float Bs[8][64];
    int tid = threadIdx.x;
    int m0 = blockIdx.y * 64, n0 = blockIdx.x * 64;
    int tm = tid & 15, tn = tid >> 4;
    float acc[4][8];
    #pragma unroll
    for (int i = 0; i < 4; i++)
        #pragma unroll
        for (int j = 0; j < 8; j++) acc[i][j] = 0.f;
    for (int kk = 0; kk < K; kk += 8) {
        #pragma unroll
        for (int i = 0; i < 4; i++) {
            int l = tid + i * 128, m = l >> 3, k = l & 7;
            int gm = m0 + m, gk = kk + k;
            As[k][m] = (gm < M && gk < K) ? A[(size_t)gm * K + gk] : 0.f;
        }
        #pragma unroll
        for (int i = 0; i < 4; i++) {
            int l = tid + i * 128, k = l >> 6, n = l & 63;
            int gk = kk + k, gn = n0 + n;
            Bs[k][n] = (gk < K && gn < N) ? Bm[(size_t)gk * N + gn] : 0.f;
        }
        __syncthreads();
        #pragma unroll
        for (int k = 0; k < 8; k++) {
            float a[4], bv[8];
            #pragma unroll
            for (int i = 0; i < 4; i++) a[i] = As[k][tm * 4 + i];
            #pragma unroll
            for (int j = 0; j < 8; j++) bv[j] = Bs[k][tn * 8 + j];
            #pragma unroll
            for (int i = 0; i < 4; i++)
                #pragma unroll
                for (int j = 0; j < 8; j++) acc[i][j] += a[i] * bv[j];
        }
        __syncthreads();
    }
    #pragma unroll
    for (int i = 0; i < 4; i++) {
        int gm = m0 + tm * 4 + i;
        if (gm >= M) continue;
        #pragma unroll
        for (int j = 0; j < 8; j++) {
            int gn = n0 + tn * 8 + j;
            if (gn < N) C[(size_t)gm * N + gn] = acc[i][j] + (bias ? bias[gn] : 0.f);
        }
    }
}

// ---------------- launch ----------------
extern "C" void kernel_launch(void* const* d_in, const int* in_sizes, int n_in,
                              void* d_out, int out_size) {
    const float* x      = (const float*)d_in[0];
    const float* conv_w = (const float*)d_in[1];
    const float* conv_b = (const float*)d_in[2];
    const float* W1     = (const float*)d_in[3];
    const float* U1     = (const float*)d_in[4];
    const float* b1     = (const float*)d_in[5];
    const float* W2     = (const float*)d_in[6];
    const float* U2     = (const float*)d_in[7];
    const float* b2     = (const float*)d_in[8];
    const float* fc1_w  = (const float*)d_in[9];
    const float* fc1_b  = (const float*)d_in[10];
    const float* proj_w = (const float*)d_in[11];
    const float* proj_b = (const float*)d_in[12];
    float* out = (float*)d_out;

    __nv_bfloat16 *pA2dft, *pB2dft, *pA2mel, *pB2mel, *pMelsp, *pB2conv, *pA2g;
    __nv_bfloat16 *pB2W1p, *pB2W2p, *pU1p, *pU2p, *pH1s;
    float *pG, *pHmean, *pHfc, *pB1p, *pB2p;
    cudaGetSymbolAddress((void**)&pA2dft,  d_A2dft);
    cudaGetSymbolAddress((void**)&pB2dft,  d_B2dft);
    cudaGetSymbolAddress((void**)&pA2mel,  d_A2mel);
    cudaGetSymbolAddress((void**)&pB2mel,  d_B2mel);
    cudaGetSymbolAddress((void**)&pMelsp,  d_melsp);
    cudaGetSymbolAddress((void**)&pB2conv, d_B2conv);
    cudaGetSymbolAddress((void**)&pA2g,    d_A2g);
    cudaGetSymbolAddress((void**)&pB2W1p,  d_B2W1p);
    cudaGetSymbolAddress((void**)&pB2W2p,  d_B2W2p);
    cudaGetSymbolAddress((void**)&pU1p,    d_U1p);
    cudaGetSymbolAddress((void**)&pU2p,    d_U2p);
    cudaGetSymbolAddress((void**)&pH1s,    d_h1s);
    cudaGetSymbolAddress((void**)&pG,      d_g);
    cudaGetSymbolAddress((void**)&pHmean,  d_hmean);
    cudaGetSymbolAddress((void**)&pHfc,    d_hfc);
    cudaGetSymbolAddress((void**)&pB1p,    d_b1p);
    cudaGetSymbolAddress((void**)&pB2p,    d_b2p);

    cudaFuncSetAttribute(k_lstm_mma, cudaFuncAttributeMaxDynamicSharedMemorySize, LSTM_SMEM_BYTES);
    cudaFuncSetAttribute(k_gemm,     cudaFuncAttributeMaxDynamicSharedMemorySize, GEMM_SMEM_BYTES);
    cudaFuncSetAttribute(k_gemm,     cudaFuncAttributePreferredSharedMemoryCarveout,
                         cudaSharedmemCarveoutMaxShared);

    k_precompute<<<128, 256>>>(conv_w, W1, W2, U1, U2, b1, b2);
    k_window<<<dim3(NFRAMES, BATCH), 256>>>(x);

    // DFT -> power split-pack into A2mel
    k_gemm<<<dim3(NP_DFT / 64, R1 / 128), 256, GEMM_SMEM_BYTES>>>(
        pA2dft, pB2dft, KP_DFT, nullptr, 1, nullptr, 0, NBINS, pA2mel, KP_MEL);
    // mel -> split pack
    k_gemm<<<dim3(2, R1 / 128), 256, GEMM_SMEM_BYTES>>>(
        pA2mel, pB2mel, KP_MEL, nullptr, 2, nullptr, 0, NMELS, pMelsp, 128);
    // conv (shifted-row) -> split pack into A2g
    k_gemm_conv<<<dim3(2, R2 / 128), 256>>>(pMelsp, pB2conv, conv_b, pA2g);
    // g1 (permuted gates)
    k_gemm<<<dim3(8, R2 / 128), 256, GEMM_SMEM_BYTES>>>(
        pA2g, pB2W1p, KP_G, pB1p, 0, pG, G4, G4, nullptr, 0);
    k_lstm_mma<<<BATCH / 16, 256, LSTM_SMEM_BYTES>>>(pG, pU1p, pH1s, nullptr);
    // g2 (permuted gates)
    k_gemm<<<dim3(8, R2 / 128), 256, GEMM_SMEM_BYTES>>>(
        pH1s, pB2W2p, KP_G, pB2p, 0, pG, G4, G4, nullptr, 0);
    k_lstm_mma<<<BATCH / 16, 256, LSTM_SMEM_BYTES>>>(pG, pU2p, nullptr, pHmean);

    k_sgemm<<<dim3(2, BATCH / 64), 128>>>(pHmean, fc1_w, pHfc, fc1_b, BATCH, 128, 128);
    k_sgemm<<<dim3(1, BATCH / 64), 128>>>(pHfc, proj_w, out, proj_b, BATCH, 35, 128);
}

// round 11
// speedup vs baseline: 1.5869x; 1.0643x over previous
#include <cuda_runtime.h>
#include <cuda_bf16.h>
#include <cuda_fp16.h>
#include <math.h>

// ---------------- problem dims ----------------
#define BATCH   1024
#define TLEN    16000
#define NFFT    400
#define HOP     200
#define NBINS   201
#define NMELS   128
#define NFRAMES 81
#define TSTEPS  79
#define HID     128
#define G4      512
#define R1      (BATCH*NFRAMES)   // 82944
#define R2      (BATCH*TSTEPS)    // 80896

#define KP_DFT  416
#define KP_MEL  224
#define KP_G    128
#define NP_DFT  448
#define KCONV   384

// k_gemm dynamic smem layout (bf16 elems)
#define GEMM_SMEM_ELEMS (2*128*40*2 + 2*64*40*2)   // 30720
#define GEMM_SMEM_BYTES (GEMM_SMEM_ELEMS*2)        // 61440
#define OFF_AL  10240
#define OFF_BH  20480
#define OFF_BL  25600

// fp16 DFT kernel smem (half elems): Ah[2][128][40] + Bh[2][64][40]
#define DFT16_SMEM_ELEMS (2*128*40 + 2*64*40)      // 15360
#define DFT16_SMEM_BYTES (DFT16_SMEM_ELEMS*2)      // 30720
#define DOFF_B  10240

// LSTM smem (bf16 elements)
#define UH_STRIDE 136
#define ULW_STRIDE 24
#define H_STRIDE  264
#define SM_UH   (512*UH_STRIDE)
#define SM_ULW  (3*64*ULW_STRIDE)
#define SM_UL   (8*SM_ULW)
#define SM_H    (16*H_STRIDE)
#define LSTM_SMEM_BYTES ((SM_UH + SM_UL + SM_H)*2)  // 221440

// ---------------- scratch ----------------
__device__ float          d_hann[NFFT];
__device__ __half         d_A1dft[(size_t)R1 * KP_DFT];
__device__ __half         d_B1dft[(size_t)NP_DFT * KP_DFT];
__device__ __nv_bfloat16  d_A2mel[(size_t)R1 * 2 * KP_MEL];
__device__ __nv_bfloat16  d_B2mel[(size_t)128 * 2 * KP_MEL];
__device__ __nv_bfloat16  d_melsp[(size_t)R1 * 256];
__device__ __nv_bfloat16  d_B2conv[(size_t)128 * 2 * KCONV];
__device__ __nv_bfloat16  d_A2g[(size_t)R2 * 2 * KP_G];
__device__ __nv_bfloat16  d_B2W1p[(size_t)G4 * 2 * KP_G];
__device__ __nv_bfloat16  d_B2W2p[(size_t)G4 * 2 * KP_G];
__device__ __nv_bfloat16  d_U1p[(size_t)G4 * 2 * KP_G];
__device__ __nv_bfloat16  d_U2p[(size_t)G4 * 2 * KP_G];
__device__ float          d_b1p[G4];
__device__ float          d_b2p[G4];
__device__ float          d_g[(size_t)R2 * G4];
__device__ __nv_bfloat16  d_h1s[(size_t)R2 * 2 * KP_G];
__device__ float          d_hmean[BATCH * 128];
__device__ float          d_hfc[BATCH * 128];

// ---------------- helpers ----------------
__device__ __forceinline__ float sigf(float x) { return 1.0f / (1.0f + __expf(-x)); }
__device__ __forceinline__ float tanhf_acc(float x) {
    float t = __expf(-2.0f * fabsf(x));
    float r = (1.0f - t) / (1.0f + t);
    return copysignf(r, x);
}
__device__ __forceinline__ void splitw(__nv_bfloat16* P, size_t base, int KpOut, int k, float v) {
    __nv_bfloat16 h = __float2bfloat16(v);
    P[base + k] = h;
    P[base + KpOut + k] = __float2bfloat16(v - __bfloat162float(h));
}
__device__ __forceinline__ unsigned smaddr(const void* p) {
    return (unsigned)__cvta_generic_to_shared(p);
}
__device__ __forceinline__ void cpa16(unsigned dst, const void* src) {
    asm volatile("cp.async.cg.shared.global [%0], [%1], 16;" :: "r"(dst), "l"(src));
}
__device__ __forceinline__ void cpa_commit() { asm volatile("cp.async.commit_group;"); }
__device__ __forceinline__ void mma16816(float* c, const unsigned* a, unsigned b0, unsigned b1) {
    asm volatile(
        "mma.sync.aligned.m16n8k16.row.col.f32.bf16.bf16.f32 "
        "{%0,%1,%2,%3}, {%4,%5,%6,%7}, {%8,%9}, {%0,%1,%2,%3};"
        : "+f"(c[0]), "+f"(c[1]), "+f"(c[2]), "+f"(c[3])
        : "r"(a[0]), "r"(a[1]), "r"(a[2]), "r"(a[3]), "r"(b0), "r"(b1));
}
__device__ __forceinline__ void mma16816h(float* c, const unsigned* a, unsigned b0, unsigned b1) {
    asm volatile(
        "mma.sync.aligned.m16n8k16.row.col.f32.f16.f16.f32 "
        "{%0,%1,%2,%3}, {%4,%5,%6,%7}, {%8,%9}, {%0,%1,%2,%3};"
        : "+f"(c[0]), "+f"(c[1]), "+f"(c[2]), "+f"(c[3])
        : "r"(a[0]), "r"(a[1]), "r"(a[2]), "r"(a[3]), "r"(b0), "r"(b1));
}
__device__ __forceinline__ int gperm(int n) {
    int w = n >> 6, s = n & 63, gate = s >> 4, u = s & 15;
    return gate * 128 + w * 16 + u;
}

// ---------------- precompute (fp32 fast math) ----------------
__global__ void k_precompute(const float* __restrict__ conv_w,
                             const float* __restrict__ W1, const float* __restrict__ W2,
                             const float* __restrict__ U1, const float* __restrict__ U2,
                             const float* __restrict__ b1, const float* __restrict__ b2) {
    int tid = blockIdx.x * blockDim.x + threadIdx.x;
    int nth = gridDim.x * blockDim.x;

    for (int k = tid; k < NFFT; k += nth)
        d_hann[k] = 0.5f - 0.5f * cospif((float)k / 200.0f);

    for (int idx = tid; idx < NP_DFT * KP_DFT; idx += nth) {
        int n = idx / KP_DFT, k = idx % KP_DFT;
        float v = 0.f;
        if (n < 2 * NBINS && k < NFFT) {
            int m = n >> 1;
            int ph = (m * k) % 400;
            float s, c;
            sincospif((float)ph / 200.0f, &s, &c);
            v = (n & 1) ? s : c;
        }
        d_B1dft[(size_t)n * KP_DFT + k] = __float2half(v);
    }

    const float mel_max = 2595.0f * log10f(1.0f + 8000.0f / 700.0f);
    for (int idx = tid; idx < 128 * KP_MEL; idx += nth) {
        int m = idx / KP_MEL, k = idx % KP_MEL;
        float v = 0.f;
        if (k < NBINS) {
            float freq = 40.0f * (float)k;
            float f0 = 700.0f * (exp10f((mel_max * (float)(m    ) / 129.0f) / 2595.0f) - 1.0f);
            float f1 = 700.0f * (exp10f((mel_max * (float)(m + 1) / 129.0f) / 2595.0f) - 1.0f);
            float f2 = 700.0f * (exp10f((mel_max * (float)(m + 2) / 129.0f) / 2595.0f) - 1.0f);
            float dn = (freq - f0) / (f1 - f0);
            float up = (f2 - freq) / (f2 - f1);
            float t = fminf(dn, up);
            v = fmaxf(t, 0.0f);
        }
        splitw(d_B2mel, (size_t)m * (2 * KP_MEL), KP_MEL, k, v);
    }

    for (int idx = tid; idx < 128 * KCONV; idx += nth) {
        int o = idx / KCONV, q = idx % KCONV;
        int kk = q >> 7, i = q & 127;
        splitw(d_B2conv, (size_t)o * (2 * KCONV), KCONV, q, conv_w[o * 384 + i * 3 + kk]);
    }

    for (int idx = tid; idx < G4 * KP_G; idx += nth) {
        int n = idx / KP_G, k = idx % KP_G;
        int no = gperm(n);
        splitw(d_B2W1p, (size_t)n * (2 * KP_G), KP_G, k, W1[k * G4 + no]);
        splitw(d_B2W2p, (size_t)n * (2 * KP_G), KP_G, k, W2[k * G4 + no]);
        splitw(d_U1p,   (size_t)n * (2 * KP_G), KP_G, k, U1[k * G4 + no]);
        splitw(d_U2p,   (size_t)n * (2 * KP_G), KP_G, k, U2[k * G4 + no]);
    }
    for (int n = tid; n < G4; n += nth) {
        int no = gperm(n);
        d_b1p[n] = b1[no];
        d_b2p[n] = b2[no];
    }

    for (int idx = tid; idx < R1 * (KP_MEL - NBINS); idx += nth) {
        int r = idx / (KP_MEL - NBINS), k = NBINS + idx % (KP_MEL - NBINS);
        d_A2mel[(size_t)r * (2 * KP_MEL) + k] = __float2bfloat16(0.f);
        d_A2mel[(size_t)r * (2 * KP_MEL) + KP_MEL + k] = __float2bfloat16(0.f);
    }
}

// ---------------- window -> fp16 A ----------------
__global__ void k_window(const float* __restrict__ x) {
    int f = blockIdx.x, b = blockIdx.y, tid = threadIdx.x;
    size_t row = (size_t)(b * NFRAMES + f) * KP_DFT;
    for (int k = tid; k < KP_DFT; k += blockDim.x) {
        float v = 0.f;
        if (k < NFFT) {
            int p = f * HOP + k - 200;
            int i = (p < 0) ? -p : ((p >= TLEN) ? (2 * TLEN - 2 - p) : p);
            v = x[(size_t)b * TLEN + i] * d_hann[k];
        }
        d_A1dft[row + k] = __float2half(v);
    }
}

// ---------------- single-term fp16 DFT GEMM -> power split pack ----------------
__global__ void __launch_bounds__(256, 3)
k_gemm_dft16(const __half* __restrict__ A1, const __half* __restrict__ B1,
             __nv_bfloat16* __restrict__ outP) {
    extern __shared__ __half smh[];
    __half* AHs = smh;              // [2][128][40]
    __half* BHs = smh + DOFF_B;     // [2][64][40]

    int tid = threadIdx.x, lane = tid & 31, w = tid >> 5;
    int wm = w >> 1, wn = w & 1;
    int m0 = blockIdx.y * 128, n0 = blockIdx.x * 64;
    int g = lane >> 2, t = lane & 3;
    int la_row = tid >> 2, la_kc = (tid & 3) << 3;

    const __half* Abase = A1 + (size_t)m0 * KP_DFT;
    const __half* Bbase = B1 + (size_t)n0 * KP_DFT;

    float acc[2][4][4];
    #pragma unroll
    for (int i = 0; i < 2; i++)
        #pragma unroll
        for (int j = 0; j < 4; j++)
            #pragma unroll
            for (int q = 0; q < 4; q++) acc[i][j][q] = 0.f;

    auto load_chunk = [&](int buf, int kk) {
        int bo = buf * 5120, bo2 = buf * 2560;
        cpa16(smaddr(AHs + bo + la_row * 40 + la_kc),        Abase + (size_t)la_row * KP_DFT + kk + la_kc);
        cpa16(smaddr(AHs + bo + (la_row + 64) * 40 + la_kc), Abase + (size_t)(la_row + 64) * KP_DFT + kk + la_kc);
        cpa16(smaddr(BHs + bo2 + la_row * 40 + la_kc),       Bbase + (size_t)la_row * KP_DFT + kk + la_kc);
        cpa_commit();
    };

    load_chunk(0, 0);

    #pragma unroll 1
    for (int kk = 0; kk < KP_DFT; kk += 32) {
        int buf = (kk >> 5) & 1;
        asm volatile("cp.async.wait_group 0;");
        __syncthreads();
        if (kk + 32 < KP_DFT) load_chunk(buf ^ 1, kk + 32);

        int bo = buf * 5120, bo2 = buf * 2560;
        #pragma unroll
        for (int ko = 0; ko < 32; ko += 16) {
            unsigned ahf[2][4], bhf[4][2];
            #pragma unroll
            for (int i = 0; i < 2; i++) {
                int r = wm * 32 + i * 16;
                ahf[i][0] = *(const unsigned*)&AHs[bo + (r + g) * 40 + ko + 2 * t];
                ahf[i][1] = *(const unsigned*)&AHs[bo + (r + g + 8) * 40 + ko + 2 * t];
                ahf[i][2] = *(const unsigned*)&AHs[bo + (r + g) * 40 + ko + 2 * t + 8];
                ahf[i][3] = *(const unsigned*)&AHs[bo + (r + g + 8) * 40 + ko + 2 * t + 8];
            }
            #pragma unroll
            for (int j = 0; j < 4; j++) {
                int bn = wn * 32 + j * 8 + g;
                bhf[j][0] = *(const unsigned*)&BHs[bo2 + bn * 40 + ko + 2 * t];
                bhf[j][1] = *(const unsigned*)&BHs[bo2 + bn * 40 + ko + 2 * t + 8];
            }
            #pragma unroll
            for (int i = 0; i < 2; i++)
                #pragma unroll
                for (int j = 0; j < 4; j++)
                    mma16816h(acc[i][j], ahf[i], bhf[j][0], bhf[j][1]);
        }
        __syncthreads();
    }

    // power epilogue: even col = cos part, odd col = sin part
    #pragma unroll
    for (int i = 0; i < 2; i++) {
        int r = m0 + wm * 32 + i * 16 + g;
        #pragma unroll
        for (int j = 0; j < 4; j++) {
            int c = n0 + wn * 32 + j * 8 + 2 * t;
            int k = c >> 1;
            if (k < NBINS) {
                float p0 = acc[i][j][0] * acc[i][j][0] + acc[i][j][1] * acc[i][j][1];
                float p1 = acc[i][j][2] * acc[i][j][2] + acc[i][j][3] * acc[i][j][3];
                splitw(outP, (size_t)r * (2 * KP_MEL), KP_MEL, k, p0);
                splitw(outP, (size_t)(r + 8) * (2 * KP_MEL), KP_MEL, k, p1);
            }
        }
    }
}

// ---------------- single-pass split-bf16 tensor GEMM (R9/R10 proven) ----------------
__global__ void __launch_bounds__(256, 3)
k_gemm(const __nv_bfloat16* __restrict__ A2, const __nv_bfloat16* __restrict__ B2,
       int Kp, const float* __restrict__ bias, int mode,
       float* __restrict__ outF, int ldc, int Nreal,
       __nv_bfloat16* __restrict__ outP, int KpOut) {
    extern __shared__ __nv_bfloat16 smd[];
    __nv_bfloat16* AHs = smd;
    __nv_bfloat16* ALs = smd + OFF_AL;
    __nv_bfloat16* BHs = smd + OFF_BH;
    __nv_bfloat16* BLs = smd + OFF_BL;

    int tid = threadIdx.x, lane = tid & 31, w = tid >> 5;
    int wm = w >> 1, wn = w & 1;
    int m0 = blockIdx.y * 128, n0 = blockIdx.x * 64;
    int g = lane >> 2, t = lane & 3;
    int strideA = 2 * Kp;
    int la_row = tid >> 2, la_kc = (tid & 3) << 3;

    const __nv_bfloat16* Abase = A2 + (size_t)m0 * strideA;
    const __nv_bfloat16* Bbase = B2 + (size_t)n0 * strideA;

    float acc[2][4][4];
    #pragma unroll
    for (int i = 0; i < 2; i++)
        #pragma unroll
        for (int j = 0; j < 4; j++)
            #pragma unroll
            for (int q = 0; q < 4; q++) acc[i][j][q] = 0.f;

    auto load_chunk = [&](int buf, int kk) {
        int bo = buf * 5120, bo2 = buf * 2560;
        cpa16(smaddr(AHs + bo + la_row * 40 + la_kc),        Abase + (size_t)la_row * strideA + kk + la_kc);
        cpa16(smaddr(AHs + bo + (la_row + 64) * 40 + la_kc), Abase + (size_t)(la_row + 64) * strideA + kk + la_kc);
        cpa16(smaddr(ALs + bo + la_row * 40 + la_kc),        Abase + (size_t)la_row * strideA + Kp + kk + la_kc);
        cpa16(smaddr(ALs + bo + (la_row + 64) * 40 + la_kc), Abase + (size_t)(la_row + 64) * strideA + Kp + kk + la_kc);
        cpa16(smaddr(BHs + bo2 + la_row * 40 + la_kc),       Bbase + (size_t)la_row * strideA + kk + la_kc);
        cpa16(smaddr(BLs + bo2 + la_row * 40 + la_kc),       Bbase + (size_t)la_row * strideA + Kp + kk + la_kc);
        cpa_commit();
    };

    load_chunk(0, 0);

    #pragma unroll 1
    for (int kk = 0; kk < Kp; kk += 32) {
        int buf = (kk >> 5) & 1;
        asm volatile("cp.async.wait_group 0;");
        __syncthreads();
        if (kk + 32 < Kp) load_chunk(buf ^ 1, kk + 32);

        int bo = buf * 5120, bo2 = buf * 2560;
        #pragma unroll
        for (int ko = 0; ko < 32; ko += 16) {
            unsigned ahf[2][4], alf[2][4], bhf[4][2], blf[4][2];
            #pragma unroll
            for (int i = 0; i < 2; i++) {
                int r = wm * 32 + i * 16;
                ahf[i][0] = *(const unsigned*)&AHs[bo + (r + g) * 40 + ko + 2 * t];
                ahf[i][1] = *(const unsigned*)&AHs[bo + (r + g + 8) * 40 + ko + 2 * t];
                ahf[i][2] = *(const unsigned*)&AHs[bo + (r + g) * 40 + ko + 2 * t + 8];
                ahf[i][3] = *(const unsigned*)&AHs[bo + (r + g + 8) * 40 + ko + 2 * t + 8];
                alf[i][0] = *(const unsigned*)&ALs[bo + (r + g) * 40 + ko + 2 * t];
                alf[i][1] = *(const unsigned*)&ALs[bo + (r + g + 8) * 40 + ko + 2 * t];
                alf[i][2] = *(const unsigned*)&ALs[bo + (r + g) * 40 + ko + 2 * t + 8];
                alf[i][3] = *(const unsigned*)&ALs[bo + (r + g + 8) * 40 + ko + 2 * t + 8];
            }
            #pragma unroll
            for (int j = 0; j < 4; j++) {
                int bn = wn * 32 + j * 8 + g;
                bhf[j][0] = *(const unsigned*)&BHs[bo2 + bn * 40 + ko + 2 * t];
                bhf[j][1] = *(const unsigned*)&BHs[bo2 + bn * 40 + ko + 2 * t + 8];
                blf[j][0] = *(const unsigned*)&BLs[bo2 + bn * 40 + ko + 2 * t];
                blf[j][1] = *(const unsigned*)&BLs[bo2 + bn * 40 + ko + 2 * t + 8];
            }
            #pragma unroll
            for (int i = 0; i < 2; i++)
                #pragma unroll
                for (int j = 0; j < 4; j++) {
                    mma16816(acc[i][j], ahf[i], bhf[j][0], bhf[j][1]);
                    mma16816(acc[i][j], ahf[i], blf[j][0], blf[j][1]);
                    mma16816(acc[i][j], alf[i], bhf[j][0], bhf[j][1]);
                }
        }
        __syncthreads();
    }

    #pragma unroll
    for (int i = 0; i < 2; i++) {
        int r = m0 + wm * 32 + i * 16 + g;
        #pragma unroll
        for (int j = 0; j < 4; j++) {
            int c = n0 + wn * 32 + j * 8 + 2 * t;
            float v00 = acc[i][j][0], v01 = acc[i][j][1];
            float v10 = acc[i][j][2], v11 = acc[i][j][3];
            if (mode == 0) {
                float b0 = bias ? bias[c] : 0.f, b1 = bias ? bias[c + 1] : 0.f;
                outF[(size_t)r * ldc + c]           = v00 + b0;
                outF[(size_t)r * ldc + c + 1]       = v01 + b1;
                outF[(size_t)(r + 8) * ldc + c]     = v10 + b0;
                outF[(size_t)(r + 8) * ldc + c + 1] = v11 + b1;
            } else {
                float b0 = bias ? bias[c] : 0.f, b1 = bias ? bias[c + 1] : 0.f;
                splitw(outP, (size_t)r * (2 * KpOut), KpOut, c, v00 + b0);
                splitw(outP, (size_t)r * (2 * KpOut), KpOut, c + 1, v01 + b1);
                splitw(outP, (size_t)(r + 8) * (2 * KpOut), KpOut, c, v10 + b0);
                splitw(outP, (size_t)(r + 8) * (2 * KpOut), KpOut, c + 1, v11 + b1);
            }
        }
    }
}

// ---------------- conv GEMM (R5 proven): shifted rows, 9 segments ----------------
__global__ void __launch_bounds__(256, 3)
k_gemm_conv(const __nv_bfloat16* __restrict__ Msp, const __nv_bfloat16* __restrict__ B2,
            const float* __restrict__ bias, __nv_bfloat16* __restrict__ outP) {
    __shared__ __nv_bfloat16 As[2][128][40];
    __shared__ __nv_bfloat16 Bs[2][64][40];
    int tid = threadIdx.x, lane = tid & 31, w = tid >> 5;
    int wm = w >> 1, wn = w & 1;
    int m0 = blockIdx.y * 128, n0 = blockIdx.x * 64;
    int g = lane >> 2, t = lane & 3;
    int la_row = tid >> 2, la_kc = (tid & 3) << 3;

    int gm0 = m0 + la_row, gm1 = m0 + la_row + 64;
    int sr0 = gm0 + 2 * (gm0 / TSTEPS);
    int sr1 = gm1 + 2 * (gm1 / TSTEPS);

    float acc[2][4][4];
    #pragma unroll
    for (int i = 0; i < 2; i++)
        #pragma unroll
        for (int j = 0; j < 4; j++)
            #pragma unroll
            for (int q = 0; q < 4; q++) acc[i][j][q] = 0.f;

    #pragma unroll 1
    for (int s = 0; s < 9; s++) {
        int split = s / 3, shift = s % 3;
        int aoff = (split == 2) ? 128 : 0;
        int boff = ((split == 1) ? KCONV : 0) + shift * 128;
        const __nv_bfloat16* A0 = Msp + (size_t)(sr0 + shift) * 256 + aoff;
        const __nv_bfloat16* A1 = Msp + (size_t)(sr1 + shift) * 256 + aoff;
        const __nv_bfloat16* Bb = B2 + (size_t)n0 * (2 * KCONV) + boff;

        cpa16(smaddr(&As[0][la_row][la_kc]),      A0 + la_kc);
        cpa16(smaddr(&As[0][la_row + 64][la_kc]), A1 + la_kc);
        cpa16(smaddr(&Bs[0][la_row][la_kc]),      Bb + (size_t)la_row * (2 * KCONV) + la_kc);
        cpa_commit();
        #pragma unroll 1
        for (int kk = 0; kk < 128; kk += 32) {
            int buf = (kk >> 5) & 1;
            asm volatile("cp.async.wait_group 0;");
            __syncthreads();
            if (kk + 32 < 128) {
                int nb = buf ^ 1, kn = kk + 32;
                cpa16(smaddr(&As[nb][la_row][la_kc]),      A0 + kn + la_kc);
                cpa16(smaddr(&As[nb][la_row + 64][la_kc]), A1 + kn + la_kc);
                cpa16(smaddr(&Bs[nb][la_row][la_kc]),      Bb + (size_t)la_row * (2 * KCONV) + kn + la_kc);
                cpa_commit();
            }
            #pragma unroll
            for (int ko = 0; ko < 32; ko += 16) {
                unsigned a[2][4], bfr[4][2];
                #pragma unroll
                for (int i = 0; i < 2; i++) {
                    int r = wm * 32 + i * 16;
                    a[i][0] = *(const unsigned*)&As[buf][r + g][ko + 2 * t];
                    a[i][1] = *(const unsigned*)&As[buf][r + g + 8][ko + 2 * t];
                    a[i][2] = *(const unsigned*)&As[buf][r + g][ko + 2 * t + 8];
                    a[i][3] = *(const unsigned*)&As[buf][r + g + 8][ko + 2 * t + 8];
                }
                #pragma unroll
                for (int j = 0; j < 4; j++) {
                    int bn = wn * 32 + j * 8 + g;
                    bfr[j][0] = *(const unsigned*)&Bs[buf][bn][ko + 2 * t];
                    bfr[j][1] = *(const unsigned*)&Bs[buf][bn][ko + 2 * t + 8];
                }
                #pragma unroll
                for (int i = 0; i < 2; i++)
                    #pragma unroll
                    for (int j = 0; j < 4; j++)
                        mma16816(acc[i][j], a[i], bfr[j][0], bfr[j][1]);
            }
            __syncthreads();
        }
    }

    #pragma unroll
    for (int i = 0; i < 2; i++) {
        int r = m0 + wm * 32 + i * 16 + g;
        #pragma unroll
        for (int j = 0; j < 4; j++) {
            int c = n0 + wn * 32 + j * 8 + 2 * t;
            float b0 = bias[c], b1 = bias[c + 1];
            splitw(outP, (size_t)r * 256, 128, c,     acc[i][j][0] + b0);
            splitw(outP, (size_t)r * 256, 128, c + 1, acc[i][j][1] + b1);
            splitw(outP, (size_t)(r + 8) * 256, 128, c,     acc[i][j][2] + b0);
            splitw(outP, (size_t)(r + 8) * 256, 128, c + 1, acc[i][j][3] + b1);
        }
    }
}

// ---------------- tensor-core LSTM v3 + coalesced h-split store ----------------
__global__ void __launch_bounds__(256)
k_lstm_mma(const float* __restrict__ gx, const __nv_bfloat16* __restrict__ Up,
           __nv_bfloat16* __restrict__ hsplit, float* __restrict__ hmean) {
    extern __shared__ __nv_bfloat16 sm[];
    __nv_bfloat16* Uh  = sm;
    __nv_bfloat16* Ulw = sm + SM_UH;
    __nv_bfloat16* Hsp = sm + SM_UH + SM_UL;

    int tid = threadIdx.x, lane = tid & 31, w = tid >> 5;
    int g = lane >> 2, tq = lane & 3;
    int b0 = blockIdx.x * 16;
    int wbase = w * 64;
    __nv_bfloat16* myUl = Ulw + w * SM_ULW;

    for (int idx = tid; idx < 512 * 16; idx += 256) {
        int n = idx >> 4, j = idx & 15;
        *(uint4*)(Uh + n * UH_STRIDE + j * 8) = *(const uint4*)(Up + (size_t)n * 256 + j * 8);
    }
    for (int idx = tid; idx < SM_H; idx += 256) Hsp[idx] = __float2bfloat16(0.f);

    float cst[8], hsum[8];
    #pragma unroll
    for (int i = 0; i < 8; i++) { cst[i] = 0.f; hsum[i] = 0.f; }

    for (int t = 0; t < TSTEPS; t++) {
        float acc[8][4];
        {
            size_t rlo = ((size_t)(b0 + g) * TSTEPS + t) * G4 + wbase + 2 * tq;
            size_t rhi = ((size_t)(b0 + g + 8) * TSTEPS + t) * G4 + wbase + 2 * tq;
            #pragma unroll
            for (int a = 0; a < 8; a++) {
                float2 v0 = *(const float2*)&gx[rlo + a * 8];
                float2 v1 = *(const float2*)&gx[rhi + a * 8];
                acc[a][0] = v0.x; acc[a][1] = v0.y;
                acc[a][2] = v1.x; acc[a][3] = v1.y;
            }
        }
        __syncthreads();

        #pragma unroll
        for (int c0 = 0; c0 < 2; c0++) {
            __nv_bfloat16* buf = myUl + (c0 % 3) * 64 * ULW_STRIDE;
            #pragma unroll
            for (int i = 0; i < 4; i++) {
                int u = lane + 32 * i, n1 = u >> 1, hf = u & 1;
                cpa16(smaddr(buf + n1 * ULW_STRIDE + hf * 8),
                      Up + (size_t)(wbase + n1) * 256 + 128 + c0 * 16 + hf * 8);
            }
            cpa_commit();
        }

        #pragma unroll 1
        for (int c = 0; c < 8; c++) {
            if (c < 7) asm volatile("cp.async.wait_group 1;");
            else       asm volatile("cp.async.wait_group 0;");
            __syncwarp();
            if (c + 2 < 8) {
                __nv_bfloat16* nbuf = myUl + ((c + 2) % 3) * 64 * ULW_STRIDE;
                #pragma unroll
                for (int i = 0; i < 4; i++) {
                    int u = lane + 32 * i, n1 = u >> 1, hf = u & 1;
                    cpa16(smaddr(nbuf + n1 * ULW_STRIDE + hf * 8),
                          Up + (size_t)(wbase + n1) * 256 + 128 + (c + 2) * 16 + hf * 8);
                }
                cpa_commit();
            }
            int ko = c * 16 + 2 * tq;
            unsigned ah[4], al[4];
            ah[0] = *(const unsigned*)&Hsp[g * H_STRIDE + ko];
            ah[1] = *(const unsigned*)&Hsp[(g + 8) * H_STRIDE + ko];
            ah[2] = *(const unsigned*)&Hsp[g * H_STRIDE + ko + 8];
            ah[3] = *(const unsigned*)&Hsp[(g + 8) * H_STRIDE + ko + 8];
            al[0] = *(const unsigned*)&Hsp[g * H_STRIDE + 128 + ko];
            al[1] = *(const unsigned*)&Hsp[(g + 8) * H_STRIDE + 128 + ko];
            al[2] = *(const unsigned*)&Hsp[g * H_STRIDE + 128 + ko + 8];
            al[3] = *(const unsigned*)&Hsp[(g + 8) * H_STRIDE + 128 + ko + 8];
            const __nv_bfloat16* ulB = myUl + (c % 3) * 64 * ULW_STRIDE;
            #pragma unroll
            for (int bn = 0; bn < 8; bn++) {
                int n = wbase + bn * 8 + g;
                const __nv_bfloat16* bph = Uh + n * UH_STRIDE + ko;
                unsigned h0 = *(const unsigned*)bph;
                unsigned h1 = *(const unsigned*)(bph + 8);
                mma16816(acc[bn], ah, h0, h1);
                mma16816(acc[bn], al, h0, h1);
                const __nv_bfloat16* bpl = ulB + (bn * 8 + g) * ULW_STRIDE + 2 * tq;
                unsigned l0 = *(const unsigned*)bpl;
                unsigned l1 = *(const unsigned*)(bpl + 8);
                mma16816(acc[bn], ah, l0, l1);
            }
        }
        __syncthreads();

        #pragma unroll
        for (int uh = 0; uh < 2; uh++)
            #pragma unroll
            for (int par = 0; par < 2; par++)
                #pragma unroll
                for (int q2 = 0; q2 < 2; q2++) {
                    int u = uh * 8 + 2 * tq + par;
                    int r = g + 8 * q2;
                    int qq = q2 * 2 + par;
                    int ci = uh * 4 + par * 2 + q2;
                    float gi = acc[0 + uh][qq];
                    float gf = acc[2 + uh][qq];
                    float gg = acc[4 + uh][qq];
                    float go = acc[6 + uh][qq];
                    float c = sigf(gf) * cst[ci] + sigf(gi) * tanhf_acc(gg);
                    float h = sigf(go) * tanhf_acc(c);
                    cst[ci] = c;
                    int ug = w * 16 + u;
                    __nv_bfloat16 hh = __float2bfloat16(h);
                    __nv_bfloat16 hl = __float2bfloat16(h - __bfloat162float(hh));
                    Hsp[r * H_STRIDE + ug] = hh;
                    Hsp[r * H_STRIDE + 128 + ug] = hl;
                    hsum[ci] += h;
                }

        if (hsplit) {
            __syncthreads();
            #pragma unroll
            for (int i = tid; i < 512; i += 256) {
                int r = i >> 5, c16 = i & 31;
                size_t row2 = ((size_t)(b0 + r) * TSTEPS + t) * 256;
                *(uint4*)(hsplit + row2 + c16 * 8) =
                    *(const uint4*)(Hsp + r * H_STRIDE + c16 * 8);
            }
        }
    }

    if (hmean) {
        #pragma unroll
        for (int uh = 0; uh < 2; uh++)
            #pragma unroll
            for (int par = 0; par < 2; par++)
                #pragma unroll
                for (int q2 = 0; q2 < 2; q2++) {
                    int u = uh * 8 + 2 * tq + par;
                    int r = g + 8 * q2;
                    int ci = uh * 4 + par * 2 + q2;
                    hmean[(size_t)(b0 + r) * 128 + w * 16 + u] = hsum[ci] * (1.0f / (float)TSTEPS);
                }
    }
}

// ---------------- small fp32 SGEMM for fc/proj ----------------
__global__ void k_sgemm(const float* __restrict__ A, const float* __restrict__ Bm,
                        float* __restrict__ C, const float* __restrict__ bias,
                        int M, int N, int K) {
    __shared__ float As[8][68];
    __shared__ float Bs[8][64];
    int tid = threadIdx.x;
    int m0 = blockIdx.y * 64, n0 = blockIdx.x * 64;
    int tm = tid & 15, tn = tid >> 4;
    float acc[4][8];
    #pragma unroll
    for (int i = 0; i < 4; i++)
        #pragma unroll
        for (int j = 0; j < 8; j++) acc[i][j] = 0.f;
    for (int kk = 0; kk < K; kk += 8) {
        #pragma unroll
        for (int i = 0; i < 4; i++) {
            int l = tid + i * 128, m = l >> 3, k = l & 7;
            int gm = m0 + m, gk = kk + k;
            As[k][m] = (gm < M && gk < K) ? A[(size_t)gm * K + gk] : 0.f;
        }
        #pragma unroll
        for (int i = 0; i < 4; i++) {
            int l = tid + i * 128, k = l >> 6, n = l & 63;
            int gk = kk + k, gn = n0 + n;
            Bs[k][n] = (gk < K && gn < N) ? Bm[(size_t)gk * N + gn] : 0.f;
        }
        __syncthreads();
        #pragma unroll
        for (int k = 0; k < 8; k++) {
            float a[4], bv[8];
            #pragma unroll
            for (int i = 0; i < 4; i++) a[i] = As[k][tm * 4 + i];
            #pragma unroll
            for (int j = 0; j < 8; j++) bv[j] = Bs[k][tn * 8 + j];
            #pragma unroll
            for (int i = 0; i < 4; i++)
                #pragma unroll
                for (int j = 0; j < 8; j++) acc[i][j] += a[i] * bv[j];
        }
        __syncthreads();
    }
    #pragma unroll
    for (int i = 0; i < 4; i++) {
        int gm = m0 + tm * 4 + i;
        if (gm >= M) continue;
        #pragma unroll
        for (int j = 0; j < 8; j++) {
            int gn = n0 + tn * 8 + j;
            if (gn < N) C[(size_t)gm * N + gn] = acc[i][j] + (bias ? bias[gn] : 0.f);
        }
    }
}

// ---------------- launch ----------------
extern "C" void kernel_launch(void* const* d_in, const int* in_sizes, int n_in,
                              void* d_out, int out_size) {
    const float* x      = (const float*)d_in[0];
    const float* conv_w = (const float*)d_in[1];
    const float* conv_b = (const float*)d_in[2];
    const float* W1     = (const float*)d_in[3];
    const float* U1     = (const float*)d_in[4];
    const float* b1     = (const float*)d_in[5];
    const float* W2     = (const float*)d_in[6];
    const float* U2     = (const float*)d_in[7];
    const float* b2     = (const float*)d_in[8];
    const float* fc1_w  = (const float*)d_in[9];
    const float* fc1_b  = (const float*)d_in[10];
    const float* proj_w = (const float*)d_in[11];
    const float* proj_b = (const float*)d_in[12];
    float* out = (float*)d_out;

    __half *pA1dft, *pB1dft;
    __nv_bfloat16 *pA2mel, *pB2mel, *pMelsp, *pB2conv, *pA2g;
    __nv_bfloat16 *pB2W1p, *pB2W2p, *pU1p, *pU2p, *pH1s;
    float *pG, *pHmean, *pHfc, *pB1p, *pB2p;
    cudaGetSymbolAddress((void**)&pA1dft,  d_A1dft);
    cudaGetSymbolAddress((void**)&pB1dft,  d_B1dft);
    cudaGetSymbolAddress((void**)&pA2mel,  d_A2mel);
    cudaGetSymbolAddress((void**)&pB2mel,  d_B2mel);
    cudaGetSymbolAddress((void**)&pMelsp,  d_melsp);
    cudaGetSymbolAddress((void**)&pB2conv, d_B2conv);
    cudaGetSymbolAddress((void**)&pA2g,    d_A2g);
    cudaGetSymbolAddress((void**)&pB2W1p,  d_B2W1p);
    cudaGetSymbolAddress((void**)&pB2W2p,  d_B2W2p);
    cudaGetSymbolAddress((void**)&pU1p,    d_U1p);
    cudaGetSymbolAddress((void**)&pU2p,    d_U2p);
    cudaGetSymbolAddress((void**)&pH1s,    d_h1s);
    cudaGetSymbolAddress((void**)&pG,      d_g);
    cudaGetSymbolAddress((void**)&pHmean,  d_hmean);
    cudaGetSymbolAddress((void**)&pHfc,    d_hfc);
    cudaGetSymbolAddress((void**)&pB1p,    d_b1p);
    cudaGetSymbolAddress((void**)&pB2p,    d_b2p);

    cudaFuncSetAttribute(k_lstm_mma,   cudaFuncAttributeMaxDynamicSharedMemorySize, LSTM_SMEM_BYTES);
    cudaFuncSetAttribute(k_gemm,       cudaFuncAttributeMaxDynamicSharedMemorySize, GEMM_SMEM_BYTES);
    cudaFuncSetAttribute(k_gemm_dft16, cudaFuncAttributeMaxDynamicSharedMemorySize, DFT16_SMEM_BYTES);

    k_precompute<<<128, 256>>>(conv_w, W1, W2, U1, U2, b1, b2);
    k_window<<<dim3(NFRAMES, BATCH), 256>>>(x);

    // DFT (single-term fp16) -> power split-pack into A2mel
    k_gemm_dft16<<<dim3(NP_DFT / 64, R1 / 128), 256, DFT16_SMEM_BYTES>>>(
        pA1dft, pB1dft, pA2mel);
    // mel -> split pack
    k_gemm<<<dim3(2, R1 / 128), 256, GEMM_SMEM_BYTES>>>(
        pA2mel, pB2mel, KP_MEL, nullptr, 2, nullptr, 0, NMELS, pMelsp, 128);
    // conv (shifted-row) -> split pack into A2g
    k_gemm_conv<<<dim3(2, R2 / 128), 256>>>(pMelsp, pB2conv, conv_b, pA2g);
    // g1 (permuted gates)
    k_gemm<<<dim3(8, R2 / 128), 256, GEMM_SMEM_BYTES>>>(
        pA2g, pB2W1p, KP_G, pB1p, 0, pG, G4, G4, nullptr, 0);
    k_lstm_mma<<<BATCH / 16, 256, LSTM_SMEM_BYTES>>>(pG, pU1p, pH1s, nullptr);
    // g2 (permuted gates)
    k_gemm<<<dim3(8, R2 / 128), 256, GEMM_SMEM_BYTES>>>(
        pH1s, pB2W2p, KP_G, pB2p, 0, pG, G4, G4, nullptr, 0);
    k_lstm_mma<<<BATCH / 16, 256, LSTM_SMEM_BYTES>>>(pG, pU2p, nullptr, pHmean);

    k_sgemm<<<dim3(2, BATCH / 64), 128>>>(pHmean, fc1_w, pHfc, fc1_b, BATCH, 128, 128);
    k_sgemm<<<dim3(1, BATCH / 64), 128>>>(pHfc, proj_w, out, proj_b, BATCH, 35, 128);
}

// round 13
// speedup vs baseline: 1.6752x; 1.0556x over previous
#include <cuda_runtime.h>
#include <cuda_bf16.h>
#include <cuda_fp16.h>
#include <math.h>

// ---------------- problem dims ----------------
#define BATCH   1024
#define TLEN    16000
#define NFFT    400
#define HOP     200
#define NBINS   201
#define NMELS   128
#define NFRAMES 81
#define TSTEPS  79
#define HID     128
#define G4      512
#define R1      (BATCH*NFRAMES)   // 82944
#define R2      (BATCH*TSTEPS)    // 80896

#define KP_DFT  416
#define KP_MEL  224
#define KP_G    128
#define NP_DFT  448
#define KCONV   384

// bf16 split k_gemm dynamic smem (bf16 elems)
#define GEMM_SMEM_ELEMS (2*128*40*2 + 2*64*40*2)   // 30720
#define GEMM_SMEM_BYTES (GEMM_SMEM_ELEMS*2)        // 61440
#define OFF_AL  10240
#define OFF_BH  20480
#define OFF_BL  25600

// fp16 single-term GEMM smem (half elems): Ah[2][128][40] + Bh[2][64][40]
#define F16_SMEM_ELEMS (2*128*40 + 2*64*40)        // 15360
#define F16_SMEM_BYTES (F16_SMEM_ELEMS*2)          // 30720
#define DOFF_B  10240

// LSTM smem (bf16 elements)
#define UH_STRIDE 136
#define ULW_STRIDE 24
#define H_STRIDE  264
#define SM_UH   (512*UH_STRIDE)
#define SM_ULW  (3*64*ULW_STRIDE)
#define SM_UL   (8*SM_ULW)
#define SM_H    (16*H_STRIDE)
#define LSTM_SMEM_BYTES ((SM_UH + SM_UL + SM_H)*2)  // 221440

// ---------------- scratch ----------------
__device__ float          d_hann[NFFT];
__device__ __half         d_A1dft[(size_t)R1 * KP_DFT];
__device__ __half         d_B1dft[(size_t)NP_DFT * KP_DFT];
__device__ __nv_bfloat16  d_A2mel[(size_t)R1 * 2 * KP_MEL];
__device__ __nv_bfloat16  d_B2mel[(size_t)128 * 2 * KP_MEL];
__device__ __nv_bfloat16  d_melsp[(size_t)R1 * 256];
__device__ __nv_bfloat16  d_B2conv[(size_t)128 * 2 * KCONV];
__device__ __half         d_A1g[(size_t)R2 * KP_G];       // conv out, fp16 single
__device__ __half         d_W1h[(size_t)G4 * KP_G];       // gate-permuted W, fp16
__device__ __half         d_W2h[(size_t)G4 * KP_G];
__device__ __nv_bfloat16  d_U1p[(size_t)G4 * 2 * KP_G];
__device__ __nv_bfloat16  d_U2p[(size_t)G4 * 2 * KP_G];
__device__ float          d_b1p[G4];
__device__ float          d_b2p[G4];
__device__ float          d_g[(size_t)R2 * G4];
__device__ __half         d_h1h[(size_t)R2 * KP_G];       // layer-1 h, fp16 single
__device__ float          d_hmean[BATCH * 128];
__device__ float          d_hfc[BATCH * 128];

// ---------------- helpers ----------------
__device__ __forceinline__ float sigf(float x) { return 1.0f / (1.0f + __expf(-x)); }
__device__ __forceinline__ float tanhf_acc(float x) {
    float t = __expf(-2.0f * fabsf(x));
    float r = (1.0f - t) / (1.0f + t);
    return copysignf(r, x);
}
__device__ __forceinline__ void splitw(__nv_bfloat16* P, size_t base, int KpOut, int k, float v) {
    __nv_bfloat16 h = __float2bfloat16(v);
    P[base + k] = h;
    P[base + KpOut + k] = __float2bfloat16(v - __bfloat162float(h));
}
__device__ __forceinline__ unsigned smaddr(const void* p) {
    return (unsigned)__cvta_generic_to_shared(p);
}
__device__ __forceinline__ void cpa16(unsigned dst, const void* src) {
    asm volatile("cp.async.cg.shared.global [%0], [%1], 16;" :: "r"(dst), "l"(src));
}
__device__ __forceinline__ void cpa_commit() { asm volatile("cp.async.commit_group;"); }
__device__ __forceinline__ void mma16816(float* c, const unsigned* a, unsigned b0, unsigned b1) {
    asm volatile(
        "mma.sync.aligned.m16n8k16.row.col.f32.bf16.bf16.f32 "
        "{%0,%1,%2,%3}, {%4,%5,%6,%7}, {%8,%9}, {%0,%1,%2,%3};"
        : "+f"(c[0]), "+f"(c[1]), "+f"(c[2]), "+f"(c[3])
        : "r"(a[0]), "r"(a[1]), "r"(a[2]), "r"(a[3]), "r"(b0), "r"(b1));
}
__device__ __forceinline__ void mma16816h(float* c, const unsigned* a, unsigned b0, unsigned b1) {
    asm volatile(
        "mma.sync.aligned.m16n8k16.row.col.f32.f16.f16.f32 "
        "{%0,%1,%2,%3}, {%4,%5,%6,%7}, {%8,%9}, {%0,%1,%2,%3};"
        : "+f"(c[0]), "+f"(c[1]), "+f"(c[2]), "+f"(c[3])
        : "r"(a[0]), "r"(a[1]), "r"(a[2]), "r"(a[3]), "r"(b0), "r"(b1));
}
__device__ __forceinline__ int gperm(int n) {
    int w = n >> 6, s = n & 63, gate = s >> 4, u = s & 15;
    return gate * 128 + w * 16 + u;
}

// ---------------- precompute (fp32 fast math) ----------------
__global__ void k_precompute(const float* __restrict__ conv_w,
                             const float* __restrict__ W1, const float* __restrict__ W2,
                             const float* __restrict__ U1, const float* __restrict__ U2,
                             const float* __restrict__ b1, const float* __restrict__ b2) {
    int tid = blockIdx.x * blockDim.x + threadIdx.x;
    int nth = gridDim.x * blockDim.x;

    for (int k = tid; k < NFFT; k += nth)
        d_hann[k] = 0.5f - 0.5f * cospif((float)k / 200.0f);

    for (int idx = tid; idx < NP_DFT * KP_DFT; idx += nth) {
        int n = idx / KP_DFT, k = idx % KP_DFT;
        float v = 0.f;
        if (n < 2 * NBINS && k < NFFT) {
            int m = n >> 1;
            int ph = (m * k) % 400;
            float s, c;
            sincospif((float)ph / 200.0f, &s, &c);
            v = (n & 1) ? s : c;
        }
        d_B1dft[(size_t)n * KP_DFT + k] = __float2half(v);
    }

    const float mel_max = 2595.0f * log10f(1.0f + 8000.0f / 700.0f);
    for (int idx = tid; idx < 128 * KP_MEL; idx += nth) {
        int m = idx / KP_MEL, k = idx % KP_MEL;
        float v = 0.f;
        if (k < NBINS) {
            float freq = 40.0f * (float)k;
            float f0 = 700.0f * (exp10f((mel_max * (float)(m    ) / 129.0f) / 2595.0f) - 1.0f);
            float f1 = 700.0f * (exp10f((mel_max * (float)(m + 1) / 129.0f) / 2595.0f) - 1.0f);
            float f2 = 700.0f * (exp10f((mel_max * (float)(m + 2) / 129.0f) / 2595.0f) - 1.0f);
            float dn = (freq - f0) / (f1 - f0);
            float up = (f2 - freq) / (f2 - f1);
            float t = fminf(dn, up);
            v = fmaxf(t, 0.0f);
        }
        splitw(d_B2mel, (size_t)m * (2 * KP_MEL), KP_MEL, k, v);
    }

    for (int idx = tid; idx < 128 * KCONV; idx += nth) {
        int o = idx / KCONV, q = idx % KCONV;
        int kk = q >> 7, i = q & 127;
        splitw(d_B2conv, (size_t)o * (2 * KCONV), KCONV, q, conv_w[o * 384 + i * 3 + kk]);
    }

    for (int idx = tid; idx < G4 * KP_G; idx += nth) {
        int n = idx / KP_G, k = idx % KP_G;
        int no = gperm(n);
        d_W1h[(size_t)n * KP_G + k] = __float2half(W1[k * G4 + no]);
        d_W2h[(size_t)n * KP_G + k] = __float2half(W2[k * G4 + no]);
        splitw(d_U1p, (size_t)n * (2 * KP_G), KP_G, k, U1[k * G4 + no]);
        splitw(d_U2p, (size_t)n * (2 * KP_G), KP_G, k, U2[k * G4 + no]);
    }
    for (int n = tid; n < G4; n += nth) {
        int no = gperm(n);
        d_b1p[n] = b1[no];
        d_b2p[n] = b2[no];
    }

    for (int idx = tid; idx < R1 * (KP_MEL - NBINS); idx += nth) {
        int r = idx / (KP_MEL - NBINS), k = NBINS + idx % (KP_MEL - NBINS);
        d_A2mel[(size_t)r * (2 * KP_MEL) + k] = __float2bfloat16(0.f);
        d_A2mel[(size_t)r * (2 * KP_MEL) + KP_MEL + k] = __float2bfloat16(0.f);
    }
}

// ---------------- window -> fp16 A ----------------
__global__ void k_window(const float* __restrict__ x) {
    int f = blockIdx.x, b = blockIdx.y, tid = threadIdx.x;
    size_t row = (size_t)(b * NFRAMES + f) * KP_DFT;
    for (int k = tid; k < KP_DFT; k += blockDim.x) {
        float v = 0.f;
        if (k < NFFT) {
            int p = f * HOP + k - 200;
            int i = (p < 0) ? -p : ((p >= TLEN) ? (2 * TLEN - 2 - p) : p);
            v = x[(size_t)b * TLEN + i] * d_hann[k];
        }
        d_A1dft[row + k] = __float2half(v);
    }
}

// ---------------- generic single-term fp16 GEMM ----------------
// mode 0: fp32 out + bias; mode 1: DFT power -> bf16 split pack into outP
__global__ void __launch_bounds__(256, 3)
k_gemm16(const __half* __restrict__ A1, const __half* __restrict__ B1,
         int Kp, const float* __restrict__ bias, int mode,
         float* __restrict__ outF, int ldc,
         __nv_bfloat16* __restrict__ outP) {
    extern __shared__ __half smh[];
    __half* AHs = smh;              // [2][128][40]
    __half* BHs = smh + DOFF_B;     // [2][64][40]

    int tid = threadIdx.x, lane = tid & 31, w = tid >> 5;
    int wm = w >> 1, wn = w & 1;
    int m0 = blockIdx.y * 128, n0 = blockIdx.x * 64;
    int g = lane >> 2, t = lane & 3;
    int la_row = tid >> 2, la_kc = (tid & 3) << 3;

    const __half* Abase = A1 + (size_t)m0 * Kp;
    const __half* Bbase = B1 + (size_t)n0 * Kp;

    float acc[2][4][4];
    #pragma unroll
    for (int i = 0; i < 2; i++)
        #pragma unroll
        for (int j = 0; j < 4; j++)
            #pragma unroll
            for (int q = 0; q < 4; q++) acc[i][j][q] = 0.f;

    auto load_chunk = [&](int buf, int kk) {
        int bo = buf * 5120, bo2 = buf * 2560;
        cpa16(smaddr(AHs + bo + la_row * 40 + la_kc),        Abase + (size_t)la_row * Kp + kk + la_kc);
        cpa16(smaddr(AHs + bo + (la_row + 64) * 40 + la_kc), Abase + (size_t)(la_row + 64) * Kp + kk + la_kc);
        cpa16(smaddr(BHs + bo2 + la_row * 40 + la_kc),       Bbase + (size_t)la_row * Kp + kk + la_kc);
        cpa_commit();
    };

    load_chunk(0, 0);

    #pragma unroll 1
    for (int kk = 0; kk < Kp; kk += 32) {
        int buf = (kk >> 5) & 1;
        asm volatile("cp.async.wait_group 0;");
        __syncthreads();
        if (kk + 32 < Kp) load_chunk(buf ^ 1, kk + 32);

        int bo = buf * 5120, bo2 = buf * 2560;
        #pragma unroll
        for (int ko = 0; ko < 32; ko += 16) {
            unsigned ahf[2][4], bhf[4][2];
            #pragma unroll
            for (int i = 0; i < 2; i++) {
                int r = wm * 32 + i * 16;
                ahf[i][0] = *(const unsigned*)&AHs[bo + (r + g) * 40 + ko + 2 * t];
                ahf[i][1] = *(const unsigned*)&AHs[bo + (r + g + 8) * 40 + ko + 2 * t];
                ahf[i][2] = *(const unsigned*)&AHs[bo + (r + g) * 40 + ko + 2 * t + 8];
                ahf[i][3] = *(const unsigned*)&AHs[bo + (r + g + 8) * 40 + ko + 2 * t + 8];
            }
            #pragma unroll
            for (int j = 0; j < 4; j++) {
                int bn = wn * 32 + j * 8 + g;
                bhf[j][0] = *(const unsigned*)&BHs[bo2 + bn * 40 + ko + 2 * t];
                bhf[j][1] = *(const unsigned*)&BHs[bo2 + bn * 40 + ko + 2 * t + 8];
            }
            #pragma unroll
            for (int i = 0; i < 2; i++)
                #pragma unroll
                for (int j = 0; j < 4; j++)
                    mma16816h(acc[i][j], ahf[i], bhf[j][0], bhf[j][1]);
        }
        __syncthreads();
    }

    #pragma unroll
    for (int i = 0; i < 2; i++) {
        int r = m0 + wm * 32 + i * 16 + g;
        #pragma unroll
        for (int j = 0; j < 4; j++) {
            int c = n0 + wn * 32 + j * 8 + 2 * t;
            if (mode == 0) {
                float b0 = bias ? bias[c] : 0.f, b1 = bias ? bias[c + 1] : 0.f;
                outF[(size_t)r * ldc + c]           = acc[i][j][0] + b0;
                outF[(size_t)r * ldc + c + 1]       = acc[i][j][1] + b1;
                outF[(size_t)(r + 8) * ldc + c]     = acc[i][j][2] + b0;
                outF[(size_t)(r + 8) * ldc + c + 1] = acc[i][j][3] + b1;
            } else {
                int k = c >> 1;
                if (k < NBINS) {
                    float p0 = acc[i][j][0] * acc[i][j][0] + acc[i][j][1] * acc[i][j][1];
                    float p1 = acc[i][j][2] * acc[i][j][2] + acc[i][j][3] * acc[i][j][3];
                    splitw(outP, (size_t)r * (2 * KP_MEL), KP_MEL, k, p0);
                    splitw(outP, (size_t)(r + 8) * (2 * KP_MEL), KP_MEL, k, p1);
                }
            }
        }
    }
}

// ---------------- split-bf16 tensor GEMM (mel; proven) ----------------
__global__ void __launch_bounds__(256, 3)
k_gemm(const __nv_bfloat16* __restrict__ A2, const __nv_bfloat16* __restrict__ B2,
       int Kp, const float* __restrict__ bias, int mode,
       float* __restrict__ outF, int ldc, int Nreal,
       __nv_bfloat16* __restrict__ outP, int KpOut) {
    extern __shared__ __nv_bfloat16 smd[];
    __nv_bfloat16* AHs = smd;
    __nv_bfloat16* ALs = smd + OFF_AL;
    __nv_bfloat16* BHs = smd + OFF_BH;
    __nv_bfloat16* BLs = smd + OFF_BL;

    int tid = threadIdx.x, lane = tid & 31, w = tid >> 5;
    int wm = w >> 1, wn = w & 1;
    int m0 = blockIdx.y * 128, n0 = blockIdx.x * 64;
    int g = lane >> 2, t = lane & 3;
    int strideA = 2 * Kp;
    int la_row = tid >> 2, la_kc = (tid & 3) << 3;

    const __nv_bfloat16* Abase = A2 + (size_t)m0 * strideA;
    const __nv_bfloat16* Bbase = B2 + (size_t)n0 * strideA;

    float acc[2][4][4];
    #pragma unroll
    for (int i = 0; i < 2; i++)
        #pragma unroll
        for (int j = 0; j < 4; j++)
            #pragma unroll
            for (int q = 0; q < 4; q++) acc[i][j][q] = 0.f;

    auto load_chunk = [&](int buf, int kk) {
        int bo = buf * 5120, bo2 = buf * 2560;
        cpa16(smaddr(AHs + bo + la_row * 40 + la_kc),        Abase + (size_t)la_row * strideA + kk + la_kc);
        cpa16(smaddr(AHs + bo + (la_row + 64) * 40 + la_kc), Abase + (size_t)(la_row + 64) * strideA + kk + la_kc);
        cpa16(smaddr(ALs + bo + la_row * 40 + la_kc),        Abase + (size_t)la_row * strideA + Kp + kk + la_kc);
        cpa16(smaddr(ALs + bo + (la_row + 64) * 40 + la_kc), Abase + (size_t)(la_row + 64) * strideA + Kp + kk + la_kc);
        cpa16(smaddr(BHs + bo2 + la_row * 40 + la_kc),       Bbase + (size_t)la_row * strideA + kk + la_kc);
        cpa16(smaddr(BLs + bo2 + la_row * 40 + la_kc),       Bbase + (size_t)la_row * strideA + Kp + kk + la_kc);
        cpa_commit();
    };

    load_chunk(0, 0);

    #pragma unroll 1
    for (int kk = 0; kk < Kp; kk += 32) {
        int buf = (kk >> 5) & 1;
        asm volatile("cp.async.wait_group 0;");
        __syncthreads();
        if (kk + 32 < Kp) load_chunk(buf ^ 1, kk + 32);

        int bo = buf * 5120, bo2 = buf * 2560;
        #pragma unroll
        for (int ko = 0; ko < 32; ko += 16) {
            unsigned ahf[2][4], alf[2][4], bhf[4][2], blf[4][2];
            #pragma unroll
            for (int i = 0; i < 2; i++) {
                int r = wm * 32 + i * 16;
                ahf[i][0] = *(const unsigned*)&AHs[bo + (r + g) * 40 + ko + 2 * t];
                ahf[i][1] = *(const unsigned*)&AHs[bo + (r + g + 8) * 40 + ko + 2 * t];
                ahf[i][2] = *(const unsigned*)&AHs[bo + (r + g) * 40 + ko + 2 * t + 8];
                ahf[i][3] = *(const unsigned*)&AHs[bo + (r + g + 8) * 40 + ko + 2 * t + 8];
                alf[i][0] = *(const unsigned*)&ALs[bo + (r + g) * 40 + ko + 2 * t];
                alf[i][1] = *(const unsigned*)&ALs[bo + (r + g + 8) * 40 + ko + 2 * t];
                alf[i][2] = *(const unsigned*)&ALs[bo + (r + g) * 40 + ko + 2 * t + 8];
                alf[i][3] = *(const unsigned*)&ALs[bo + (r + g + 8) * 40 + ko + 2 * t + 8];
            }
            #pragma unroll
            for (int j = 0; j < 4; j++) {
                int bn = wn * 32 + j * 8 + g;
                bhf[j][0] = *(const unsigned*)&BHs[bo2 + bn * 40 + ko + 2 * t];
                bhf[j][1] = *(const unsigned*)&BHs[bo2 + bn * 40 + ko + 2 * t + 8];
                blf[j][0] = *(const unsigned*)&BLs[bo2 + bn * 40 + ko + 2 * t];
                blf[j][1] = *(const unsigned*)&BLs[bo2 + bn * 40 + ko + 2 * t + 8];
            }
            #pragma unroll
            for (int i = 0; i < 2; i++)
                #pragma unroll
                for (int j = 0; j < 4; j++) {
                    mma16816(acc[i][j], ahf[i], bhf[j][0], bhf[j][1]);
                    mma16816(acc[i][j], ahf[i], blf[j][0], blf[j][1]);
                    mma16816(acc[i][j], alf[i], bhf[j][0], bhf[j][1]);
                }
        }
        __syncthreads();
    }

    #pragma unroll
    for (int i = 0; i < 2; i++) {
        int r = m0 + wm * 32 + i * 16 + g;
        #pragma unroll
        for (int j = 0; j < 4; j++) {
            int c = n0 + wn * 32 + j * 8 + 2 * t;
            float v00 = acc[i][j][0], v01 = acc[i][j][1];
            float v10 = acc[i][j][2], v11 = acc[i][j][3];
            if (mode == 0) {
                float b0 = bias ? bias[c] : 0.f, b1 = bias ? bias[c + 1] : 0.f;
                outF[(size_t)r * ldc + c]           = v00 + b0;
                outF[(size_t)r * ldc + c + 1]       = v01 + b1;
                outF[(size_t)(r + 8) * ldc + c]     = v10 + b0;
                outF[(size_t)(r + 8) * ldc + c + 1] = v11 + b1;
            } else {
                float b0 = bias ? bias[c] : 0.f, b1 = bias ? bias[c + 1] : 0.f;
                splitw(outP, (size_t)r * (2 * KpOut), KpOut, c, v00 + b0);
                splitw(outP, (size_t)r * (2 * KpOut), KpOut, c + 1, v01 + b1);
                splitw(outP, (size_t)(r + 8) * (2 * KpOut), KpOut, c, v10 + b0);
                splitw(outP, (size_t)(r + 8) * (2 * KpOut), KpOut, c + 1, v11 + b1);
            }
        }
    }
}

// ---------------- conv GEMM: shifted rows, 9 segments, fp16 single output ----------------
__global__ void __launch_bounds__(256, 3)
k_gemm_conv(const __nv_bfloat16* __restrict__ Msp, const __nv_bfloat16* __restrict__ B2,
            const float* __restrict__ bias, __half* __restrict__ outH) {
    __shared__ __nv_bfloat16 As[2][128][40];
    __shared__ __nv_bfloat16 Bs[2][64][40];
    int tid = threadIdx.x, lane = tid & 31, w = tid >> 5;
    int wm = w >> 1, wn = w & 1;
    int m0 = blockIdx.y * 128, n0 = blockIdx.x * 64;
    int g = lane >> 2, t = lane & 3;
    int la_row = tid >> 2, la_kc = (tid & 3) << 3;

    int gm0 = m0 + la_row, gm1 = m0 + la_row + 64;
    int sr0 = gm0 + 2 * (gm0 / TSTEPS);
    int sr1 = gm1 + 2 * (gm1 / TSTEPS);

    float acc[2][4][4];
    #pragma unroll
    for (int i = 0; i < 2; i++)
        #pragma unroll
        for (int j = 0; j < 4; j++)
            #pragma unroll
            for (int q = 0; q < 4; q++) acc[i][j][q] = 0.f;

    #pragma unroll 1
    for (int s = 0; s < 9; s++) {
        int split = s / 3, shift = s % 3;
        int aoff = (split == 2) ? 128 : 0;
        int boff = ((split == 1) ? KCONV : 0) + shift * 128;
        const __nv_bfloat16* A0 = Msp + (size_t)(sr0 + shift) * 256 + aoff;
        const __nv_bfloat16* A1 = Msp + (size_t)(sr1 + shift) * 256 + aoff;
        const __nv_bfloat16* Bb = B2 + (size_t)n0 * (2 * KCONV) + boff;

        cpa16(smaddr(&As[0][la_row][la_kc]),      A0 + la_kc);
        cpa16(smaddr(&As[0][la_row + 64][la_kc]), A1 + la_kc);
        cpa16(smaddr(&Bs[0][la_row][la_kc]),      Bb + (size_t)la_row * (2 * KCONV) + la_kc);
        cpa_commit();
        #pragma unroll 1
        for (int kk = 0; kk < 128; kk += 32) {
            int buf = (kk >> 5) & 1;
            asm volatile("cp.async.wait_group 0;");
            __syncthreads();
            if (kk + 32 < 128) {
                int nb = buf ^ 1, kn = kk + 32;
                cpa16(smaddr(&As[nb][la_row][la_kc]),      A0 + kn + la_kc);
                cpa16(smaddr(&As[nb][la_row + 64][la_kc]), A1 + kn + la_kc);
                cpa16(smaddr(&Bs[nb][la_row][la_kc]),      Bb + (size_t)la_row * (2 * KCONV) + kn + la_kc);
                cpa_commit();
            }
            #pragma unroll
            for (int ko = 0; ko < 32; ko += 16) {
                unsigned a[2][4], bfr[4][2];
                #pragma unroll
                for (int i = 0; i < 2; i++) {
                    int r = wm * 32 + i * 16;
                    a[i][0] = *(const unsigned*)&As[buf][r + g][ko + 2 * t];
                    a[i][1] = *(const unsigned*)&As[buf][r + g + 8][ko + 2 * t];
                    a[i][2] = *(const unsigned*)&As[buf][r + g][ko + 2 * t + 8];
                    a[i][3] = *(const unsigned*)&As[buf][r + g + 8][ko + 2 * t + 8];
                }
                #pragma unroll
                for (int j = 0; j < 4; j++) {
                    int bn = wn * 32 + j * 8 + g;
                    bfr[j][0] = *(const unsigned*)&Bs[buf][bn][ko + 2 * t];
                    bfr[j][1] = *(const unsigned*)&Bs[buf][bn][ko + 2 * t + 8];
                }
                #pragma unroll
                for (int i = 0; i < 2; i++)
                    #pragma unroll
                    for (int j = 0; j < 4; j++)
                        mma16816(acc[i][j], a[i], bfr[j][0], bfr[j][1]);
            }
            __syncthreads();
        }
    }

    #pragma unroll
    for (int i = 0; i < 2; i++) {
        int r = m0 + wm * 32 + i * 16 + g;
        #pragma unroll
        for (int j = 0; j < 4; j++) {
            int c = n0 + wn * 32 + j * 8 + 2 * t;
            float b0 = bias[c], b1 = bias[c + 1];
            outH[(size_t)r * KP_G + c]           = __float2half(acc[i][j][0] + b0);
            outH[(size_t)r * KP_G + c + 1]       = __float2half(acc[i][j][1] + b1);
            outH[(size_t)(r + 8) * KP_G + c]     = __float2half(acc[i][j][2] + b0);
            outH[(size_t)(r + 8) * KP_G + c + 1] = __float2half(acc[i][j][3] + b1);
        }
    }
}

// ---------------- tensor-core LSTM v3, fp16 h-export ----------------
__global__ void __launch_bounds__(256)
k_lstm_mma(const float* __restrict__ gx, const __nv_bfloat16* __restrict__ Up,
           __half* __restrict__ hexp, float* __restrict__ hmean) {
    extern __shared__ __nv_bfloat16 sm[];
    __nv_bfloat16* Uh  = sm;
    __nv_bfloat16* Ulw = sm + SM_UH;
    __nv_bfloat16* Hsp = sm + SM_UH + SM_UL;

    int tid = threadIdx.x, lane = tid & 31, w = tid >> 5;
    int g = lane >> 2, tq = lane & 3;
    int b0 = blockIdx.x * 16;
    int wbase = w * 64;
    __nv_bfloat16* myUl = Ulw + w * SM_ULW;

    for (int idx = tid; idx < 512 * 16; idx += 256) {
        int n = idx >> 4, j = idx & 15;
        *(uint4*)(Uh + n * UH_STRIDE + j * 8) = *(const uint4*)(Up + (size_t)n * 256 + j * 8);
    }
    for (int idx = tid; idx < SM_H; idx += 256) Hsp[idx] = __float2bfloat16(0.f);

    float cst[8], hsum[8];
    #pragma unroll
    for (int i = 0; i < 8; i++) { cst[i] = 0.f; hsum[i] = 0.f; }

    for (int t = 0; t < TSTEPS; t++) {
        float acc[8][4];
        {
            size_t rlo = ((size_t)(b0 + g) * TSTEPS + t) * G4 + wbase + 2 * tq;
            size_t rhi = ((size_t)(b0 + g + 8) * TSTEPS + t) * G4 + wbase + 2 * tq;
            #pragma unroll
            for (int a = 0; a < 8; a++) {
                float2 v0 = *(const float2*)&gx[rlo + a * 8];
                float2 v1 = *(const float2*)&gx[rhi + a * 8];
                acc[a][0] = v0.x; acc[a][1] = v0.y;
                acc[a][2] = v1.x; acc[a][3] = v1.y;
            }
        }
        __syncthreads();

        #pragma unroll
        for (int c0 = 0; c0 < 2; c0++) {
            __nv_bfloat16* buf = myUl + (c0 % 3) * 64 * ULW_STRIDE;
            #pragma unroll
            for (int i = 0; i < 4; i++) {
                int u = lane + 32 * i, n1 = u >> 1, hf = u & 1;
                cpa16(smaddr(buf + n1 * ULW_STRIDE + hf * 8),
                      Up + (size_t)(wbase + n1) * 256 + 128 + c0 * 16 + hf * 8);
            }
            cpa_commit();
        }

        #pragma unroll 1
        for (int c = 0; c < 8; c++) {
            if (c < 7) asm volatile("cp.async.wait_group 1;");
            else       asm volatile("cp.async.wait_group 0;");
            __syncwarp();
            if (c + 2 < 8) {
                __nv_bfloat16* nbuf = myUl + ((c + 2) % 3) * 64 * ULW_STRIDE;
                #pragma unroll
                for (int i = 0; i < 4; i++) {
                    int u = lane + 32 * i, n1 = u >> 1, hf = u & 1;
                    cpa16(smaddr(nbuf + n1 * ULW_STRIDE + hf * 8),
                          Up + (size_t)(wbase + n1) * 256 + 128 + (c + 2) * 16 + hf * 8);
                }
                cpa_commit();
            }
            int ko = c * 16 + 2 * tq;
            unsigned ah[4], al[4];
            ah[0] = *(const unsigned*)&Hsp[g * H_STRIDE + ko];
            ah[1] = *(const unsigned*)&Hsp[(g + 8) * H_STRIDE + ko];
            ah[2] = *(const unsigned*)&Hsp[g * H_STRIDE + ko + 8];
            ah[3] = *(const unsigned*)&Hsp[(g + 8) * H_STRIDE + ko + 8];
            al[0] = *(const unsigned*)&Hsp[g * H_STRIDE + 128 + ko];
            al[1] = *(const unsigned*)&Hsp[(g + 8) * H_STRIDE + 128 + ko];
            al[2] = *(const unsigned*)&Hsp[g * H_STRIDE + 128 + ko + 8];
            al[3] = *(const unsigned*)&Hsp[(g + 8) * H_STRIDE + 128 + ko + 8];
            const __nv_bfloat16* ulB = myUl + (c % 3) * 64 * ULW_STRIDE;
            #pragma unroll
            for (int bn = 0; bn < 8; bn++) {
                int n = wbase + bn * 8 + g;
                const __nv_bfloat16* bph = Uh + n * UH_STRIDE + ko;
                unsigned h0 = *(const unsigned*)bph;
                unsigned h1 = *(const unsigned*)(bph + 8);
                mma16816(acc[bn], ah, h0, h1);
                mma16816(acc[bn], al, h0, h1);
                const __nv_bfloat16* bpl = ulB + (bn * 8 + g) * ULW_STRIDE + 2 * tq;
                unsigned l0 = *(const unsigned*)bpl;
                unsigned l1 = *(const unsigned*)(bpl + 8);
                mma16816(acc[bn], ah, l0, l1);
            }
        }
        __syncthreads();

        #pragma unroll
        for (int uh = 0; uh < 2; uh++)
            #pragma unroll
            for (int par = 0; par < 2; par++)
                #pragma unroll
                for (int q2 = 0; q2 < 2; q2++) {
                    int u = uh * 8 + 2 * tq + par;
                    int r = g + 8 * q2;
                    int qq = q2 * 2 + par;
                    int ci = uh * 4 + par * 2 + q2;
                    float gi = acc[0 + uh][qq];
                    float gf = acc[2 + uh][qq];
                    float gg = acc[4 + uh][qq];
                    float go = acc[6 + uh][qq];
                    float c = sigf(gf) * cst[ci] + sigf(gi) * tanhf_acc(gg);
                    float h = sigf(go) * tanhf_acc(c);
                    cst[ci] = c;
                    int ug = w * 16 + u;
                    __nv_bfloat16 hh = __float2bfloat16(h);
                    __nv_bfloat16 hl = __float2bfloat16(h - __bfloat162float(hh));
                    Hsp[r * H_STRIDE + ug] = hh;
                    Hsp[r * H_STRIDE + 128 + ug] = hl;
                    if (hexp) {
                        size_t row2 = ((size_t)(b0 + r) * TSTEPS + t) * KP_G;
                        hexp[row2 + ug] = __float2half(h);
                    }
                    hsum[ci] += h;
                }
    }

    if (hmean) {
        #pragma unroll
        for (int uh = 0; uh < 2; uh++)
            #pragma unroll
            for (int par = 0; par < 2; par++)
                #pragma unroll
                for (int q2 = 0; q2 < 2; q2++) {
                    int u = uh * 8 + 2 * tq + par;
                    int r = g + 8 * q2;
                    int ci = uh * 4 + par * 2 + q2;
                    hmean[(size_t)(b0 + r) * 128 + w * 16 + u] = hsum[ci] * (1.0f / (float)TSTEPS);
                }
    }
}

// ---------------- small fp32 SGEMM for fc/proj ----------------
__global__ void k_sgemm(const float* __restrict__ A, const float* __restrict__ Bm,
                        float* __restrict__ C, const float* __restrict__ bias,
                        int M, int N, int K) {
    __shared__ float As[8][68];
    __shared__ float Bs[8][64];
    int tid = threadIdx.x;
    int m0 = blockIdx.y * 64, n0 = blockIdx.x * 64;
    int tm = tid & 15, tn = tid >> 4;
    float acc[4][8];
    #pragma unroll
    for (int i = 0; i < 4; i++)
        #pragma unroll
        for (int j = 0; j < 8; j++) acc[i][j] = 0.f;
    for (int kk = 0; kk < K; kk += 8) {
        #pragma unroll
        for (int i = 0; i < 4; i++) {
            int l = tid + i * 128, m = l >> 3, k = l & 7;
            int gm = m0 + m, gk = kk + k;
            As[k][m] = (gm < M && gk < K) ? A[(size_t)gm * K + gk] : 0.f;
        }
        #pragma unroll
        for (int i = 0; i < 4; i++) {
            int l = tid + i * 128, k = l >> 6, n = l & 63;
            int gk = kk + k, gn = n0 + n;
            Bs[k][n] = (gk < K && gn < N) ? Bm[(size_t)gk * N + gn] : 0.f;
        }
        __syncthreads();
        #pragma unroll
        for (int k = 0; k < 8; k++) {
            float a[4], bv[8];
            #pragma unroll
            for (int i = 0; i < 4; i++) a[i] = As[k][tm * 4 + i];
            #pragma unroll
            for (int j = 0; j < 8; j++) bv[j] = Bs[k][tn * 8 + j];
            #pragma unroll
            for (int i = 0; i < 4; i++)
                #pragma unroll
                for (int j = 0; j < 8; j++) acc[i][j] += a[i] * bv[j];
        }
        __syncthreads();
    }
    #pragma unroll
    for (int i = 0; i < 4; i++) {
        int gm = m0 + tm * 4 + i;
        if (gm >= M) continue;
        #pragma unroll
        for (int j = 0; j < 8; j++) {
            int gn = n0 + tn * 8 + j;
            if (gn < N) C[(size_t)gm * N + gn] = acc[i][j] + (bias ? bias[gn] : 0.f);
        }
    }
}

// ---------------- launch ----------------
extern "C" void kernel_launch(void* const* d_in, const int* in_sizes, int n_in,
                              void* d_out, int out_size) {
    const float* x      = (const float*)d_in[0];
    const float* conv_w = (const float*)d_in[1];
    const float* conv_b = (const float*)d_in[2];
    const float* W1     = (const float*)d_in[3];
    const float* U1     = (const float*)d_in[4];
    const float* b1     = (const float*)d_in[5];
    const float* W2     = (const float*)d_in[6];
    const float* U2     = (const float*)d_in[7];
    const float* b2     = (const float*)d_in[8];
    const float* fc1_w  = (const float*)d_in[9];
    const float* fc1_b  = (const float*)d_in[10];
    const float* proj_w = (const float*)d_in[11];
    const float* proj_b = (const float*)d_in[12];
    float* out = (float*)d_out;

    __half *pA1dft, *pB1dft, *pA1g, *pW1h, *pW2h, *pH1h;
    __nv_bfloat16 *pA2mel, *pB2mel, *pMelsp, *pB2conv, *pU1p, *pU2p;
    float *pG, *pHmean, *pHfc, *pB1p, *pB2p;
    cudaGetSymbolAddress((void**)&pA1dft,  d_A1dft);
    cudaGetSymbolAddress((void**)&pB1dft,  d_B1dft);
    cudaGetSymbolAddress((void**)&pA2mel,  d_A2mel);
    cudaGetSymbolAddress((void**)&pB2mel,  d_B2mel);
    cudaGetSymbolAddress((void**)&pMelsp,  d_melsp);
    cudaGetSymbolAddress((void**)&pB2conv, d_B2conv);
    cudaGetSymbolAddress((void**)&pA1g,    d_A1g);
    cudaGetSymbolAddress((void**)&pW1h,    d_W1h);
    cudaGetSymbolAddress((void**)&pW2h,    d_W2h);
    cudaGetSymbolAddress((void**)&pU1p,    d_U1p);
    cudaGetSymbolAddress((void**)&pU2p,    d_U2p);
    cudaGetSymbolAddress((void**)&pH1h,    d_h1h);
    cudaGetSymbolAddress((void**)&pG,      d_g);
    cudaGetSymbolAddress((void**)&pHmean,  d_hmean);
    cudaGetSymbolAddress((void**)&pHfc,    d_hfc);
    cudaGetSymbolAddress((void**)&pB1p,    d_b1p);
    cudaGetSymbolAddress((void**)&pB2p,    d_b2p);

    cudaFuncSetAttribute(k_lstm_mma, cudaFuncAttributeMaxDynamicSharedMemorySize, LSTM_SMEM_BYTES);
    cudaFuncSetAttribute(k_gemm,     cudaFuncAttributeMaxDynamicSharedMemorySize, GEMM_SMEM_BYTES);
    cudaFuncSetAttribute(k_gemm16,   cudaFuncAttributeMaxDynamicSharedMemorySize, F16_SMEM_BYTES);

    k_precompute<<<128, 256>>>(conv_w, W1, W2, U1, U2, b1, b2);
    k_window<<<dim3(NFRAMES, BATCH), 256>>>(x);

    // DFT (fp16 single) -> power split-pack into A2mel
    k_gemm16<<<dim3(NP_DFT / 64, R1 / 128), 256, F16_SMEM_BYTES>>>(
        pA1dft, pB1dft, KP_DFT, nullptr, 1, nullptr, 0, pA2mel);
    // mel (bf16 split) -> split pack
    k_gemm<<<dim3(2, R1 / 128), 256, GEMM_SMEM_BYTES>>>(
        pA2mel, pB2mel, KP_MEL, nullptr, 2, nullptr, 0, NMELS, pMelsp, 128);
    // conv (bf16 split, shifted rows) -> fp16 single into A1g
    k_gemm_conv<<<dim3(2, R2 / 128), 256>>>(pMelsp, pB2conv, conv_b, pA1g);
    // g1 (fp16 single, permuted gates)
    k_gemm16<<<dim3(8, R2 / 128), 256, F16_SMEM_BYTES>>>(
        pA1g, pW1h, KP_G, pB1p, 0, pG, G4, nullptr);
    k_lstm_mma<<<BATCH / 16, 256, LSTM_SMEM_BYTES>>>(pG, pU1p, pH1h, nullptr);
    // g2 (fp16 single)
    k_gemm16<<<dim3(8, R2 / 128), 256, F16_SMEM_BYTES>>>(
        pH1h, pW2h, KP_G, pB2p, 0, pG, G4, nullptr);
    k_lstm_mma<<<BATCH / 16, 256, LSTM_SMEM_BYTES>>>(pG, pU2p, nullptr, pHmean);

    k_sgemm<<<dim3(2, BATCH / 64), 128>>>(pHmean, fc1_w, pHfc, fc1_b, BATCH, 128, 128);
    k_sgemm<<<dim3(1, BATCH / 64), 128>>>(pHfc, proj_w, out, proj_b, BATCH, 35, 128);
}

// round 15
// speedup vs baseline: 2.1779x; 1.3001x over previous
#include <cuda_runtime.h>
#include <cuda_bf16.h>
#include <cuda_fp16.h>
#include <math.h>

// ---------------- problem dims ----------------
#define BATCH   1024
#define TLEN    16000
#define NFFT    400
#define HOP     200
#define NBINS   201
#define NMELS   128
#define NFRAMES 81
#define TSTEPS  79
#define HID     128
#define G4      512
#define R1      (BATCH*NFRAMES)   // 82944
#define R2      (BATCH*TSTEPS)    // 80896

#define KP_DFT  416
#define KP_MEL  224
#define KP_G    128
#define NP_DFT  448
#define KCONV   384

// bf16 split k_gemm dynamic smem (bf16 elems)
#define GEMM_SMEM_ELEMS (2*128*40*2 + 2*64*40*2)   // 30720
#define GEMM_SMEM_BYTES (GEMM_SMEM_ELEMS*2)        // 61440
#define OFF_AL  10240
#define OFF_BH  20480
#define OFF_BL  25600

// fp16 single-term GEMM smem
#define F16_SMEM_ELEMS (2*128*40 + 2*64*40)        // 15360
#define F16_SMEM_BYTES (F16_SMEM_ELEMS*2)          // 30720
#define DOFF_B  10240

// LSTM (cluster-paired n-split) smem, bf16 elems
#define UH_STRIDE 136
#define ULW_STRIDE 24
#define H_STRIDE  264
#define SM_UH2   (256*UH_STRIDE)           // 34816
#define SM_ULW2  (3*32*ULW_STRIDE)         // 2304 per warp (3 bufs)
#define SM_UL2   (8*SM_ULW2)               // 18432
#define SM_H     (16*H_STRIDE)             // 4224
#define LSTM2_SMEM_BYTES ((SM_UH2 + SM_UL2 + SM_H)*2)   // 114944

// ---------------- scratch ----------------
__device__ float          d_hann[NFFT];
__device__ __half         d_A1dft[(size_t)R1 * KP_DFT];
__device__ __half         d_B1dft[(size_t)NP_DFT * KP_DFT];
__device__ __nv_bfloat16  d_A2mel[(size_t)R1 * 2 * KP_MEL];
__device__ __nv_bfloat16  d_B2mel[(size_t)128 * 2 * KP_MEL];
__device__ __nv_bfloat16  d_melsp[(size_t)R1 * 256];
__device__ __nv_bfloat16  d_B2conv[(size_t)128 * 2 * KCONV];
__device__ __half         d_A1g[(size_t)R2 * KP_G];
__device__ __half         d_W1h[(size_t)G4 * KP_G];
__device__ __half         d_W2h[(size_t)G4 * KP_G];
__device__ __nv_bfloat16  d_U1p[(size_t)G4 * 2 * KP_G];
__device__ __nv_bfloat16  d_U2p[(size_t)G4 * 2 * KP_G];
__device__ float          d_b1p[G4];
__device__ float          d_b2p[G4];
__device__ float          d_g[(size_t)R2 * G4];
__device__ __half         d_h1h[(size_t)R2 * KP_G];
__device__ float          d_hmean[BATCH * 128];
__device__ float          d_hfc[BATCH * 128];

// ---------------- helpers ----------------
__device__ __forceinline__ float sigf(float x) { return 1.0f / (1.0f + __expf(-x)); }
__device__ __forceinline__ float tanhf_acc(float x) {
    float t = __expf(-2.0f * fabsf(x));
    float r = (1.0f - t) / (1.0f + t);
    return copysignf(r, x);
}
__device__ __forceinline__ void splitw(__nv_bfloat16* P, size_t base, int KpOut, int k, float v) {
    __nv_bfloat16 h = __float2bfloat16(v);
    P[base + k] = h;
    P[base + KpOut + k] = __float2bfloat16(v - __bfloat162float(h));
}
__device__ __forceinline__ unsigned smaddr(const void* p) {
    return (unsigned)__cvta_generic_to_shared(p);
}
__device__ __forceinline__ void cpa16(unsigned dst, const void* src) {
    asm volatile("cp.async.cg.shared.global [%0], [%1], 16;" :: "r"(dst), "l"(src));
}
__device__ __forceinline__ void cpa_commit() { asm volatile("cp.async.commit_group;"); }
__device__ __forceinline__ void mma16816(float* c, const unsigned* a, unsigned b0, unsigned b1) {
    asm volatile(
        "mma.sync.aligned.m16n8k16.row.col.f32.bf16.bf16.f32 "
        "{%0,%1,%2,%3}, {%4,%5,%6,%7}, {%8,%9}, {%0,%1,%2,%3};"
        : "+f"(c[0]), "+f"(c[1]), "+f"(c[2]), "+f"(c[3])
        : "r"(a[0]), "r"(a[1]), "r"(a[2]), "r"(a[3]), "r"(b0), "r"(b1));
}
__device__ __forceinline__ void mma16816h(float* c, const unsigned* a, unsigned b0, unsigned b1) {
    asm volatile(
        "mma.sync.aligned.m16n8k16.row.col.f32.f16.f16.f32 "
        "{%0,%1,%2,%3}, {%4,%5,%6,%7}, {%8,%9}, {%0,%1,%2,%3};"
        : "+f"(c[0]), "+f"(c[1]), "+f"(c[2]), "+f"(c[3])
        : "r"(a[0]), "r"(a[1]), "r"(a[2]), "r"(a[3]), "r"(b0), "r"(b1));
}
// packed gate col n -> original col.  slice = n>>5 (8-unit slice), s = n&31,
// gate = s>>3, u = s&7.  Warp-w/CTA-r slice = r*8+w holds units [slice*8, slice*8+8), all 4 gates.
__device__ __forceinline__ int gperm(int n) {
    int slice = n >> 5, s = n & 31, gate = s >> 3, u = s & 7;
    return gate * 128 + slice * 8 + u;
}
#define CLUSTER_SYNC() do { \
    asm volatile("barrier.cluster.arrive.aligned;" ::: "memory"); \
    asm volatile("barrier.cluster.wait.aligned;"   ::: "memory"); } while (0)

// ---------------- precompute (fp32 fast math) ----------------
__global__ void k_precompute(const float* __restrict__ conv_w,
                             const float* __restrict__ W1, const float* __restrict__ W2,
                             const float* __restrict__ U1, const float* __restrict__ U2,
                             const float* __restrict__ b1, const float* __restrict__ b2) {
    int tid = blockIdx.x * blockDim.x + threadIdx.x;
    int nth = gridDim.x * blockDim.x;

    for (int k = tid; k < NFFT; k += nth)
        d_hann[k] = 0.5f - 0.5f * cospif((float)k / 200.0f);

    for (int idx = tid; idx < NP_DFT * KP_DFT; idx += nth) {
        int n = idx / KP_DFT, k = idx % KP_DFT;
        float v = 0.f;
        if (n < 2 * NBINS && k < NFFT) {
            int m = n >> 1;
            int ph = (m * k) % 400;
            float s, c;
            sincospif((float)ph / 200.0f, &s, &c);
            v = (n & 1) ? s : c;
        }
        d_B1dft[(size_t)n * KP_DFT + k] = __float2half(v);
    }

    const float mel_max = 2595.0f * log10f(1.0f + 8000.0f / 700.0f);
    for (int idx = tid; idx < 128 * KP_MEL; idx += nth) {
        int m = idx / KP_MEL, k = idx % KP_MEL;
        float v = 0.f;
        if (k < NBINS) {
            float freq = 40.0f * (float)k;
            float f0 = 700.0f * (exp10f((mel_max * (float)(m    ) / 129.0f) / 2595.0f) - 1.0f);
            float f1 = 700.0f * (exp10f((mel_max * (float)(m + 1) / 129.0f) / 2595.0f) - 1.0f);
            float f2 = 700.0f * (exp10f((mel_max * (float)(m + 2) / 129.0f) / 2595.0f) - 1.0f);
            float dn = (freq - f0) / (f1 - f0);
            float up = (f2 - freq) / (f2 - f1);
            float t = fminf(dn, up);
            v = fmaxf(t, 0.0f);
        }
        splitw(d_B2mel, (size_t)m * (2 * KP_MEL), KP_MEL, k, v);
    }

    for (int idx = tid; idx < 128 * KCONV; idx += nth) {
        int o = idx / KCONV, q = idx % KCONV;
        int kk = q >> 7, i = q & 127;
        splitw(d_B2conv, (size_t)o * (2 * KCONV), KCONV, q, conv_w[o * 384 + i * 3 + kk]);
    }

    for (int idx = tid; idx < G4 * KP_G; idx += nth) {
        int n = idx / KP_G, k = idx % KP_G;
        int no = gperm(n);
        d_W1h[(size_t)n * KP_G + k] = __float2half(W1[k * G4 + no]);
        d_W2h[(size_t)n * KP_G + k] = __float2half(W2[k * G4 + no]);
        splitw(d_U1p, (size_t)n * (2 * KP_G), KP_G, k, U1[k * G4 + no]);
        splitw(d_U2p, (size_t)n * (2 * KP_G), KP_G, k, U2[k * G4 + no]);
    }
    for (int n = tid; n < G4; n += nth) {
        int no = gperm(n);
        d_b1p[n] = b1[no];
        d_b2p[n] = b2[no];
    }

    for (int idx = tid; idx < R1 * (KP_MEL - NBINS); idx += nth) {
        int r = idx / (KP_MEL - NBINS), k = NBINS + idx % (KP_MEL - NBINS);
        d_A2mel[(size_t)r * (2 * KP_MEL) + k] = __float2bfloat16(0.f);
        d_A2mel[(size_t)r * (2 * KP_MEL) + KP_MEL + k] = __float2bfloat16(0.f);
    }
}

// ---------------- window -> fp16 A ----------------
__global__ void k_window(const float* __restrict__ x) {
    int f = blockIdx.x, b = blockIdx.y, tid = threadIdx.x;
    size_t row = (size_t)(b * NFRAMES + f) * KP_DFT;
    for (int k = tid; k < KP_DFT; k += blockDim.x) {
        float v = 0.f;
        if (k < NFFT) {
            int p = f * HOP + k - 200;
            int i = (p < 0) ? -p : ((p >= TLEN) ? (2 * TLEN - 2 - p) : p);
            v = x[(size_t)b * TLEN + i] * d_hann[k];
        }
        d_A1dft[row + k] = __float2half(v);
    }
}

// ---------------- generic single-term fp16 GEMM ----------------
// mode 0: fp32 out + bias; mode 1: DFT power -> bf16 split pack into outP
__global__ void __launch_bounds__(256, 3)
k_gemm16(const __half* __restrict__ A1, const __half* __restrict__ B1,
         int Kp, const float* __restrict__ bias, int mode,
         float* __restrict__ outF, int ldc,
         __nv_bfloat16* __restrict__ outP) {
    extern __shared__ __half smh[];
    __half* AHs = smh;
    __half* BHs = smh + DOFF_B;

    int tid = threadIdx.x, lane = tid & 31, w = tid >> 5;
    int wm = w >> 1, wn = w & 1;
    int m0 = blockIdx.y * 128, n0 = blockIdx.x * 64;
    int g = lane >> 2, t = lane & 3;
    int la_row = tid >> 2, la_kc = (tid & 3) << 3;

    const __half* Abase = A1 + (size_t)m0 * Kp;
    const __half* Bbase = B1 + (size_t)n0 * Kp;

    float acc[2][4][4];
    #pragma unroll
    for (int i = 0; i < 2; i++)
        #pragma unroll
        for (int j = 0; j < 4; j++)
            #pragma unroll
            for (int q = 0; q < 4; q++) acc[i][j][q] = 0.f;

    auto load_chunk = [&](int buf, int kk) {
        int bo = buf * 5120, bo2 = buf * 2560;
        cpa16(smaddr(AHs + bo + la_row * 40 + la_kc),        Abase + (size_t)la_row * Kp + kk + la_kc);
        cpa16(smaddr(AHs + bo + (la_row + 64) * 40 + la_kc), Abase + (size_t)(la_row + 64) * Kp + kk + la_kc);
        cpa16(smaddr(BHs + bo2 + la_row * 40 + la_kc),       Bbase + (size_t)la_row * Kp + kk + la_kc);
        cpa_commit();
    };

    load_chunk(0, 0);

    #pragma unroll 1
    for (int kk = 0; kk < Kp; kk += 32) {
        int buf = (kk >> 5) & 1;
        asm volatile("cp.async.wait_group 0;");
        __syncthreads();
        if (kk + 32 < Kp) load_chunk(buf ^ 1, kk + 32);

        int bo = buf * 5120, bo2 = buf * 2560;
        #pragma unroll
        for (int ko = 0; ko < 32; ko += 16) {
            unsigned ahf[2][4], bhf[4][2];
            #pragma unroll
            for (int i = 0; i < 2; i++) {
                int r = wm * 32 + i * 16;
                ahf[i][0] = *(const unsigned*)&AHs[bo + (r + g) * 40 + ko + 2 * t];
                ahf[i][1] = *(const unsigned*)&AHs[bo + (r + g + 8) * 40 + ko + 2 * t];
                ahf[i][2] = *(const unsigned*)&AHs[bo + (r + g) * 40 + ko + 2 * t + 8];
                ahf[i][3] = *(const unsigned*)&AHs[bo + (r + g + 8) * 40 + ko + 2 * t + 8];
            }
            #pragma unroll
            for (int j = 0; j < 4; j++) {
                int bn = wn * 32 + j * 8 + g;
                bhf[j][0] = *(const unsigned*)&BHs[bo2 + bn * 40 + ko + 2 * t];
                bhf[j][1] = *(const unsigned*)&BHs[bo2 + bn * 40 + ko + 2 * t + 8];
            }
            #pragma unroll
            for (int i = 0; i < 2; i++)
                #pragma unroll
                for (int j = 0; j < 4; j++)
                    mma16816h(acc[i][j], ahf[i], bhf[j][0], bhf[j][1]);
        }
        __syncthreads();
    }

    #pragma unroll
    for (int i = 0; i < 2; i++) {
        int r = m0 + wm * 32 + i * 16 + g;
        #pragma unroll
        for (int j = 0; j < 4; j++) {
            int c = n0 + wn * 32 + j * 8 + 2 * t;
            if (mode == 0) {
                float b0 = bias ? bias[c] : 0.f, b1 = bias ? bias[c + 1] : 0.f;
                outF[(size_t)r * ldc + c]           = acc[i][j][0] + b0;
                outF[(size_t)r * ldc + c + 1]       = acc[i][j][1] + b1;
                outF[(size_t)(r + 8) * ldc + c]     = acc[i][j][2] + b0;
                outF[(size_t)(r + 8) * ldc + c + 1] = acc[i][j][3] + b1;
            } else {
                int k = c >> 1;
                if (k < NBINS) {
                    float p0 = acc[i][j][0] * acc[i][j][0] + acc[i][j][1] * acc[i][j][1];
                    float p1 = acc[i][j][2] * acc[i][j][2] + acc[i][j][3] * acc[i][j][3];
                    splitw(outP, (size_t)r * (2 * KP_MEL), KP_MEL, k, p0);
                    splitw(outP, (size_t)(r + 8) * (2 * KP_MEL), KP_MEL, k, p1);
                }
            }
        }
    }
}

// ---------------- split-bf16 tensor GEMM (mel; proven) ----------------
__global__ void __launch_bounds__(256, 3)
k_gemm(const __nv_bfloat16* __restrict__ A2, const __nv_bfloat16* __restrict__ B2,
       int Kp, const float* __restrict__ bias, int mode,
       float* __restrict__ outF, int ldc, int Nreal,
       __nv_bfloat16* __restrict__ outP, int KpOut) {
    extern __shared__ __nv_bfloat16 smd[];
    __nv_bfloat16* AHs = smd;
    __nv_bfloat16* ALs = smd + OFF_AL;
    __nv_bfloat16* BHs = smd + OFF_BH;
    __nv_bfloat16* BLs = smd + OFF_BL;

    int tid = threadIdx.x, lane = tid & 31, w = tid >> 5;
    int wm = w >> 1, wn = w & 1;
    int m0 = blockIdx.y * 128, n0 = blockIdx.x * 64;
    int g = lane >> 2, t = lane & 3;
    int strideA = 2 * Kp;
    int la_row = tid >> 2, la_kc = (tid & 3) << 3;

    const __nv_bfloat16* Abase = A2 + (size_t)m0 * strideA;
    const __nv_bfloat16* Bbase = B2 + (size_t)n0 * strideA;

    float acc[2][4][4];
    #pragma unroll
    for (int i = 0; i < 2; i++)
        #pragma unroll
        for (int j = 0; j < 4; j++)
            #pragma unroll
            for (int q = 0; q < 4; q++) acc[i][j][q] = 0.f;

    auto load_chunk = [&](int buf, int kk) {
        int bo = buf * 5120, bo2 = buf * 2560;
        cpa16(smaddr(AHs + bo + la_row * 40 + la_kc),        Abase + (size_t)la_row * strideA + kk + la_kc);
        cpa16(smaddr(AHs + bo + (la_row + 64) * 40 + la_kc), Abase + (size_t)(la_row + 64) * strideA + kk + la_kc);
        cpa16(smaddr(ALs + bo + la_row * 40 + la_kc),        Abase + (size_t)la_row * strideA + Kp + kk + la_kc);
        cpa16(smaddr(ALs + bo + (la_row + 64) * 40 + la_kc), Abase + (size_t)(la_row + 64) * strideA + Kp + kk + la_kc);
        cpa16(smaddr(BHs + bo2 + la_row * 40 + la_kc),       Bbase + (size_t)la_row * strideA + kk + la_kc);
        cpa16(smaddr(BLs + bo2 + la_row * 40 + la_kc),       Bbase + (size_t)la_row * strideA + Kp + kk + la_kc);
        cpa_commit();
    };

    load_chunk(0, 0);

    #pragma unroll 1
    for (int kk = 0; kk < Kp; kk += 32) {
        int buf = (kk >> 5) & 1;
        asm volatile("cp.async.wait_group 0;");
        __syncthreads();
        if (kk + 32 < Kp) load_chunk(buf ^ 1, kk + 32);

        int bo = buf * 5120, bo2 = buf * 2560;
        #pragma unroll
        for (int ko = 0; ko < 32; ko += 16) {
            unsigned ahf[2][4], alf[2][4], bhf[4][2], blf[4][2];
            #pragma unroll
            for (int i = 0; i < 2; i++) {
                int r = wm * 32 + i * 16;
                ahf[i][0] = *(const unsigned*)&AHs[bo + (r + g) * 40 + ko + 2 * t];
                ahf[i][1] = *(const unsigned*)&AHs[bo + (r + g + 8) * 40 + ko + 2 * t];
                ahf[i][2] = *(const unsigned*)&AHs[bo + (r + g) * 40 + ko + 2 * t + 8];
                ahf[i][3] = *(const unsigned*)&AHs[bo + (r + g + 8) * 40 + ko + 2 * t + 8];
                alf[i][0] = *(const unsigned*)&ALs[bo + (r + g) * 40 + ko + 2 * t];
                alf[i][1] = *(const unsigned*)&ALs[bo + (r + g + 8) * 40 + ko + 2 * t];
                alf[i][2] = *(const unsigned*)&ALs[bo + (r + g) * 40 + ko + 2 * t + 8];
                alf[i][3] = *(const unsigned*)&ALs[bo + (r + g + 8) * 40 + ko + 2 * t + 8];
            }
            #pragma unroll
            for (int j = 0; j < 4; j++) {
                int bn = wn * 32 + j * 8 + g;
                bhf[j][0] = *(const unsigned*)&BHs[bo2 + bn * 40 + ko + 2 * t];
                bhf[j][1] = *(const unsigned*)&BHs[bo2 + bn * 40 + ko + 2 * t + 8];
                blf[j][0] = *(const unsigned*)&BLs[bo2 + bn * 40 + ko + 2 * t];
                blf[j][1] = *(const unsigned*)&BLs[bo2 + bn * 40 + ko + 2 * t + 8];
            }
            #pragma unroll
            for (int i = 0; i < 2; i++)
                #pragma unroll
                for (int j = 0; j < 4; j++) {
                    mma16816(acc[i][j], ahf[i], bhf[j][0], bhf[j][1]);
                    mma16816(acc[i][j], ahf[i], blf[j][0], blf[j][1]);
                    mma16816(acc[i][j], alf[i], bhf[j][0], bhf[j][1]);
                }
        }
        __syncthreads();
    }

    #pragma unroll
    for (int i = 0; i < 2; i++) {
        int r = m0 + wm * 32 + i * 16 + g;
        #pragma unroll
        for (int j = 0; j < 4; j++) {
            int c = n0 + wn * 32 + j * 8 + 2 * t;
            float v00 = acc[i][j][0], v01 = acc[i][j][1];
            float v10 = acc[i][j][2], v11 = acc[i][j][3];
            if (mode == 0) {
                float b0 = bias ? bias[c] : 0.f, b1 = bias ? bias[c + 1] : 0.f;
                outF[(size_t)r * ldc + c]           = v00 + b0;
                outF[(size_t)r * ldc + c + 1]       = v01 + b1;
                outF[(size_t)(r + 8) * ldc + c]     = v10 + b0;
                outF[(size_t)(r + 8) * ldc + c + 1] = v11 + b1;
            } else {
                float b0 = bias ? bias[c] : 0.f, b1 = bias ? bias[c + 1] : 0.f;
                splitw(outP, (size_t)r * (2 * KpOut), KpOut, c, v00 + b0);
                splitw(outP, (size_t)r * (2 * KpOut), KpOut, c + 1, v01 + b1);
                splitw(outP, (size_t)(r + 8) * (2 * KpOut), KpOut, c, v10 + b0);
                splitw(outP, (size_t)(r + 8) * (2 * KpOut), KpOut, c + 1, v11 + b1);
            }
        }
    }
}

// ---------------- conv GEMM: shifted rows, 9 segments, fp16 single output ----------------
__global__ void __launch_bounds__(256, 3)
k_gemm_conv(const __nv_bfloat16* __restrict__ Msp, const __nv_bfloat16* __restrict__ B2,
            const float* __restrict__ bias, __half* __restrict__ outH) {
    __shared__ __nv_bfloat16 As[2][128][40];
    __shared__ __nv_bfloat16 Bs[2][64][40];
    int tid = threadIdx.x, lane = tid & 31, w = tid >> 5;
    int wm = w >> 1, wn = w & 1;
    int m0 = blockIdx.y * 128, n0 = blockIdx.x * 64;
    int g = lane >> 2, t = lane & 3;
    int la_row = tid >> 2, la_kc = (tid & 3) << 3;

    int gm0 = m0 + la_row, gm1 = m0 + la_row + 64;
    int sr0 = gm0 + 2 * (gm0 / TSTEPS);
    int sr1 = gm1 + 2 * (gm1 / TSTEPS);

    float acc[2][4][4];
    #pragma unroll
    for (int i = 0; i < 2; i++)
        #pragma unroll
        for (int j = 0; j < 4; j++)
            #pragma unroll
            for (int q = 0; q < 4; q++) acc[i][j][q] = 0.f;

    #pragma unroll 1
    for (int s = 0; s < 9; s++) {
        int split = s / 3, shift = s % 3;
        int aoff = (split == 2) ? 128 : 0;
        int boff = ((split == 1) ? KCONV : 0) + shift * 128;
        const __nv_bfloat16* A0 = Msp + (size_t)(sr0 + shift) * 256 + aoff;
        const __nv_bfloat16* A1 = Msp + (size_t)(sr1 + shift) * 256 + aoff;
        const __nv_bfloat16* Bb = B2 + (size_t)n0 * (2 * KCONV) + boff;

        cpa16(smaddr(&As[0][la_row][la_kc]),      A0 + la_kc);
        cpa16(smaddr(&As[0][la_row + 64][la_kc]), A1 + la_kc);
        cpa16(smaddr(&Bs[0][la_row][la_kc]),      Bb + (size_t)la_row * (2 * KCONV) + la_kc);
        cpa_commit();
        #pragma unroll 1
        for (int kk = 0; kk < 128; kk += 32) {
            int buf = (kk >> 5) & 1;
            asm volatile("cp.async.wait_group 0;");
            __syncthreads();
            if (kk + 32 < 128) {
                int nb = buf ^ 1, kn = kk + 32;
                cpa16(smaddr(&As[nb][la_row][la_kc]),      A0 + kn + la_kc);
                cpa16(smaddr(&As[nb][la_row + 64][la_kc]), A1 + kn + la_kc);
                cpa16(smaddr(&Bs[nb][la_row][la_kc]),      Bb + (size_t)la_row * (2 * KCONV) + kn + la_kc);
                cpa_commit();
            }
            #pragma unroll
            for (int ko = 0; ko < 32; ko += 16) {
                unsigned a[2][4], bfr[4][2];
                #pragma unroll
                for (int i = 0; i < 2; i++) {
                    int r = wm * 32 + i * 16;
                    a[i][0] = *(const unsigned*)&As[buf][r + g][ko + 2 * t];
                    a[i][1] = *(const unsigned*)&As[buf][r + g + 8][ko + 2 * t];
                    a[i][2] = *(const unsigned*)&As[buf][r + g][ko + 2 * t + 8];
                    a[i][3] = *(const unsigned*)&As[buf][r + g + 8][ko + 2 * t + 8];
                }
                #pragma unroll
                for (int j = 0; j < 4; j++) {
                    int bn = wn * 32 + j * 8 + g;
                    bfr[j][0] = *(const unsigned*)&Bs[buf][bn][ko + 2 * t];
                    bfr[j][1] = *(const unsigned*)&Bs[buf][bn][ko + 2 * t + 8];
                }
                #pragma unroll
                for (int i = 0; i < 2; i++)
                    #pragma unroll
                    for (int j = 0; j < 4; j++)
                        mma16816(acc[i][j], a[i], bfr[j][0], bfr[j][1]);
            }
            __syncthreads();
        }
    }

    #pragma unroll
    for (int i = 0; i < 2; i++) {
        int r = m0 + wm * 32 + i * 16 + g;
        #pragma unroll
        for (int j = 0; j < 4; j++) {
            int c = n0 + wn * 32 + j * 8 + 2 * t;
            float b0 = bias[c], b1 = bias[c + 1];
            outH[(size_t)r * KP_G + c]           = __float2half(acc[i][j][0] + b0);
            outH[(size_t)r * KP_G + c + 1]       = __float2half(acc[i][j][1] + b1);
            outH[(size_t)(r + 8) * KP_G + c]     = __float2half(acc[i][j][2] + b0);
            outH[(size_t)(r + 8) * KP_G + c + 1] = __float2half(acc[i][j][3] + b1);
        }
    }
}

// ---------------- cluster-paired n-split LSTM: 2 CTAs share 16 batch rows ----------------
__global__ void __cluster_dims__(2, 1, 1) __launch_bounds__(256)
k_lstm_mma(const float* __restrict__ gx, const __nv_bfloat16* __restrict__ Up,
           __half* __restrict__ hexp, float* __restrict__ hmean) {
    extern __shared__ __nv_bfloat16 sm[];
    __nv_bfloat16* Uh  = sm;                       // [256][136]
    __nv_bfloat16* Ulw = sm + SM_UH2;              // per-warp 3 x [32][24]
    __nv_bfloat16* Hsp = sm + SM_UH2 + SM_UL2;     // [16][264] hi|lo (full 128 units)

    int tid = threadIdx.x, lane = tid & 31, w = tid >> 5;
    int g = lane >> 2, tq = lane & 3;
    unsigned rank;
    asm("mov.u32 %0, %%cluster_ctarank;" : "=r"(rank));
    int b0 = (blockIdx.x >> 1) * 16;
    int nbase_l = w * 32;                          // local packed col base
    int gbase = (int)rank * 256 + nbase_l;         // global packed col base
    int slice = (int)rank * 8 + w;                 // unit slice (8 units)
    __nv_bfloat16* myUl = Ulw + w * SM_ULW2;
    const __nv_bfloat16* UpC = Up + (size_t)((int)rank * 256) * 256;

    unsigned peerHsp;
    asm("mapa.shared::cluster.u32 %0, %1, %2;"
        : "=r"(peerHsp) : "r"(smaddr(Hsp)), "r"(1u - rank));

    // load this CTA's Uh (256 rows x 128 hi); zero Hsp
    for (int idx = tid; idx < 256 * 16; idx += 256) {
        int n = idx >> 4, j = idx & 15;
        *(uint4*)(Uh + n * UH_STRIDE + j * 8) = *(const uint4*)(UpC + (size_t)n * 256 + j * 8);
    }
    for (int idx = tid; idx < SM_H; idx += 256) Hsp[idx] = __float2bfloat16(0.f);

    float cst[4], hsum[4];
    #pragma unroll
    for (int i = 0; i < 4; i++) { cst[i] = 0.f; hsum[i] = 0.f; }

    for (int t = 0; t < TSTEPS; t++) {
        // gx loads (no smem dependency), 4 n-tiles
        float acc[4][4];
        {
            size_t rlo = ((size_t)(b0 + g) * TSTEPS + t) * G4 + gbase + 2 * tq;
            size_t rhi = ((size_t)(b0 + g + 8) * TSTEPS + t) * G4 + gbase + 2 * tq;
            #pragma unroll
            for (int bn = 0; bn < 4; bn++) {
                float2 v0 = *(const float2*)&gx[rlo + bn * 8];
                float2 v1 = *(const float2*)&gx[rhi + bn * 8];
                acc[bn][0] = v0.x; acc[bn][1] = v0.y;
                acc[bn][2] = v1.x; acc[bn][3] = v1.y;
            }
        }
        CLUSTER_SYNC();   // Hsp(t-1) complete in BOTH CTAs (incl. peer DSMEM writes)

        // warp-private prefetch of U_lo chunks 0,1
        #pragma unroll
        for (int c0 = 0; c0 < 2; c0++) {
            __nv_bfloat16* buf = myUl + (c0 % 3) * 32 * ULW_STRIDE;
            #pragma unroll
            for (int i = 0; i < 2; i++) {
                int u = lane + 32 * i, n1 = u >> 1, hf = u & 1;
                cpa16(smaddr(buf + n1 * ULW_STRIDE + hf * 8),
                      UpC + (size_t)(nbase_l + n1) * 256 + 128 + c0 * 16 + hf * 8);
            }
            cpa_commit();
        }

        #pragma unroll 1
        for (int c = 0; c < 8; c++) {
            if (c < 7) asm volatile("cp.async.wait_group 1;");
            else       asm volatile("cp.async.wait_group 0;");
            __syncwarp();
            if (c + 2 < 8) {
                __nv_bfloat16* nbuf = myUl + ((c + 2) % 3) * 32 * ULW_STRIDE;
                #pragma unroll
                for (int i = 0; i < 2; i++) {
                    int u = lane + 32 * i, n1 = u >> 1, hf = u & 1;
                    cpa16(smaddr(nbuf + n1 * ULW_STRIDE + hf * 8),
                          UpC + (size_t)(nbase_l + n1) * 256 + 128 + (c + 2) * 16 + hf * 8);
                }
                cpa_commit();
            }
            int ko = c * 16 + 2 * tq;
            unsigned ah[4], al[4];
            ah[0] = *(const unsigned*)&Hsp[g * H_STRIDE + ko];
            ah[1] = *(const unsigned*)&Hsp[(g + 8) * H_STRIDE + ko];
            ah[2] = *(const unsigned*)&Hsp[g * H_STRIDE + ko + 8];
            ah[3] = *(const unsigned*)&Hsp[(g + 8) * H_STRIDE + ko + 8];
            al[0] = *(const unsigned*)&Hsp[g * H_STRIDE + 128 + ko];
            al[1] = *(const unsigned*)&Hsp[(g + 8) * H_STRIDE + 128 + ko];
            al[2] = *(const unsigned*)&Hsp[g * H_STRIDE + 128 + ko + 8];
            al[3] = *(const unsigned*)&Hsp[(g + 8) * H_STRIDE + 128 + ko + 8];
            const __nv_bfloat16* ulB = myUl + (c % 3) * 32 * ULW_STRIDE;
            #pragma unroll
            for (int bn = 0; bn < 4; bn++) {
                int n = nbase_l + bn * 8 + g;
                const __nv_bfloat16* bph = Uh + n * UH_STRIDE + ko;
                unsigned h0 = *(const unsigned*)bph;
                unsigned h1 = *(const unsigned*)(bph + 8);
                mma16816(acc[bn], ah, h0, h1);
                mma16816(acc[bn], al, h0, h1);
                const __nv_bfloat16* bpl = ulB + (bn * 8 + g) * ULW_STRIDE + 2 * tq;
                unsigned l0 = *(const unsigned*)bpl;
                unsigned l1 = *(const unsigned*)(bpl + 8);
                mma16816(acc[bn], ah, l0, l1);
            }
        }
        CLUSTER_SYNC();   // all Hsp reads done (both CTAs) before overwrite

        // elementwise: bn == gate; lane owns units 2tq, 2tq+1 of its slice, rows g, g+8
        #pragma unroll
        for (int q2 = 0; q2 < 2; q2++) {
            int r_ = g + 8 * q2;
            float hv[2];
            #pragma unroll
            for (int par = 0; par < 2; par++) {
                int qq = q2 * 2 + par;
                int ci = q2 * 2 + par;
                float gi = acc[0][qq], gf = acc[1][qq], gg = acc[2][qq], go = acc[3][qq];
                float c = sigf(gf) * cst[ci] + sigf(gi) * tanhf_acc(gg);
                float h = sigf(go) * tanhf_acc(c);
                cst[ci] = c;
                hsum[ci] += h;
                hv[par] = h;
            }
            int ug0 = slice * 8 + 2 * tq;
            __nv_bfloat16 h0h = __float2bfloat16(hv[0]);
            __nv_bfloat16 h1h = __float2bfloat16(hv[1]);
            __nv_bfloat16 h0l = __float2bfloat16(hv[0] - __bfloat162float(h0h));
            __nv_bfloat16 h1l = __float2bfloat16(hv[1] - __bfloat162float(h1h));
            unsigned hip = ((unsigned)__bfloat16_as_ushort(h1h) << 16) | __bfloat16_as_ushort(h0h);
            unsigned lop = ((unsigned)__bfloat16_as_ushort(h1l) << 16) | __bfloat16_as_ushort(h0l);
            int offHi = r_ * H_STRIDE + ug0;
            int offLo = offHi + 128;
            *(unsigned*)&Hsp[offHi] = hip;
            *(unsigned*)&Hsp[offLo] = lop;
            asm volatile("st.shared::cluster.u32 [%0], %1;" :: "r"(peerHsp + offHi * 2), "r"(hip) : "memory");
            asm volatile("st.shared::cluster.u32 [%0], %1;" :: "r"(peerHsp + offLo * 2), "r"(lop) : "memory");
            if (hexp) {
                unsigned hp = ((unsigned)__half_as_ushort(__float2half(hv[1])) << 16)
                            | __half_as_ushort(__float2half(hv[0]));
                size_t row2 = ((size_t)(b0 + r_) * TSTEPS + t) * KP_G;
                *(unsigned*)&hexp[row2 + ug0] = hp;
            }
        }
    }

    if (hmean) {
        #pragma unroll
        for (int q2 = 0; q2 < 2; q2++)
            #pragma unroll
            for (int par = 0; par < 2; par++) {
                int ci = q2 * 2 + par;
                int ug = slice * 8 + 2 * tq + par;
                hmean[(size_t)(b0 + g + 8 * q2) * 128 + ug] = hsum[ci] * (1.0f / (float)TSTEPS);
            }
    }
    CLUSTER_SYNC();   // no CTA exits while peer DSMEM stores may be in flight
}

// ---------------- small fp32 SGEMM for fc/proj ----------------
__global__ void k_sgemm(const float* __restrict__ A, const float* __restrict__ Bm,
                        float* __restrict__ C, const float* __restrict__ bias,
                        int M, int N, int K) {
    __shared__ float As[8][68];
    __shared__ float Bs[8][64];
    int tid = threadIdx.x;
    int m0 = blockIdx.y * 64, n0 = blockIdx.x * 64;
    int tm = tid & 15, tn = tid >> 4;
    float acc[4][8];
    #pragma unroll
    for (int i = 0; i < 4; i++)
        #pragma unroll
        for (int j = 0; j < 8; j++) acc[i][j] = 0.f;
    for (int kk = 0; kk < K; kk += 8) {
        #pragma unroll
        for (int i = 0; i < 4; i++) {
            int l = tid + i * 128, m = l >> 3, k = l & 7;
            int gm = m0 + m, gk = kk + k;
            As[k][m] = (gm < M && gk < K) ? A[(size_t)gm * K + gk] : 0.f;
        }
        #pragma unroll
        for (int i = 0; i < 4; i++) {
            int l = tid + i * 128, k = l >> 6, n = l & 63;
            int gk = kk + k, gn = n0 + n;
            Bs[k][n] = (gk < K && gn < N) ? Bm[(size_t)gk * N + gn] : 0.f;
        }
        __syncthreads();
        #pragma unroll
        for (int k = 0; k < 8; k++) {
            float a[4], bv[8];
            #pragma unroll
            for (int i = 0; i < 4; i++) a[i] = As[k][tm * 4 + i];
            #pragma unroll
            for (int j = 0; j < 8; j++) bv[j] = Bs[k][tn * 8 + j];
            #pragma unroll
            for (int i = 0; i < 4; i++)
                #pragma unroll
                for (int j = 0; j < 8; j++) acc[i][j] += a[i] * bv[j];
        }
        __syncthreads();
    }
    #pragma unroll
    for (int i = 0; i < 4; i++) {
        int gm = m0 + tm * 4 + i;
        if (gm >= M) continue;
        #pragma unroll
        for (int j = 0; j < 8; j++) {
            int gn = n0 + tn * 8 + j;
            if (gn < N) C[(size_t)gm * N + gn] = acc[i][j] + (bias ? bias[gn] : 0.f);
        }
    }
}

// ---------------- launch ----------------
extern "C" void kernel_launch(void* const* d_in, const int* in_sizes, int n_in,
                              void* d_out, int out_size) {
    const float* x      = (const float*)d_in[0];
    const float* conv_w = (const float*)d_in[1];
    const float* conv_b = (const float*)d_in[2];
    const float* W1     = (const float*)d_in[3];
    const float* U1     = (const float*)d_in[4];
    const float* b1     = (const float*)d_in[5];
    const float* W2     = (const float*)d_in[6];
    const float* U2     = (const float*)d_in[7];
    const float* b2     = (const float*)d_in[8];
    const float* fc1_w  = (const float*)d_in[9];
    const float* fc1_b  = (const float*)d_in[10];
    const float* proj_w = (const float*)d_in[11];
    const float* proj_b = (const float*)d_in[12];
    float* out = (float*)d_out;

    __half *pA1dft, *pB1dft, *pA1g, *pW1h, *pW2h, *pH1h;
    __nv_bfloat16 *pA2mel, *pB2mel, *pMelsp, *pB2conv, *pU1p, *pU2p;
    float *pG, *pHmean, *pHfc, *pB1p, *pB2p;
    cudaGetSymbolAddress((void**)&pA1dft,  d_A1dft);
    cudaGetSymbolAddress((void**)&pB1dft,  d_B1dft);
    cudaGetSymbolAddress((void**)&pA2mel,  d_A2mel);
    cudaGetSymbolAddress((void**)&pB2mel,  d_B2mel);
    cudaGetSymbolAddress((void**)&pMelsp,  d_melsp);
    cudaGetSymbolAddress((void**)&pB2conv, d_B2conv);
    cudaGetSymbolAddress((void**)&pA1g,    d_A1g);
    cudaGetSymbolAddress((void**)&pW1h,    d_W1h);
    cudaGetSymbolAddress((void**)&pW2h,    d_W2h);
    cudaGetSymbolAddress((void**)&pU1p,    d_U1p);
    cudaGetSymbolAddress((void**)&pU2p,    d_U2p);
    cudaGetSymbolAddress((void**)&pH1h,    d_h1h);
    cudaGetSymbolAddress((void**)&pG,      d_g);
    cudaGetSymbolAddress((void**)&pHmean,  d_hmean);
    cudaGetSymbolAddress((void**)&pHfc,    d_hfc);
    cudaGetSymbolAddress((void**)&pB1p,    d_b1p);
    cudaGetSymbolAddress((void**)&pB2p,    d_b2p);

    cudaFuncSetAttribute(k_lstm_mma, cudaFuncAttributeMaxDynamicSharedMemorySize, LSTM2_SMEM_BYTES);
    cudaFuncSetAttribute(k_gemm,     cudaFuncAttributeMaxDynamicSharedMemorySize, GEMM_SMEM_BYTES);
    cudaFuncSetAttribute(k_gemm16,   cudaFuncAttributeMaxDynamicSharedMemorySize, F16_SMEM_BYTES);

    k_precompute<<<128, 256>>>(conv_w, W1, W2, U1, U2, b1, b2);
    k_window<<<dim3(NFRAMES, BATCH), 256>>>(x);

    // DFT (fp16 single) -> power split-pack into A2mel
    k_gemm16<<<dim3(NP_DFT / 64, R1 / 128), 256, F16_SMEM_BYTES>>>(
        pA1dft, pB1dft, KP_DFT, nullptr, 1, nullptr, 0, pA2mel);
    // mel (bf16 split) -> split pack
    k_gemm<<<dim3(2, R1 / 128), 256, GEMM_SMEM_BYTES>>>(
        pA2mel, pB2mel, KP_MEL, nullptr, 2, nullptr, 0, NMELS, pMelsp, 128);
    // conv (bf16 split, shifted rows) -> fp16 single into A1g
    k_gemm_conv<<<dim3(2, R2 / 128), 256>>>(pMelsp, pB2conv, conv_b, pA1g);
    // g1 (fp16 single, permuted gates)
    k_gemm16<<<dim3(8, R2 / 128), 256, F16_SMEM_BYTES>>>(
        pA1g, pW1h, KP_G, pB1p, 0, pG, G4, nullptr);
    k_lstm_mma<<<(BATCH / 16) * 2, 256, LSTM2_SMEM_BYTES>>>(pG, pU1p, pH1h, nullptr);
    // g2 (fp16 single)
    k_gemm16<<<dim3(8, R2 / 128), 256, F16_SMEM_BYTES>>>(
        pH1h, pW2h, KP_G, pB2p, 0, pG, G4, nullptr);
    k_lstm_mma<<<(BATCH / 16) * 2, 256, LSTM2_SMEM_BYTES>>>(pG, pU2p, nullptr, pHmean);

    k_sgemm<<<dim3(2, BATCH / 64), 128>>>(pHmean, fc1_w, pHfc, fc1_b, BATCH, 128, 128);
    k_sgemm<<<dim3(1, BATCH / 64), 128>>>(pHfc, proj_w, out, proj_b, BATCH, 35, 128);
}

// round 16
// speedup vs baseline: 2.5810x; 1.1851x over previous
#include <cuda_runtime.h>
#include <cuda_bf16.h>
#include <cuda_fp16.h>
#include <math.h>

// ---------------- problem dims ----------------
#define BATCH   1024
#define TLEN    16000
#define NFFT    400
#define HOP     200
#define NBINS   201
#define NMELS   128
#define NFRAMES 81
#define TSTEPS  79
#define HID     128
#define G4      512
#define R1      (BATCH*NFRAMES)   // 82944
#define R2      (BATCH*TSTEPS)    // 80896

#define KP_DFT  416
#define KP_MEL  224
#define KP_G    128
#define NP_DFT  448
#define KCONV   384

// bf16 split k_gemm dynamic smem (bf16 elems)
#define GEMM_SMEM_ELEMS (2*128*40*2 + 2*64*40*2)   // 30720
#define GEMM_SMEM_BYTES (GEMM_SMEM_ELEMS*2)        // 61440
#define OFF_AL  10240
#define OFF_BH  20480
#define OFF_BL  25600

// fp16 single-term GEMM smem
#define F16_SMEM_ELEMS (2*128*40 + 2*64*40)        // 15360
#define F16_SMEM_BYTES (F16_SMEM_ELEMS*2)          // 30720
#define DOFF_B  10240

// LSTM (cluster n-split, resident U, double-buffered H) smem, bf16 elems
#define UH_STRIDE 136
#define H_STRIDE  264
#define SM_U1    (256*UH_STRIDE)           // 34816 (Uh)  — Ul same size
#define SM_H     (16*H_STRIDE)             // 4224 per buffer
#define LSTM2_SMEM_BYTES ((2*SM_U1 + 2*SM_H)*2)   // 156160

// ---------------- scratch ----------------
__device__ float          d_hann[NFFT];
__device__ __half         d_A1dft[(size_t)R1 * KP_DFT];
__device__ __half         d_B1dft[(size_t)NP_DFT * KP_DFT];
__device__ __nv_bfloat16  d_A2mel[(size_t)R1 * 2 * KP_MEL];
__device__ __nv_bfloat16  d_B2mel[(size_t)128 * 2 * KP_MEL];
__device__ __nv_bfloat16  d_melsp[(size_t)R1 * 256];
__device__ __nv_bfloat16  d_B2conv[(size_t)128 * 2 * KCONV];
__device__ __half         d_A1g[(size_t)R2 * KP_G];
__device__ __half         d_W1h[(size_t)G4 * KP_G];
__device__ __half         d_W2h[(size_t)G4 * KP_G];
__device__ __nv_bfloat16  d_U1p[(size_t)G4 * 2 * KP_G];
__device__ __nv_bfloat16  d_U2p[(size_t)G4 * 2 * KP_G];
__device__ float          d_b1p[G4];
__device__ float          d_b2p[G4];
__device__ float          d_g[(size_t)R2 * G4];
__device__ __half         d_h1h[(size_t)R2 * KP_G];
__device__ float          d_hmean[BATCH * 128];
__device__ float          d_hfc[BATCH * 128];

// ---------------- helpers ----------------
__device__ __forceinline__ float sigf(float x) { return 1.0f / (1.0f + __expf(-x)); }
__device__ __forceinline__ float tanhf_acc(float x) {
    float t = __expf(-2.0f * fabsf(x));
    float r = (1.0f - t) / (1.0f + t);
    return copysignf(r, x);
}
__device__ __forceinline__ void splitw(__nv_bfloat16* P, size_t base, int KpOut, int k, float v) {
    __nv_bfloat16 h = __float2bfloat16(v);
    P[base + k] = h;
    P[base + KpOut + k] = __float2bfloat16(v - __bfloat162float(h));
}
__device__ __forceinline__ unsigned smaddr(const void* p) {
    return (unsigned)__cvta_generic_to_shared(p);
}
__device__ __forceinline__ void cpa16(unsigned dst, const void* src) {
    asm volatile("cp.async.cg.shared.global [%0], [%1], 16;" :: "r"(dst), "l"(src));
}
__device__ __forceinline__ void cpa_commit() { asm volatile("cp.async.commit_group;"); }
__device__ __forceinline__ void mma16816(float* c, const unsigned* a, unsigned b0, unsigned b1) {
    asm volatile(
        "mma.sync.aligned.m16n8k16.row.col.f32.bf16.bf16.f32 "
        "{%0,%1,%2,%3}, {%4,%5,%6,%7}, {%8,%9}, {%0,%1,%2,%3};"
        : "+f"(c[0]), "+f"(c[1]), "+f"(c[2]), "+f"(c[3])
        : "r"(a[0]), "r"(a[1]), "r"(a[2]), "r"(a[3]), "r"(b0), "r"(b1));
}
__device__ __forceinline__ void mma16816h(float* c, const unsigned* a, unsigned b0, unsigned b1) {
    asm volatile(
        "mma.sync.aligned.m16n8k16.row.col.f32.f16.f16.f32 "
        "{%0,%1,%2,%3}, {%4,%5,%6,%7}, {%8,%9}, {%0,%1,%2,%3};"
        : "+f"(c[0]), "+f"(c[1]), "+f"(c[2]), "+f"(c[3])
        : "r"(a[0]), "r"(a[1]), "r"(a[2]), "r"(a[3]), "r"(b0), "r"(b1));
}
// packed gate col n -> original col (slice/gate/unit; same as R15)
__device__ __forceinline__ int gperm(int n) {
    int slice = n >> 5, s = n & 31, gate = s >> 3, u = s & 7;
    return gate * 128 + slice * 8 + u;
}
#define CLUSTER_SYNC() do { \
    asm volatile("barrier.cluster.arrive.aligned;" ::: "memory"); \
    asm volatile("barrier.cluster.wait.aligned;"   ::: "memory"); } while (0)

// ---------------- precompute (fp32 fast math) ----------------
__global__ void k_precompute(const float* __restrict__ conv_w,
                             const float* __restrict__ W1, const float* __restrict__ W2,
                             const float* __restrict__ U1, const float* __restrict__ U2,
                             const float* __restrict__ b1, const float* __restrict__ b2) {
    int tid = blockIdx.x * blockDim.x + threadIdx.x;
    int nth = gridDim.x * blockDim.x;

    for (int k = tid; k < NFFT; k += nth)
        d_hann[k] = 0.5f - 0.5f * cospif((float)k / 200.0f);

    for (int idx = tid; idx < NP_DFT * KP_DFT; idx += nth) {
        int n = idx / KP_DFT, k = idx % KP_DFT;
        float v = 0.f;
        if (n < 2 * NBINS && k < NFFT) {
            int m = n >> 1;
            int ph = (m * k) % 400;
            float s, c;
            sincospif((float)ph / 200.0f, &s, &c);
            v = (n & 1) ? s : c;
        }
        d_B1dft[(size_t)n * KP_DFT + k] = __float2half(v);
    }

    const float mel_max = 2595.0f * log10f(1.0f + 8000.0f / 700.0f);
    for (int idx = tid; idx < 128 * KP_MEL; idx += nth) {
        int m = idx / KP_MEL, k = idx % KP_MEL;
        float v = 0.f;
        if (k < NBINS) {
            float freq = 40.0f * (float)k;
            float f0 = 700.0f * (exp10f((mel_max * (float)(m    ) / 129.0f) / 2595.0f) - 1.0f);
            float f1 = 700.0f * (exp10f((mel_max * (float)(m + 1) / 129.0f) / 2595.0f) - 1.0f);
            float f2 = 700.0f * (exp10f((mel_max * (float)(m + 2) / 129.0f) / 2595.0f) - 1.0f);
            float dn = (freq - f0) / (f1 - f0);
            float up = (f2 - freq) / (f2 - f1);
            float t = fminf(dn, up);
            v = fmaxf(t, 0.0f);
        }
        splitw(d_B2mel, (size_t)m * (2 * KP_MEL), KP_MEL, k, v);
    }

    for (int idx = tid; idx < 128 * KCONV; idx += nth) {
        int o = idx / KCONV, q = idx % KCONV;
        int kk = q >> 7, i = q & 127;
        splitw(d_B2conv, (size_t)o * (2 * KCONV), KCONV, q, conv_w[o * 384 + i * 3 + kk]);
    }

    for (int idx = tid; idx < G4 * KP_G; idx += nth) {
        int n = idx / KP_G, k = idx % KP_G;
        int no = gperm(n);
        d_W1h[(size_t)n * KP_G + k] = __float2half(W1[k * G4 + no]);
        d_W2h[(size_t)n * KP_G + k] = __float2half(W2[k * G4 + no]);
        splitw(d_U1p, (size_t)n * (2 * KP_G), KP_G, k, U1[k * G4 + no]);
        splitw(d_U2p, (size_t)n * (2 * KP_G), KP_G, k, U2[k * G4 + no]);
    }
    for (int n = tid; n < G4; n += nth) {
        int no = gperm(n);
        d_b1p[n] = b1[no];
        d_b2p[n] = b2[no];
    }

    for (int idx = tid; idx < R1 * (KP_MEL - NBINS); idx += nth) {
        int r = idx / (KP_MEL - NBINS), k = NBINS + idx % (KP_MEL - NBINS);
        d_A2mel[(size_t)r * (2 * KP_MEL) + k] = __float2bfloat16(0.f);
        d_A2mel[(size_t)r * (2 * KP_MEL) + KP_MEL + k] = __float2bfloat16(0.f);
    }
}

// ---------------- window -> fp16 A ----------------
__global__ void k_window(const float* __restrict__ x) {
    int f = blockIdx.x, b = blockIdx.y, tid = threadIdx.x;
    size_t row = (size_t)(b * NFRAMES + f) * KP_DFT;
    for (int k = tid; k < KP_DFT; k += blockDim.x) {
        float v = 0.f;
        if (k < NFFT) {
            int p = f * HOP + k - 200;
            int i = (p < 0) ? -p : ((p >= TLEN) ? (2 * TLEN - 2 - p) : p);
            v = x[(size_t)b * TLEN + i] * d_hann[k];
        }
        d_A1dft[row + k] = __float2half(v);
    }
}

// ---------------- generic single-term fp16 GEMM ----------------
// mode 0: fp32 out + bias; mode 1: DFT power -> bf16 split pack into outP
__global__ void __launch_bounds__(256, 3)
k_gemm16(const __half* __restrict__ A1, const __half* __restrict__ B1,
         int Kp, const float* __restrict__ bias, int mode,
         float* __restrict__ outF, int ldc,
         __nv_bfloat16* __restrict__ outP) {
    extern __shared__ __half smh[];
    __half* AHs = smh;
    __half* BHs = smh + DOFF_B;

    int tid = threadIdx.x, lane = tid & 31, w = tid >> 5;
    int wm = w >> 1, wn = w & 1;
    int m0 = blockIdx.y * 128, n0 = blockIdx.x * 64;
    int g = lane >> 2, t = lane & 3;
    int la_row = tid >> 2, la_kc = (tid & 3) << 3;

    const __half* Abase = A1 + (size_t)m0 * Kp;
    const __half* Bbase = B1 + (size_t)n0 * Kp;

    float acc[2][4][4];
    #pragma unroll
    for (int i = 0; i < 2; i++)
        #pragma unroll
        for (int j = 0; j < 4; j++)
            #pragma unroll
            for (int q = 0; q < 4; q++) acc[i][j][q] = 0.f;

    auto load_chunk = [&](int buf, int kk) {
        int bo = buf * 5120, bo2 = buf * 2560;
        cpa16(smaddr(AHs + bo + la_row * 40 + la_kc),        Abase + (size_t)la_row * Kp + kk + la_kc);
        cpa16(smaddr(AHs + bo + (la_row + 64) * 40 + la_kc), Abase + (size_t)(la_row + 64) * Kp + kk + la_kc);
        cpa16(smaddr(BHs + bo2 + la_row * 40 + la_kc),       Bbase + (size_t)la_row * Kp + kk + la_kc);
        cpa_commit();
    };

    load_chunk(0, 0);

    #pragma unroll 1
    for (int kk = 0; kk < Kp; kk += 32) {
        int buf = (kk >> 5) & 1;
        asm volatile("cp.async.wait_group 0;");
        __syncthreads();
        if (kk + 32 < Kp) load_chunk(buf ^ 1, kk + 32);

        int bo = buf * 5120, bo2 = buf * 2560;
        #pragma unroll
        for (int ko = 0; ko < 32; ko += 16) {
            unsigned ahf[2][4], bhf[4][2];
            #pragma unroll
            for (int i = 0; i < 2; i++) {
                int r = wm * 32 + i * 16;
                ahf[i][0] = *(const unsigned*)&AHs[bo + (r + g) * 40 + ko + 2 * t];
                ahf[i][1] = *(const unsigned*)&AHs[bo + (r + g + 8) * 40 + ko + 2 * t];
                ahf[i][2] = *(const unsigned*)&AHs[bo + (r + g) * 40 + ko + 2 * t + 8];
                ahf[i][3] = *(const unsigned*)&AHs[bo + (r + g + 8) * 40 + ko + 2 * t + 8];
            }
            #pragma unroll
            for (int j = 0; j < 4; j++) {
                int bn = wn * 32 + j * 8 + g;
                bhf[j][0] = *(const unsigned*)&BHs[bo2 + bn * 40 + ko + 2 * t];
                bhf[j][1] = *(const unsigned*)&BHs[bo2 + bn * 40 + ko + 2 * t + 8];
            }
            #pragma unroll
            for (int i = 0; i < 2; i++)
                #pragma unroll
                for (int j = 0; j < 4; j++)
                    mma16816h(acc[i][j], ahf[i], bhf[j][0], bhf[j][1]);
        }
        __syncthreads();
    }

    #pragma unroll
    for (int i = 0; i < 2; i++) {
        int r = m0 + wm * 32 + i * 16 + g;
        #pragma unroll
        for (int j = 0; j < 4; j++) {
            int c = n0 + wn * 32 + j * 8 + 2 * t;
            if (mode == 0) {
                float b0 = bias ? bias[c] : 0.f, b1 = bias ? bias[c + 1] : 0.f;
                outF[(size_t)r * ldc + c]           = acc[i][j][0] + b0;
                outF[(size_t)r * ldc + c + 1]       = acc[i][j][1] + b1;
                outF[(size_t)(r + 8) * ldc + c]     = acc[i][j][2] + b0;
                outF[(size_t)(r + 8) * ldc + c + 1] = acc[i][j][3] + b1;
            } else {
                int k = c >> 1;
                if (k < NBINS) {
                    float p0 = acc[i][j][0] * acc[i][j][0] + acc[i][j][1] * acc[i][j][1];
                    float p1 = acc[i][j][2] * acc[i][j][2] + acc[i][j][3] * acc[i][j][3];
                    splitw(outP, (size_t)r * (2 * KP_MEL), KP_MEL, k, p0);
                    splitw(outP, (size_t)(r + 8) * (2 * KP_MEL), KP_MEL, k, p1);
                }
            }
        }
    }
}

// ---------------- split-bf16 tensor GEMM (mel; proven) ----------------
__global__ void __launch_bounds__(256, 3)
k_gemm(const __nv_bfloat16* __restrict__ A2, const __nv_bfloat16* __restrict__ B2,
       int Kp, const float* __restrict__ bias, int mode,
       float* __restrict__ outF, int ldc, int Nreal,
       __nv_bfloat16* __restrict__ outP, int KpOut) {
    extern __shared__ __nv_bfloat16 smd[];
    __nv_bfloat16* AHs = smd;
    __nv_bfloat16* ALs = smd + OFF_AL;
    __nv_bfloat16* BHs = smd + OFF_BH;
    __nv_bfloat16* BLs = smd + OFF_BL;

    int tid = threadIdx.x, lane = tid & 31, w = tid >> 5;
    int wm = w >> 1, wn = w & 1;
    int m0 = blockIdx.y * 128, n0 = blockIdx.x * 64;
    int g = lane >> 2, t = lane & 3;
    int strideA = 2 * Kp;
    int la_row = tid >> 2, la_kc = (tid & 3) << 3;

    const __nv_bfloat16* Abase = A2 + (size_t)m0 * strideA;
    const __nv_bfloat16* Bbase = B2 + (size_t)n0 * strideA;

    float acc[2][4][4];
    #pragma unroll
    for (int i = 0; i < 2; i++)
        #pragma unroll
        for (int j = 0; j < 4; j++)
            #pragma unroll
            for (int q = 0; q < 4; q++) acc[i][j][q] = 0.f;

    auto load_chunk = [&](int buf, int kk) {
        int bo = buf * 5120, bo2 = buf * 2560;
        cpa16(smaddr(AHs + bo + la_row * 40 + la_kc),        Abase + (size_t)la_row * strideA + kk + la_kc);
        cpa16(smaddr(AHs + bo + (la_row + 64) * 40 + la_kc), Abase + (size_t)(la_row + 64) * strideA + kk + la_kc);
        cpa16(smaddr(ALs + bo + la_row * 40 + la_kc),        Abase + (size_t)la_row * strideA + Kp + kk + la_kc);
        cpa16(smaddr(ALs + bo + (la_row + 64) * 40 + la_kc), Abase + (size_t)(la_row + 64) * strideA + Kp + kk + la_kc);
        cpa16(smaddr(BHs + bo2 + la_row * 40 + la_kc),       Bbase + (size_t)la_row * strideA + kk + la_kc);
        cpa16(smaddr(BLs + bo2 + la_row * 40 + la_kc),       Bbase + (size_t)la_row * strideA + Kp + kk + la_kc);
        cpa_commit();
    };

    load_chunk(0, 0);

    #pragma unroll 1
    for (int kk = 0; kk < Kp; kk += 32) {
        int buf = (kk >> 5) & 1;
        asm volatile("cp.async.wait_group 0;");
        __syncthreads();
        if (kk + 32 < Kp) load_chunk(buf ^ 1, kk + 32);

        int bo = buf * 5120, bo2 = buf * 2560;
        #pragma unroll
        for (int ko = 0; ko < 32; ko += 16) {
            unsigned ahf[2][4], alf[2][4], bhf[4][2], blf[4][2];
            #pragma unroll
            for (int i = 0; i < 2; i++) {
                int r = wm * 32 + i * 16;
                ahf[i][0] = *(const unsigned*)&AHs[bo + (r + g) * 40 + ko + 2 * t];
                ahf[i][1] = *(const unsigned*)&AHs[bo + (r + g + 8) * 40 + ko + 2 * t];
                ahf[i][2] = *(const unsigned*)&AHs[bo + (r + g) * 40 + ko + 2 * t + 8];
                ahf[i][3] = *(const unsigned*)&AHs[bo + (r + g + 8) * 40 + ko + 2 * t + 8];
                alf[i][0] = *(const unsigned*)&ALs[bo + (r + g) * 40 + ko + 2 * t];
                alf[i][1] = *(const unsigned*)&ALs[bo + (r + g + 8) * 40 + ko + 2 * t];
                alf[i][2] = *(const unsigned*)&ALs[bo + (r + g) * 40 + ko + 2 * t + 8];
                alf[i][3] = *(const unsigned*)&ALs[bo + (r + g + 8) * 40 + ko + 2 * t + 8];
            }
            #pragma unroll
            for (int j = 0; j < 4; j++) {
                int bn = wn * 32 + j * 8 + g;
                bhf[j][0] = *(const unsigned*)&BHs[bo2 + bn * 40 + ko + 2 * t];
                bhf[j][1] = *(const unsigned*)&BHs[bo2 + bn * 40 + ko + 2 * t + 8];
                blf[j][0] = *(const unsigned*)&BLs[bo2 + bn * 40 + ko + 2 * t];
                blf[j][1] = *(const unsigned*)&BLs[bo2 + bn * 40 + ko + 2 * t + 8];
            }
            #pragma unroll
            for (int i = 0; i < 2; i++)
                #pragma unroll
                for (int j = 0; j < 4; j++) {
                    mma16816(acc[i][j], ahf[i], bhf[j][0], bhf[j][1]);
                    mma16816(acc[i][j], ahf[i], blf[j][0], blf[j][1]);
                    mma16816(acc[i][j], alf[i], bhf[j][0], bhf[j][1]);
                }
        }
        __syncthreads();
    }

    #pragma unroll
    for (int i = 0; i < 2; i++) {
        int r = m0 + wm * 32 + i * 16 + g;
        #pragma unroll
        for (int j = 0; j < 4; j++) {
            int c = n0 + wn * 32 + j * 8 + 2 * t;
            float v00 = acc[i][j][0], v01 = acc[i][j][1];
            float v10 = acc[i][j][2], v11 = acc[i][j][3];
            if (mode == 0) {
                float b0 = bias ? bias[c] : 0.f, b1 = bias ? bias[c + 1] : 0.f;
                outF[(size_t)r * ldc + c]           = v00 + b0;
                outF[(size_t)r * ldc + c + 1]       = v01 + b1;
                outF[(size_t)(r + 8) * ldc + c]     = v10 + b0;
                outF[(size_t)(r + 8) * ldc + c + 1] = v11 + b1;
            } else {
                float b0 = bias ? bias[c] : 0.f, b1 = bias ? bias[c + 1] : 0.f;
                splitw(outP, (size_t)r * (2 * KpOut), KpOut, c, v00 + b0);
                splitw(outP, (size_t)r * (2 * KpOut), KpOut, c + 1, v01 + b1);
                splitw(outP, (size_t)(r + 8) * (2 * KpOut), KpOut, c, v10 + b0);
                splitw(outP, (size_t)(r + 8) * (2 * KpOut), KpOut, c + 1, v11 + b1);
            }
        }
    }
}

// ---------------- conv GEMM: shifted rows, 9 segments, fp16 single output ----------------
__global__ void __launch_bounds__(256, 3)
k_gemm_conv(const __nv_bfloat16* __restrict__ Msp, const __nv_bfloat16* __restrict__ B2,
            const float* __restrict__ bias, __half* __restrict__ outH) {
    __shared__ __nv_bfloat16 As[2][128][40];
    __shared__ __nv_bfloat16 Bs[2][64][40];
    int tid = threadIdx.x, lane = tid & 31, w = tid >> 5;
    int wm = w >> 1, wn = w & 1;
    int m0 = blockIdx.y * 128, n0 = blockIdx.x * 64;
    int g = lane >> 2, t = lane & 3;
    int la_row = tid >> 2, la_kc = (tid & 3) << 3;

    int gm0 = m0 + la_row, gm1 = m0 + la_row + 64;
    int sr0 = gm0 + 2 * (gm0 / TSTEPS);
    int sr1 = gm1 + 2 * (gm1 / TSTEPS);

    float acc[2][4][4];
    #pragma unroll
    for (int i = 0; i < 2; i++)
        #pragma unroll
        for (int j = 0; j < 4; j++)
            #pragma unroll
            for (int q = 0; q < 4; q++) acc[i][j][q] = 0.f;

    #pragma unroll 1
    for (int s = 0; s < 9; s++) {
        int split = s / 3, shift = s % 3;
        int aoff = (split == 2) ? 128 : 0;
        int boff = ((split == 1) ? KCONV : 0) + shift * 128;
        const __nv_bfloat16* A0 = Msp + (size_t)(sr0 + shift) * 256 + aoff;
        const __nv_bfloat16* A1 = Msp + (size_t)(sr1 + shift) * 256 + aoff;
        const __nv_bfloat16* Bb = B2 + (size_t)n0 * (2 * KCONV) + boff;

        cpa16(smaddr(&As[0][la_row][la_kc]),      A0 + la_kc);
        cpa16(smaddr(&As[0][la_row + 64][la_kc]), A1 + la_kc);
        cpa16(smaddr(&Bs[0][la_row][la_kc]),      Bb + (size_t)la_row * (2 * KCONV) + la_kc);
        cpa_commit();
        #pragma unroll 1
        for (int kk = 0; kk < 128; kk += 32) {
            int buf = (kk >> 5) & 1;
            asm volatile("cp.async.wait_group 0;");
            __syncthreads();
            if (kk + 32 < 128) {
                int nb = buf ^ 1, kn = kk + 32;
                cpa16(smaddr(&As[nb][la_row][la_kc]),      A0 + kn + la_kc);
                cpa16(smaddr(&As[nb][la_row + 64][la_kc]), A1 + kn + la_kc);
                cpa16(smaddr(&Bs[nb][la_row][la_kc]),      Bb + (size_t)la_row * (2 * KCONV) + kn + la_kc);
                cpa_commit();
            }
            #pragma unroll
            for (int ko = 0; ko < 32; ko += 16) {
                unsigned a[2][4], bfr[4][2];
                #pragma unroll
                for (int i = 0; i < 2; i++) {
                    int r = wm * 32 + i * 16;
                    a[i][0] = *(const unsigned*)&As[buf][r + g][ko + 2 * t];
                    a[i][1] = *(const unsigned*)&As[buf][r + g + 8][ko + 2 * t];
                    a[i][2] = *(const unsigned*)&As[buf][r + g][ko + 2 * t + 8];
                    a[i][3] = *(const unsigned*)&As[buf][r + g + 8][ko + 2 * t + 8];
                }
                #pragma unroll
                for (int j = 0; j < 4; j++) {
                    int bn = wn * 32 + j * 8 + g;
                    bfr[j][0] = *(const unsigned*)&Bs[buf][bn][ko + 2 * t];
                    bfr[j][1] = *(const unsigned*)&Bs[buf][bn][ko + 2 * t + 8];
                }
                #pragma unroll
                for (int i = 0; i < 2; i++)
                    #pragma unroll
                    for (int j = 0; j < 4; j++)
                        mma16816(acc[i][j], a[i], bfr[j][0], bfr[j][1]);
            }
            __syncthreads();
        }
    }

    #pragma unroll
    for (int i = 0; i < 2; i++) {
        int r = m0 + wm * 32 + i * 16 + g;
        #pragma unroll
        for (int j = 0; j < 4; j++) {
            int c = n0 + wn * 32 + j * 8 + 2 * t;
            float b0 = bias[c], b1 = bias[c + 1];
            outH[(size_t)r * KP_G + c]           = __float2half(acc[i][j][0] + b0);
            outH[(size_t)r * KP_G + c + 1]       = __float2half(acc[i][j][1] + b1);
            outH[(size_t)(r + 8) * KP_G + c]     = __float2half(acc[i][j][2] + b0);
            outH[(size_t)(r + 8) * KP_G + c + 1] = __float2half(acc[i][j][3] + b1);
        }
    }
}

// ---------------- cluster n-split LSTM v5: resident U, double-buffered H, 1 sync/step ----------------
__global__ void __cluster_dims__(2, 1, 1) __launch_bounds__(256)
k_lstm_mma(const float* __restrict__ gx, const __nv_bfloat16* __restrict__ Up,
           __half* __restrict__ hexp, float* __restrict__ hmean) {
    extern __shared__ __nv_bfloat16 sm[];
    __nv_bfloat16* Uh   = sm;                      // [256][136] hi
    __nv_bfloat16* Ulr  = sm + SM_U1;              // [256][136] lo (resident)
    __nv_bfloat16* Hsp0 = sm + 2 * SM_U1;          // [16][264] buffer 0
    __nv_bfloat16* Hsp1 = Hsp0 + SM_H;             // [16][264] buffer 1

    int tid = threadIdx.x, lane = tid & 31, w = tid >> 5;
    int g = lane >> 2, tq = lane & 3;
    unsigned rank;
    asm("mov.u32 %0, %%cluster_ctarank;" : "=r"(rank));
    int b0 = (blockIdx.x >> 1) * 16;
    int nbase_l = w * 32;
    int gbase = (int)rank * 256 + nbase_l;
    int slice = (int)rank * 8 + w;
    const __nv_bfloat16* UpC = Up + (size_t)((int)rank * 256) * 256;

    unsigned peerH0;
    asm("mapa.shared::cluster.u32 %0, %1, %2;"
        : "=r"(peerH0) : "r"(smaddr(Hsp0)), "r"(1u - rank));

    // load this CTA's Uh (hi) and Ulr (lo); zero both H buffers
    for (int idx = tid; idx < 256 * 16; idx += 256) {
        int n = idx >> 4, j = idx & 15;
        *(uint4*)(Uh  + n * UH_STRIDE + j * 8) = *(const uint4*)(UpC + (size_t)n * 256 + j * 8);
        *(uint4*)(Ulr + n * UH_STRIDE + j * 8) = *(const uint4*)(UpC + (size_t)n * 256 + 128 + j * 8);
    }
    for (int idx = tid; idx < 2 * SM_H; idx += 256) Hsp0[idx] = __float2bfloat16(0.f);

    float cst[4], hsum[4];
    #pragma unroll
    for (int i = 0; i < 4; i++) { cst[i] = 0.f; hsum[i] = 0.f; }

    for (int t = 0; t < TSTEPS; t++) {
        float acc[4][4];
        {
            size_t rlo = ((size_t)(b0 + g) * TSTEPS + t) * G4 + gbase + 2 * tq;
            size_t rhi = ((size_t)(b0 + g + 8) * TSTEPS + t) * G4 + gbase + 2 * tq;
            #pragma unroll
            for (int bn = 0; bn < 4; bn++) {
                float2 v0 = *(const float2*)&gx[rlo + bn * 8];
                float2 v1 = *(const float2*)&gx[rhi + bn * 8];
                acc[bn][0] = v0.x; acc[bn][1] = v0.y;
                acc[bn][2] = v1.x; acc[bn][3] = v1.y;
            }
        }
        CLUSTER_SYNC();   // h(t-1) writes (incl. peer DSMEM) visible everywhere

        const __nv_bfloat16* Hrd = ((t & 1) ? Hsp0 : Hsp1);   // h(t-1) lives in buf[(t-1)&1]
        #pragma unroll 1
        for (int c = 0; c < 8; c++) {
            int ko = c * 16 + 2 * tq;
            unsigned ah[4], al[4];
            ah[0] = *(const unsigned*)&Hrd[g * H_STRIDE + ko];
            ah[1] = *(const unsigned*)&Hrd[(g + 8) * H_STRIDE + ko];
            ah[2] = *(const unsigned*)&Hrd[g * H_STRIDE + ko + 8];
            ah[3] = *(const unsigned*)&Hrd[(g + 8) * H_STRIDE + ko + 8];
            al[0] = *(const unsigned*)&Hrd[g * H_STRIDE + 128 + ko];
            al[1] = *(const unsigned*)&Hrd[(g + 8) * H_STRIDE + 128 + ko];
            al[2] = *(const unsigned*)&Hrd[g * H_STRIDE + 128 + ko + 8];
            al[3] = *(const unsigned*)&Hrd[(g + 8) * H_STRIDE + 128 + ko + 8];
            #pragma unroll
            for (int bn = 0; bn < 4; bn++) {
                int n = nbase_l + bn * 8 + g;
                const __nv_bfloat16* bph = Uh + n * UH_STRIDE + ko;
                unsigned h0 = *(const unsigned*)bph;
                unsigned h1 = *(const unsigned*)(bph + 8);
                mma16816(acc[bn], ah, h0, h1);
                mma16816(acc[bn], al, h0, h1);
                const __nv_bfloat16* bpl = Ulr + n * UH_STRIDE + ko;
                unsigned l0 = *(const unsigned*)bpl;
                unsigned l1 = *(const unsigned*)(bpl + 8);
                mma16816(acc[bn], ah, l0, l1);
            }
        }

        // elementwise; write h(t) into buf[t&1] locally + peer (DSMEM)
        __nv_bfloat16* Hwr = ((t & 1) ? Hsp1 : Hsp0);
        unsigned peerWr = peerH0 + (unsigned)((t & 1) ? SM_H * 2 : 0);
        #pragma unroll
        for (int q2 = 0; q2 < 2; q2++) {
            int r_ = g + 8 * q2;
            float hv[2];
            #pragma unroll
            for (int par = 0; par < 2; par++) {
                int qq = q2 * 2 + par;
                int ci = q2 * 2 + par;
                float gi = acc[0][qq], gf = acc[1][qq], gg = acc[2][qq], go = acc[3][qq];
                float c = sigf(gf) * cst[ci] + sigf(gi) * tanhf_acc(gg);
                float h = sigf(go) * tanhf_acc(c);
                cst[ci] = c;
                hsum[ci] += h;
                hv[par] = h;
            }
            int ug0 = slice * 8 + 2 * tq;
            __nv_bfloat16 h0h = __float2bfloat16(hv[0]);
            __nv_bfloat16 h1h = __float2bfloat16(hv[1]);
            __nv_bfloat16 h0l = __float2bfloat16(hv[0] - __bfloat162float(h0h));
            __nv_bfloat16 h1l = __float2bfloat16(hv[1] - __bfloat162float(h1h));
            unsigned hip = ((unsigned)__bfloat16_as_ushort(h1h) << 16) | __bfloat16_as_ushort(h0h);
            unsigned lop = ((unsigned)__bfloat16_as_ushort(h1l) << 16) | __bfloat16_as_ushort(h0l);
            int offHi = r_ * H_STRIDE + ug0;
            int offLo = offHi + 128;
            *(unsigned*)&Hwr[offHi] = hip;
            *(unsigned*)&Hwr[offLo] = lop;
            asm volatile("st.shared::cluster.u32 [%0], %1;" :: "r"(peerWr + offHi * 2), "r"(hip) : "memory");
            asm volatile("st.shared::cluster.u32 [%0], %1;" :: "r"(peerWr + offLo * 2), "r"(lop) : "memory");
            if (hexp) {
                unsigned hp = ((unsigned)__half_as_ushort(__float2half(hv[1])) << 16)
                            | __half_as_ushort(__float2half(hv[0]));
                size_t row2 = ((size_t)(b0 + r_) * TSTEPS + t) * KP_G;
                *(unsigned*)&hexp[row2 + ug0] = hp;
            }
        }
    }

    if (hmean) {
        #pragma unroll
        for (int q2 = 0; q2 < 2; q2++)
            #pragma unroll
            for (int par = 0; par < 2; par++) {
                int ci = q2 * 2 + par;
                int ug = slice * 8 + 2 * tq + par;
                hmean[(size_t)(b0 + g + 8 * q2) * 128 + ug] = hsum[ci] * (1.0f / (float)TSTEPS);
            }
    }
    CLUSTER_SYNC();   // no CTA exits while peer DSMEM stores may be in flight
}

// ---------------- small fp32 SGEMM for fc/proj ----------------
__global__ void k_sgemm(const float* __restrict__ A, const float* __restrict__ Bm,
                        float* __restrict__ C, const float* __restrict__ bias,
                        int M, int N, int K) {
    __shared__ float As[8][68];
    __shared__ float Bs[8][64];
    int tid = threadIdx.x;
    int m0 = blockIdx.y * 64, n0 = blockIdx.x * 64;
    int tm = tid & 15, tn = tid >> 4;
    float acc[4][8];
    #pragma unroll
    for (int i = 0; i < 4; i++)
        #pragma unroll
        for (int j = 0; j < 8; j++) acc[i][j] = 0.f;
    for (int kk = 0; kk < K; kk += 8) {
        #pragma unroll
        for (int i = 0; i < 4; i++) {
            int l = tid + i * 128, m = l >> 3, k = l & 7;
            int gm = m0 + m, gk = kk + k;
            As[k][m] = (gm < M && gk < K) ? A[(size_t)gm * K + gk] : 0.f;
        }
        #pragma unroll
        for (int i = 0; i < 4; i++) {
            int l = tid + i * 128, k = l >> 6, n = l & 63;
            int gk = kk + k, gn = n0 + n;
            Bs[k][n] = (gk < K && gn < N) ? Bm[(size_t)gk * N + gn] : 0.f;
        }
        __syncthreads();
        #pragma unroll
        for (int k = 0; k < 8; k++) {
            float a[4], bv[8];
            #pragma unroll
            for (int i = 0; i < 4; i++) a[i] = As[k][tm * 4 + i];
            #pragma unroll
            for (int j = 0; j < 8; j++) bv[j] = Bs[k][tn * 8 + j];
            #pragma unroll
            for (int i = 0; i < 4; i++)
                #pragma unroll
                for (int j = 0; j < 8; j++) acc[i][j] += a[i] * bv[j];
        }
        __syncthreads();
    }
    #pragma unroll
    for (int i = 0; i < 4; i++) {
        int gm = m0 + tm * 4 + i;
        if (gm >= M) continue;
        #pragma unroll
        for (int j = 0; j < 8; j++) {
            int gn = n0 + tn * 8 + j;
            if (gn < N) C[(size_t)gm * N + gn] = acc[i][j] + (bias ? bias[gn] : 0.f);
        }
    }
}

// ---------------- launch ----------------
extern "C" void kernel_launch(void* const* d_in, const int* in_sizes, int n_in,
                              void* d_out, int out_size) {
    const float* x      = (const float*)d_in[0];
    const float* conv_w = (const float*)d_in[1];
    const float* conv_b = (const float*)d_in[2];
    const float* W1     = (const float*)d_in[3];
    const float* U1     = (const float*)d_in[4];
    const float* b1     = (const float*)d_in[5];
    const float* W2     = (const float*)d_in[6];
    const float* U2     = (const float*)d_in[7];
    const float* b2     = (const float*)d_in[8];
    const float* fc1_w  = (const float*)d_in[9];
    const float* fc1_b  = (const float*)d_in[10];
    const float* proj_w = (const float*)d_in[11];
    const float* proj_b = (const float*)d_in[12];
    float* out = (float*)d_out;

    __half *pA1dft, *pB1dft, *pA1g, *pW1h, *pW2h, *pH1h;
    __nv_bfloat16 *pA2mel, *pB2mel, *pMelsp, *pB2conv, *pU1p, *pU2p;
    float *pG, *pHmean, *pHfc, *pB1p, *pB2p;
    cudaGetSymbolAddress((void**)&pA1dft,  d_A1dft);
    cudaGetSymbolAddress((void**)&pB1dft,  d_B1dft);
    cudaGetSymbolAddress((void**)&pA2mel,  d_A2mel);
    cudaGetSymbolAddress((void**)&pB2mel,  d_B2mel);
    cudaGetSymbolAddress((void**)&pMelsp,  d_melsp);
    cudaGetSymbolAddress((void**)&pB2conv, d_B2conv);
    cudaGetSymbolAddress((void**)&pA1g,    d_A1g);
    cudaGetSymbolAddress((void**)&pW1h,    d_W1h);
    cudaGetSymbolAddress((void**)&pW2h,    d_W2h);
    cudaGetSymbolAddress((void**)&pU1p,    d_U1p);
    cudaGetSymbolAddress((void**)&pU2p,    d_U2p);
    cudaGetSymbolAddress((void**)&pH1h,    d_h1h);
    cudaGetSymbolAddress((void**)&pG,      d_g);
    cudaGetSymbolAddress((void**)&pHmean,  d_hmean);
    cudaGetSymbolAddress((void**)&pHfc,    d_hfc);
    cudaGetSymbolAddress((void**)&pB1p,    d_b1p);
    cudaGetSymbolAddress((void**)&pB2p,    d_b2p);

    cudaFuncSetAttribute(k_lstm_mma, cudaFuncAttributeMaxDynamicSharedMemorySize, LSTM2_SMEM_BYTES);
    cudaFuncSetAttribute(k_gemm,     cudaFuncAttributeMaxDynamicSharedMemorySize, GEMM_SMEM_BYTES);
    cudaFuncSetAttribute(k_gemm16,   cudaFuncAttributeMaxDynamicSharedMemorySize, F16_SMEM_BYTES);

    k_precompute<<<128, 256>>>(conv_w, W1, W2, U1, U2, b1, b2);
    k_window<<<dim3(NFRAMES, BATCH), 256>>>(x);

    // DFT (fp16 single) -> power split-pack into A2mel
    k_gemm16<<<dim3(NP_DFT / 64, R1 / 128), 256, F16_SMEM_BYTES>>>(
        pA1dft, pB1dft, KP_DFT, nullptr, 1, nullptr, 0, pA2mel);
    // mel (bf16 split) -> split pack
    k_gemm<<<dim3(2, R1 / 128), 256, GEMM_SMEM_BYTES>>>(
        pA2mel, pB2mel, KP_MEL, nullptr, 2, nullptr, 0, NMELS, pMelsp, 128);
    // conv (bf16 split, shifted rows) -> fp16 single into A1g
    k_gemm_conv<<<dim3(2, R2 / 128), 256>>>(pMelsp, pB2conv, conv_b, pA1g);
    // g1 (fp16 single, permuted gates)
    k_gemm16<<<dim3(8, R2 / 128), 256, F16_SMEM_BYTES>>>(
        pA1g, pW1h, KP_G, pB1p, 0, pG, G4, nullptr);
    k_lstm_mma<<<(BATCH / 16) * 2, 256, LSTM2_SMEM_BYTES>>>(pG, pU1p, pH1h, nullptr);
    // g2 (fp16 single)
    k_gemm16<<<dim3(8, R2 / 128), 256, F16_SMEM_BYTES>>>(
        pH1h, pW2h, KP_G, pB2p, 0, pG, G4, nullptr);
    k_lstm_mma<<<(BATCH / 16) * 2, 256, LSTM2_SMEM_BYTES>>>(pG, pU2p, nullptr, pHmean);

    k_sgemm<<<dim3(2, BATCH / 64), 128>>>(pHmean, fc1_w, pHfc, fc1_b, BATCH, 128, 128);
    k_sgemm<<<dim3(1, BATCH / 64), 128>>>(pHfc, proj_w, out, proj_b, BATCH, 35, 128);
}